// round 9
// baseline (speedup 1.0000x reference)
#include <cuda_runtime.h>
#include <cuda_bf16.h>
#include <cstdint>
#include <math.h>

// ---------------- problem constants ----------------
#define NTOK  4096
#define EDIM  512
#define QKV   512
#define HEADS 8
#define DH    64
#define CQKV  1536
#define BP    16
#define MTOT  65536
#define EPS   1e-12f

typedef __nv_bfloat16 bf16;

// ---------------- scratch (device globals) ----------------
__device__ bf16   g_xhi[(size_t)MTOT * 512];
__device__ bf16   g_xlo[(size_t)MTOT * 512];
__device__ bf16   g_wqhi[1024 * EDIM];            // only Wq|Wk rows needed
__device__ bf16   g_wqlo[1024 * EDIM];
__device__ bf16   g_Shi[BP * 512 * 512];
__device__ bf16   g_Slo[BP * 512 * 512];
__device__ float  g_Sp[(size_t)4 * BP * 10 * 128 * 128];   // SYRK k-partials
__device__ float  g_T[(size_t)BP * 512 * 1024];            // [Tq | Tk] per bp
__device__ float  g_s[BP * 512];
__device__ float  g_attnT[BP * HEADS * DH * DH];           // transposed: [e][d]
__device__ bf16   g_w2hi[BP * EDIM * QKV];
__device__ bf16   g_w2lo[BP * EDIM * QKV];
__device__ bf16   g_wvthi[EDIM * QKV];
__device__ bf16   g_wvtlo[EDIM * QKV];
__device__ bf16   g_w3hi[BP * EDIM * EDIM];
__device__ bf16   g_w3lo[BP * EDIM * EDIM];
__device__ float  g_b3[BP * EDIM];
__device__ float  g_zerobias[1024];               // stays zero

// ---------------- PTX helpers ----------------
__device__ __forceinline__ uint32_t smem_u32(const void* p) {
    uint32_t a;
    asm("{ .reg .u64 t; cvta.to.shared.u64 t, %1; cvt.u32.u64 %0, t; }" : "=r"(a) : "l"(p));
    return a;
}
__device__ __forceinline__ void cp16(uint32_t saddr, const void* gptr) {
    asm volatile("cp.async.cg.shared.global [%0], [%1], 16;" :: "r"(saddr), "l"(gptr));
}
__device__ __forceinline__ void ldsm4(uint32_t& r0, uint32_t& r1, uint32_t& r2, uint32_t& r3,
                                      uint32_t addr) {
    asm volatile("ldmatrix.sync.aligned.m8n8.x4.shared.b16 {%0,%1,%2,%3}, [%4];"
                 : "=r"(r0), "=r"(r1), "=r"(r2), "=r"(r3) : "r"(addr));
}
__device__ __forceinline__ void ldsm4t(uint32_t& r0, uint32_t& r1, uint32_t& r2, uint32_t& r3,
                                       uint32_t addr) {
    asm volatile("ldmatrix.sync.aligned.m8n8.x4.trans.shared.b16 {%0,%1,%2,%3}, [%4];"
                 : "=r"(r0), "=r"(r1), "=r"(r2), "=r"(r3) : "r"(addr));
}
__device__ __forceinline__ void mma16816(float* d, const uint32_t* a, uint32_t b0, uint32_t b1) {
    asm volatile(
        "mma.sync.aligned.m16n8k16.row.col.f32.bf16.bf16.f32 "
        "{%0,%1,%2,%3}, {%4,%5,%6,%7}, {%8,%9}, {%0,%1,%2,%3};"
        : "+f"(d[0]), "+f"(d[1]), "+f"(d[2]), "+f"(d[3])
        : "r"(a[0]), "r"(a[1]), "r"(a[2]), "r"(a[3]), "r"(b0), "r"(b1));
}
__device__ __forceinline__ __nv_bfloat162 hi2(float a, float b) {
    __nv_bfloat162 r; r.x = __float2bfloat16(a); r.y = __float2bfloat16(b); return r;
}
__device__ __forceinline__ __nv_bfloat162 lo2(float a, float b) {
    __nv_bfloat162 r;
    r.x = __float2bfloat16(a - __bfloat162float(__float2bfloat16(a)));
    r.y = __float2bfloat16(b - __bfloat162float(__float2bfloat16(b)));
    return r;
}

// ===========================================================================
// bf16x3 GEMM: C[m,n] = (Ahi+Alo)·(Bhi+Blo)^T + bias; K=512.
// 128x128 CTA tile, BK=32, 4 warps (2x2), warp tile 64x64, 2-stage cp.async.
// MMA issue order is PRODUCT-MAJOR: 32 independent accs between same-acc MMAs
// (breaks HMMA RAW chains that capped tensor pipe at ~44%).
// ===========================================================================
#define ROWB   80
#define MATB   (128 * ROWB)
#define STGB   (4 * MATB)               // 40960
#define OFF_AH 0
#define OFF_AL MATB
#define OFF_BH (2 * MATB)
#define OFF_BL (3 * MATB)
#define NKCH   16

__global__ __launch_bounds__(128, 2)
void gemm_bf16x3(const bf16* __restrict__ Ahi, const bf16* __restrict__ Alo,
                 const bf16* __restrict__ Bhi, const bf16* __restrict__ Blo,
                 const float* __restrict__ bias, int biasStride,
                 float* __restrict__ Cfp, bf16* __restrict__ Chi, bf16* __restrict__ Clo,
                 int ldc, long long bStride)
{
    extern __shared__ char smem[];
    uint32_t sb = smem_u32(smem);
    int tid = threadIdx.x, wid = tid >> 5, lane = tid & 31;
    int n0 = blockIdx.x * 128, m0 = blockIdx.y * 128;
    int batch = m0 >> 12;

    const bf16* bh = Bhi + (long long)batch * bStride;
    const bf16* bl = Blo + (long long)batch * bStride;

    float acc[4][8][4];
#pragma unroll
    for (int i = 0; i < 4; i++)
#pragma unroll
        for (int j = 0; j < 8; j++)
#pragma unroll
            for (int r = 0; r < 4; r++) acc[i][j][r] = 0.f;

    auto load_stage = [&](int chunk, int stage) {
        uint32_t st = sb + stage * STGB;
        int k0 = chunk * 32;
#pragma unroll
        for (int i = 0; i < 4; i++) {
            int idx = i * 128 + tid;          // 0..511
            int row = idx >> 2, c = idx & 3;
            uint32_t so = (uint32_t)(row * ROWB + c * 16);
            long long ga = (long long)(m0 + row) * 512 + k0 + c * 8;
            long long gb = (long long)(n0 + row) * 512 + k0 + c * 8;
            cp16(st + OFF_AH + so, Ahi + ga);
            cp16(st + OFF_AL + so, Alo + ga);
            cp16(st + OFF_BH + so, bh + gb);
            cp16(st + OFF_BL + so, bl + gb);
        }
        asm volatile("cp.async.commit_group;" ::: "memory");
    };

    load_stage(0, 0);

    int wm = wid >> 1, wn = wid & 1;                 // warp grid 2x2
    uint32_t aRowOff = (uint32_t)((wm * 64 + (lane & 15)) * ROWB + (lane >> 4) * 16);
    uint32_t bRowOff = (uint32_t)((wn * 64 + (lane & 15)) * ROWB + (lane >> 4) * 16);

    for (int c = 0; c < NKCH; c++) {
        if (c + 1 < NKCH) {
            load_stage(c + 1, (c + 1) & 1);
            asm volatile("cp.async.wait_group 1;" ::: "memory");
        } else {
            asm volatile("cp.async.wait_group 0;" ::: "memory");
        }
        __syncthreads();

        uint32_t st = sb + (c & 1) * STGB;
#pragma unroll
        for (int kk = 0; kk < 2; kk++) {
            uint32_t kOff = kk * 32;
            uint32_t aB = st + aRowOff + kOff;
            uint32_t bB = st + bRowOff + kOff;

            uint32_t aH[4][4], aL[4][4];
#pragma unroll
            for (int im = 0; im < 4; im++) {
                ldsm4(aH[im][0], aH[im][1], aH[im][2], aH[im][3], aB + OFF_AH + im * 16 * ROWB);
                ldsm4(aL[im][0], aL[im][1], aL[im][2], aL[im][3], aB + OFF_AL + im * 16 * ROWB);
            }
            uint32_t bH[4][4], bL[4][4];
#pragma unroll
            for (int ib = 0; ib < 4; ib++) {
                ldsm4(bH[ib][0], bH[ib][1], bH[ib][2], bH[ib][3], bB + OFF_BH + ib * 16 * ROWB);
                ldsm4(bL[ib][0], bL[ib][1], bL[ib][2], bL[ib][3], bB + OFF_BL + ib * 16 * ROWB);
            }
            // product-major: consecutive MMAs always hit different accumulators
#pragma unroll
            for (int im = 0; im < 4; im++)
#pragma unroll
                for (int jn = 0; jn < 8; jn++)
                    mma16816(acc[im][jn], aH[im], bH[jn >> 1][jn & 1], bH[jn >> 1][2 + (jn & 1)]);
#pragma unroll
            for (int im = 0; im < 4; im++)
#pragma unroll
                for (int jn = 0; jn < 8; jn++)
                    mma16816(acc[im][jn], aH[im], bL[jn >> 1][jn & 1], bL[jn >> 1][2 + (jn & 1)]);
#pragma unroll
            for (int im = 0; im < 4; im++)
#pragma unroll
                for (int jn = 0; jn < 8; jn++)
                    mma16816(acc[im][jn], aL[im], bH[jn >> 1][jn & 1], bH[jn >> 1][2 + (jn & 1)]);
        }
        __syncthreads();
    }

    const float* bb = bias + (long long)batch * biasStride;
    float bcol0[8], bcol1[8];
#pragma unroll
    for (int jn = 0; jn < 8; jn++) {
        int cc = n0 + wn * 64 + jn * 8 + 2 * (lane & 3);
        bcol0[jn] = bb[cc];
        bcol1[jn] = bb[cc + 1];
    }
#pragma unroll
    for (int im = 0; im < 4; im++) {
        int r0 = m0 + wm * 64 + im * 16 + (lane >> 2);
#pragma unroll
        for (int jn = 0; jn < 8; jn++) {
            int cc = n0 + wn * 64 + jn * 8 + 2 * (lane & 3);
            float v00 = acc[im][jn][0] + bcol0[jn];
            float v01 = acc[im][jn][1] + bcol1[jn];
            float v10 = acc[im][jn][2] + bcol0[jn];
            float v11 = acc[im][jn][3] + bcol1[jn];
            if (Chi) {
                *(__nv_bfloat162*)(Chi + (long long)r0 * ldc + cc)       = hi2(v00, v01);
                *(__nv_bfloat162*)(Clo + (long long)r0 * ldc + cc)       = lo2(v00, v01);
                *(__nv_bfloat162*)(Chi + (long long)(r0 + 8) * ldc + cc) = hi2(v10, v11);
                *(__nv_bfloat162*)(Clo + (long long)(r0 + 8) * ldc + cc) = lo2(v10, v11);
            } else {
                *(float2*)(Cfp + (long long)r0 * ldc + cc)       = make_float2(v00, v01);
                *(float2*)(Cfp + (long long)(r0 + 8) * ldc + cc) = make_float2(v10, v11);
            }
        }
    }
}

// ===========================================================================
// SYRK bf16x3 partials: grid (10 blocks, 4 kchunks, 16 bp); K=1024 each.
// Product-major MMA order as in the GEMM.
// ===========================================================================
#define SROWB  272
#define SMATB  (32 * SROWB)             // 8704
#define SSTGB  (4 * SMATB)              // 34816
#define S_AH   0
#define S_AL   SMATB
#define S_BH   (2 * SMATB)
#define S_BL   (3 * SMATB)

__constant__ int c_EB[10] = {0,0,0,0,1,1,1,2,2,3};
__constant__ int c_FB[10] = {0,1,2,3,1,2,3,2,3,3};

__global__ __launch_bounds__(128, 2)
void syrk_partial(const bf16* __restrict__ Xhi, const bf16* __restrict__ Xlo)
{
    extern __shared__ char smem[];
    uint32_t sb = smem_u32(smem);
    int tid = threadIdx.x, wid = tid >> 5, lane = tid & 31;
    int p = blockIdx.x, kc = blockIdx.y, bp = blockIdx.z;
    int e0 = c_EB[p] * 128, f0 = c_FB[p] * 128;
    long long xbase = (long long)bp * NTOK * 512;

    float acc[4][8][4];
#pragma unroll
    for (int i = 0; i < 4; i++)
#pragma unroll
        for (int j = 0; j < 8; j++)
#pragma unroll
            for (int r = 0; r < 4; r++) acc[i][j][r] = 0.f;

    auto load_stage = [&](int chunk, int stage) {
        uint32_t st = sb + stage * SSTGB;
        int t0 = kc * 1024 + chunk * 32;
#pragma unroll
        for (int i = 0; i < 4; i++) {
            int idx = i * 128 + tid;          // 0..511
            int row = idx >> 4, c = idx & 15;
            uint32_t so = (uint32_t)(row * SROWB + c * 16);
            long long ge = xbase + (long long)(t0 + row) * 512 + e0 + c * 8;
            long long gf = xbase + (long long)(t0 + row) * 512 + f0 + c * 8;
            cp16(st + S_AH + so, Xhi + ge);
            cp16(st + S_AL + so, Xlo + ge);
            cp16(st + S_BH + so, Xhi + gf);
            cp16(st + S_BL + so, Xlo + gf);
        }
        asm volatile("cp.async.commit_group;" ::: "memory");
    };

    load_stage(0, 0);

    int wm = wid >> 1, wn = wid & 1;
    int sub = lane >> 3;
    int nloc = (lane & 7) + ((sub >> 1) << 3);
    uint32_t cpad = (uint32_t)((sub & 1) * 16);
    uint32_t aColB = (uint32_t)((wm * 64) * 2) + cpad;
    uint32_t bColB = (uint32_t)((wn * 64) * 2) + cpad;

    const int NCH = 32;    // 1024 tokens / 32
    for (int c = 0; c < NCH; c++) {
        if (c + 1 < NCH) {
            load_stage(c + 1, (c + 1) & 1);
            asm volatile("cp.async.wait_group 1;" ::: "memory");
        } else {
            asm volatile("cp.async.wait_group 0;" ::: "memory");
        }
        __syncthreads();

        uint32_t st = sb + (c & 1) * SSTGB;
#pragma unroll
        for (int kk = 0; kk < 2; kk++) {
            uint32_t rowB = (uint32_t)((kk * 16 + nloc) * SROWB);
            uint32_t aB = st + rowB + aColB;
            uint32_t bB = st + rowB + bColB;

            uint32_t aH[4][4], aL[4][4];
#pragma unroll
            for (int im = 0; im < 4; im++) {
                ldsm4t(aH[im][0], aH[im][1], aH[im][2], aH[im][3], aB + S_AH + im * 32);
                ldsm4t(aL[im][0], aL[im][1], aL[im][2], aL[im][3], aB + S_AL + im * 32);
            }
            uint32_t bH[4][4], bL[4][4];
#pragma unroll
            for (int ib = 0; ib < 4; ib++) {
                ldsm4t(bH[ib][0], bH[ib][1], bH[ib][2], bH[ib][3], bB + S_BH + ib * 32);
                ldsm4t(bL[ib][0], bL[ib][1], bL[ib][2], bL[ib][3], bB + S_BL + ib * 32);
            }
#pragma unroll
            for (int im = 0; im < 4; im++)
#pragma unroll
                for (int jn = 0; jn < 8; jn++)
                    mma16816(acc[im][jn], aH[im], bH[jn >> 1][jn & 1], bH[jn >> 1][2 + (jn & 1)]);
#pragma unroll
            for (int im = 0; im < 4; im++)
#pragma unroll
                for (int jn = 0; jn < 8; jn++)
                    mma16816(acc[im][jn], aH[im], bL[jn >> 1][jn & 1], bL[jn >> 1][2 + (jn & 1)]);
#pragma unroll
            for (int im = 0; im < 4; im++)
#pragma unroll
                for (int jn = 0; jn < 8; jn++)
                    mma16816(acc[im][jn], aL[im], bH[jn >> 1][jn & 1], bH[jn >> 1][2 + (jn & 1)]);
        }
        __syncthreads();
    }

    float* dst = g_Sp + (((long long)kc * BP + bp) * 10 + p) * 16384;
#pragma unroll
    for (int im = 0; im < 4; im++) {
        int el = wm * 64 + im * 16 + (lane >> 2);
#pragma unroll
        for (int jn = 0; jn < 8; jn++) {
            int fl = wn * 64 + jn * 8 + 2 * (lane & 3);
            *(float2*)(dst + el * 128 + fl)       = make_float2(acc[im][jn][0], acc[im][jn][1]);
            *(float2*)(dst + (el + 8) * 128 + fl) = make_float2(acc[im][jn][2], acc[im][jn][3]);
        }
    }
}

// ===========================================================================
// SYRK finish: sum 4 partials, write bf16 hi/lo (both orientations via smem).
// ===========================================================================
__global__ __launch_bounds__(256)
void syrk_finish()
{
    extern __shared__ float tile[];    // 128 x 129
    int p = blockIdx.x, bp = blockIdx.y;
    int e0 = c_EB[p] * 128, f0 = c_FB[p] * 128;
    int tid = threadIdx.x;

    const float* p0 = g_Sp + (((long long)0 * BP + bp) * 10 + p) * 16384;
    const float* p1 = g_Sp + (((long long)1 * BP + bp) * 10 + p) * 16384;
    const float* p2 = g_Sp + (((long long)2 * BP + bp) * 10 + p) * 16384;
    const float* p3 = g_Sp + (((long long)3 * BP + bp) * 10 + p) * 16384;
    for (int idx = tid; idx < 16384; idx += 256) {
        float s = (p0[idx] + p1[idx]) + (p2[idx] + p3[idx]);
        tile[(idx >> 7) * 129 + (idx & 127)] = s;
    }
    __syncthreads();

    bf16* ShiB = g_Shi + (long long)bp * 512 * 512;
    bf16* SloB = g_Slo + (long long)bp * 512 * 512;
    for (int idx = tid; idx < 16384; idx += 256) {
        int r = idx >> 7, c = idx & 127;
        float v = tile[r * 129 + c];
        bf16 h = __float2bfloat16(v);
        ShiB[(long long)(e0 + r) * 512 + f0 + c] = h;
        SloB[(long long)(e0 + r) * 512 + f0 + c] = __float2bfloat16(v - __bfloat162float(h));
    }
    if (e0 != f0) {
        for (int idx = tid; idx < 16384; idx += 256) {
            int r = idx >> 7, c = idx & 127;
            float v = tile[c * 129 + r];
            bf16 h = __float2bfloat16(v);
            ShiB[(long long)(f0 + r) * 512 + e0 + c] = h;
            SloB[(long long)(f0 + r) * 512 + e0 + c] = __float2bfloat16(v - __bfloat162float(h));
        }
    }
}

// ===========================================================================
// fused x split + column sums
// ===========================================================================
__global__ __launch_bounds__(256) void split_colsum(const float* __restrict__ x) {
    int bp = blockIdx.x, ch = blockIdx.y, t = threadIdx.x;
    long long base = ((long long)bp * NTOK + ch * 256) * 512 + t * 2;
    float s0 = 0.f, s1 = 0.f;
    for (int n = 0; n < 256; n++) {
        long long idx = base + (long long)n * 512;
        float2 v = *(const float2*)(x + idx);
        s0 += v.x; s1 += v.y;
        ((__nv_bfloat162*)g_xhi)[idx >> 1] = hi2(v.x, v.y);
        ((__nv_bfloat162*)g_xlo)[idx >> 1] = lo2(v.x, v.y);
    }
    atomicAdd(&g_s[bp * 512 + t * 2], s0);
    atomicAdd(&g_s[bp * 512 + t * 2 + 1], s1);
}
__global__ void zero_s_kernel() {
    int i = blockIdx.x * blockDim.x + threadIdx.x;
    if (i < BP * 512) g_s[i] = 0.f;
}

// ===========================================================================
// weight splits
// ===========================================================================
__global__ __launch_bounds__(256) void split_bf16(const float* __restrict__ src,
                                                  bf16* __restrict__ hi,
                                                  bf16* __restrict__ lo, long long n4)
{
    long long i = (long long)blockIdx.x * 256 + threadIdx.x;
    if (i >= n4) return;
    float4 v = ((const float4*)src)[i];
    ((__nv_bfloat162*)hi)[i * 2]     = hi2(v.x, v.y);
    ((__nv_bfloat162*)hi)[i * 2 + 1] = hi2(v.z, v.w);
    ((__nv_bfloat162*)lo)[i * 2]     = lo2(v.x, v.y);
    ((__nv_bfloat162*)lo)[i * 2 + 1] = lo2(v.z, v.w);
}
__global__ __launch_bounds__(256) void wvt_split_kernel(const float* __restrict__ wqkv) {
    int i = blockIdx.x * 256 + threadIdx.x;
    if (i >= 512 * 512) return;
    int e = i >> 9, c = i & 511;
    float v = wqkv[(long long)(1024 + c) * 512 + e];
    bf16 hi = __float2bfloat16(v);
    g_wvthi[i] = hi;
    g_wvtlo[i] = __float2bfloat16(v - __bfloat162float(hi));
}

// ===========================================================================
// attention finish per (bp,h); writes attn TRANSPOSED ([e][d]) for make_w2
// ===========================================================================
__global__ __launch_bounds__(256) void attn_from_s(const float* __restrict__ wqkv,
                                                   const float* __restrict__ b_qkv,
                                                   const float* __restrict__ temp)
{
    int bp = blockIdx.x, h = blockIdx.y;
    int tid = threadIdx.x, tr = tid >> 4, tc = tid & 15;

    extern __shared__ float dyn[];
    float* wqs = dyn;                  // 64 x 68
    float* wks = dyn + 4352;
    float* tqs = dyn + 2 * 4352;
    float* tks = dyn + 3 * 4352;
    __shared__ float schunk[64];
    __shared__ float uqv[64], ukv[64], nqv[64], nkv[64], bqs[64], bks[64];

    if (tid < 64)       bqs[tid] = b_qkv[h * 64 + tid];
    else if (tid < 128) bks[tid - 64] = b_qkv[512 + h * 64 + (tid - 64)];

    float acc[4][4];
#pragma unroll
    for (int i = 0; i < 4; i++)
#pragma unroll
        for (int j = 0; j < 4; j++) acc[i][j] = 0.f;
    float uacc = 0.f, nacc = 0.f;

    const float* wq_h = wqkv + (long long)(h * 64) * 512;
    const float* wk_h = wqkv + (long long)(512 + h * 64) * 512;
    const float* T_b  = g_T + (long long)bp * 512 * 1024;
    const float* svec = g_s + bp * 512;

    for (int xc = 0; xc < 8; xc++) {
        __syncthreads();
#pragma unroll
        for (int i = 0; i < 4; i++) {
            int idx4 = i * 256 + tid;
            int row = idx4 >> 4, c4 = (idx4 & 15) * 4;
            *(float4*)&wqs[row * 68 + c4] = *(const float4*)(wq_h + (long long)row * 512 + xc * 64 + c4);
            *(float4*)&wks[row * 68 + c4] = *(const float4*)(wk_h + (long long)row * 512 + xc * 64 + c4);
            const float* trow = T_b + (long long)(xc * 64 + row) * 1024 + h * 64;
            *(float4*)&tqs[row * 68 + c4] = *(const float4*)(trow + c4);
            *(float4*)&tks[row * 68 + c4] = *(const float4*)(trow + 512 + c4);
        }
        if (tid < 64) schunk[tid] = svec[xc * 64 + tid];
        __syncthreads();
#pragma unroll 8
        for (int x = 0; x < 64; x++) {
            float rm[4], rn[4];
#pragma unroll
            for (int i = 0; i < 4; i++) rm[i] = wqs[(tr * 4 + i) * 68 + x];
            float4 r4 = *(const float4*)&tks[x * 68 + tc * 4];
            rn[0] = r4.x; rn[1] = r4.y; rn[2] = r4.z; rn[3] = r4.w;
#pragma unroll
            for (int i = 0; i < 4; i++)
#pragma unroll
                for (int j = 0; j < 4; j++) acc[i][j] += rm[i] * rn[j];
        }
        if (tid < 64) {
            int d = tid;
            for (int x = 0; x < 64; x++) {
                float w = wqs[d * 68 + x];
                uacc += w * schunk[x];
                nacc += w * tqs[x * 68 + d];
            }
        } else if (tid < 128) {
            int d = tid - 64;
            for (int x = 0; x < 64; x++) {
                float w = wks[d * 68 + x];
                uacc += w * schunk[x];
                nacc += w * tks[x * 68 + d];
            }
        }
    }

    if (tid < 64) {
        float b = bqs[tid];
        float n2 = nacc + 2.f * b * uacc + (float)NTOK * b * b;
        nqv[tid] = fmaxf(sqrtf(fmaxf(n2, 0.f)), EPS);
        uqv[tid] = uacc;
    } else if (tid < 128) {
        int d = tid - 64;
        float b = bks[d];
        float n2 = nacc + 2.f * b * uacc + (float)NTOK * b * b;
        nkv[d] = fmaxf(sqrtf(fmaxf(n2, 0.f)), EPS);
        ukv[d] = uacc;
    }
    __syncthreads();

    float tf = temp[h];
    float* Gs = wqs;
#pragma unroll
    for (int i = 0; i < 4; i++) {
        int d = tr * 4 + i;
#pragma unroll
        for (int j = 0; j < 4; j++) {
            int e = tc * 4 + j;
            float G = acc[i][j] + bqs[d] * ukv[e] + bks[e] * uqv[d]
                      + (float)NTOK * bqs[d] * bks[e];
            Gs[d * 64 + e] = G * tf / (nqv[d] * nkv[e]);
        }
    }
    __syncthreads();

    int warp = tid >> 5, lane = tid & 31;
    float* attn_base = g_attnT + ((long long)(bp * HEADS + h) << 12);
    for (int rr = 0; rr < 8; rr++) {
        int r = warp * 8 + rr;      // d index
        float x0 = Gs[r * 64 + lane];
        float x1 = Gs[r * 64 + 32 + lane];
        float m = fmaxf(x0, x1);
#pragma unroll
        for (int o = 16; o > 0; o >>= 1) m = fmaxf(m, __shfl_xor_sync(0xffffffffu, m, o));
        float e0 = expf(x0 - m), e1 = expf(x1 - m);
        float ssum = e0 + e1;
#pragma unroll
        for (int o = 16; o > 0; o >>= 1) ssum += __shfl_xor_sync(0xffffffffu, ssum, o);
        float inv = 1.f / ssum;
        // transposed store: attnT[e*64 + d]
        attn_base[lane * 64 + r]        = e0 * inv;
        attn_base[(lane + 32) * 64 + r] = e1 * inv;
    }
}

// ===========================================================================
// W2[bp][f, h*64+e] = sum_d w_out[f, h*64+d]*attnT[bp,h,e,d] -> bf16 hi/lo
// (both operands contiguous)
// ===========================================================================
__global__ __launch_bounds__(256) void make_w2_kernel(const float* __restrict__ w_out) {
    long long i = (long long)blockIdx.x * 256 + threadIdx.x;
    int c = (int)(i & 511);
    int f = (int)((i >> 9) & 511);
    int bp = (int)(i >> 18);
    int h = c >> 6, e = c & 63;
    const float* wrow = w_out + f * 512 + h * 64;
    const float* arow = g_attnT + ((long long)(bp * HEADS + h) << 12) + e * 64;
    float s = 0.f;
#pragma unroll 16
    for (int d = 0; d < 64; d++) s += wrow[d] * arow[d];
    bf16 hi = __float2bfloat16(s);
    g_w2hi[i] = hi;
    g_w2lo[i] = __float2bfloat16(s - __bfloat162float(hi));
}

// ===========================================================================
// b3: warp-per-row coalesced reduction
// ===========================================================================
__global__ __launch_bounds__(256) void b3_kernel(const float* __restrict__ b_qkv,
                                                 const float* __restrict__ b_out) {
    int row = blockIdx.x * 8 + (threadIdx.x >> 5);
    int lane = threadIdx.x & 31;
    const bf16* hi = g_w2hi + (long long)row * 512;
    const bf16* lo = g_w2lo + (long long)row * 512;
    const float* bv = b_qkv + 1024;
    float s = 0.f;
#pragma unroll
    for (int i = 0; i < 16; i++) {
        int c = lane + 32 * i;
        s += (__bfloat162float(hi[c]) + __bfloat162float(lo[c])) * bv[c];
    }
#pragma unroll
    for (int o = 16; o > 0; o >>= 1) s += __shfl_xor_sync(0xffffffffu, s, o);
    if (lane == 0) g_b3[row] = s + b_out[row & 511];
}

// ===========================================================================
// launch
// ===========================================================================
extern "C" void kernel_launch(void* const* d_in, const int* in_sizes, int n_in,
                              void* d_out, int out_size)
{
    const float* x     = (const float*)d_in[0];
    const float* wq    = (const float*)d_in[1];
    const float* b_qkv = (const float*)d_in[2];
    const float* temp  = (const float*)d_in[3];
    const float* w_out = (const float*)d_in[4];
    const float* b_out = (const float*)d_in[5];
    float* out = (float*)d_out;

    bf16 *xhi_p, *xlo_p, *wqhi_p, *wqlo_p, *Shi_p, *Slo_p, *w2hi_p, *w2lo_p;
    bf16 *wvthi_p, *wvtlo_p, *w3hi_p, *w3lo_p;
    float *T_p, *b3_p, *zb_p;
    cudaGetSymbolAddress((void**)&xhi_p,  g_xhi);
    cudaGetSymbolAddress((void**)&xlo_p,  g_xlo);
    cudaGetSymbolAddress((void**)&wqhi_p, g_wqhi);
    cudaGetSymbolAddress((void**)&wqlo_p, g_wqlo);
    cudaGetSymbolAddress((void**)&Shi_p,  g_Shi);
    cudaGetSymbolAddress((void**)&Slo_p,  g_Slo);
    cudaGetSymbolAddress((void**)&T_p,    g_T);
    cudaGetSymbolAddress((void**)&w2hi_p, g_w2hi);
    cudaGetSymbolAddress((void**)&w2lo_p, g_w2lo);
    cudaGetSymbolAddress((void**)&wvthi_p, g_wvthi);
    cudaGetSymbolAddress((void**)&wvtlo_p, g_wvtlo);
    cudaGetSymbolAddress((void**)&w3hi_p, g_w3hi);
    cudaGetSymbolAddress((void**)&w3lo_p, g_w3lo);
    cudaGetSymbolAddress((void**)&b3_p,   g_b3);
    cudaGetSymbolAddress((void**)&zb_p,   g_zerobias);

    const int GEMM_SMEM = 2 * STGB;      // 81920
    const int SYRK_SMEM = 2 * SSTGB;     // 69632
    const int ATTN_SMEM = 4 * 4352 * 4;  // 69632
    const int FIN_SMEM  = 128 * 129 * 4; // 66048
    cudaFuncSetAttribute(gemm_bf16x3,  cudaFuncAttributeMaxDynamicSharedMemorySize, GEMM_SMEM);
    cudaFuncSetAttribute(syrk_partial, cudaFuncAttributeMaxDynamicSharedMemorySize, SYRK_SMEM);
    cudaFuncSetAttribute(attn_from_s,  cudaFuncAttributeMaxDynamicSharedMemorySize, ATTN_SMEM);
    cudaFuncSetAttribute(syrk_finish,  cudaFuncAttributeMaxDynamicSharedMemorySize, FIN_SMEM);

    // 1. splits + column sums (single read of x)
    zero_s_kernel<<<(BP * 512 + 255) / 256, 256>>>();
    {
        dim3 grid(BP, NTOK / 256);
        split_colsum<<<grid, 256>>>(x);
    }
    split_bf16<<<(1024 * EDIM / 4 + 255) / 256, 256>>>(wq, wqhi_p, wqlo_p, 1024 * EDIM / 4);
    wvt_split_kernel<<<(512 * 512 + 255) / 256, 256>>>(wq);

    // 2. S = X^T X: balanced k-split partials, then reduce+mirror+split
    {
        dim3 grid(10, 4, BP);
        syrk_partial<<<grid, 128, SYRK_SMEM>>>(xhi_p, xlo_p);
    }
    {
        dim3 grid(10, BP);
        syrk_finish<<<grid, 256, FIN_SMEM>>>();
    }

    // 3. T = S·[Wq|Wk]^T
    {
        dim3 grid(8, BP * 512 / 128);
        gemm_bf16x3<<<grid, 128, GEMM_SMEM>>>(Shi_p, Slo_p, wqhi_p, wqlo_p,
                                              zb_p, 0, T_p, nullptr, nullptr, 1024, 0LL);
    }

    // 4. attention logits + softmax (writes transposed attn)
    {
        dim3 grid(BP, HEADS);
        attn_from_s<<<grid, 256, ATTN_SMEM>>>(wq, b_qkv, temp);
    }

    // 5. W2; W3 = W2·Wv (bf16 out); b3
    make_w2_kernel<<<(BP * EDIM * QKV) / 256, 256>>>(w_out);
    {
        dim3 grid(4, BP * 512 / 128);
        gemm_bf16x3<<<grid, 128, GEMM_SMEM>>>(w2hi_p, w2lo_p, wvthi_p, wvtlo_p,
                                              zb_p, 0, nullptr, w3hi_p, w3lo_p, 512, 0LL);
    }
    b3_kernel<<<(BP * 512) / 8, 256>>>(b_qkv, b_out);

    // 6. out = X · W3[bp]^T + b3[bp]
    {
        dim3 grid(EDIM / 128, MTOT / 128);
        gemm_bf16x3<<<grid, 128, GEMM_SMEM>>>(xhi_p, xlo_p, w3hi_p, w3lo_p,
                                              b3_p, 512, out, nullptr, nullptr, 512,
                                              (long long)512 * 512);
    }
}

// round 10
// speedup vs baseline: 1.0509x; 1.0509x over previous
#include <cuda_runtime.h>
#include <cuda_fp16.h>
#include <cstdint>
#include <math.h>

// ---------------- problem constants ----------------
#define NTOK  4096
#define EDIM  512
#define QKV   512
#define HEADS 8
#define DH    64
#define BP    16
#define MTOT  65536
#define EPS   1e-12f

typedef __half h16;

// ---------------- scratch (device globals) ----------------
__device__ h16    g_xhi[(size_t)MTOT * 512];
__device__ h16    g_xlo[(size_t)MTOT * 512];
__device__ h16    g_wqhi[1024 * EDIM];            // Wq|Wk rows, fp16 hi
__device__ h16    g_wqlo[1024 * EDIM];
__device__ h16    g_Sf16[BP * 512 * 512];         // S single fp16
__device__ float  g_Sp[(size_t)4 * BP * 10 * 128 * 128];   // SYRK k-partials
__device__ float  g_T[(size_t)BP * 512 * 1024];            // [Tq | Tk] per bp
__device__ float  g_s[BP * 512];
__device__ float  g_attnT[BP * HEADS * DH * DH];           // transposed [e][d]
__device__ h16    g_w2hi[BP * EDIM * QKV];
__device__ h16    g_w2lo[BP * EDIM * QKV];
__device__ h16    g_wvthi[EDIM * QKV];
__device__ h16    g_wvtlo[EDIM * QKV];
__device__ h16    g_w3hi[BP * EDIM * EDIM];
__device__ h16    g_w3lo[BP * EDIM * EDIM];
__device__ float  g_b3[BP * EDIM];
__device__ float  g_zerobias[1024];               // stays zero

// ---------------- PTX helpers ----------------
__device__ __forceinline__ uint32_t smem_u32(const void* p) {
    uint32_t a;
    asm("{ .reg .u64 t; cvta.to.shared.u64 t, %1; cvt.u32.u64 %0, t; }" : "=r"(a) : "l"(p));
    return a;
}
__device__ __forceinline__ void cp16(uint32_t saddr, const void* gptr) {
    asm volatile("cp.async.cg.shared.global [%0], [%1], 16;" :: "r"(saddr), "l"(gptr));
}
__device__ __forceinline__ void ldsm4(uint32_t& r0, uint32_t& r1, uint32_t& r2, uint32_t& r3,
                                      uint32_t addr) {
    asm volatile("ldmatrix.sync.aligned.m8n8.x4.shared.b16 {%0,%1,%2,%3}, [%4];"
                 : "=r"(r0), "=r"(r1), "=r"(r2), "=r"(r3) : "r"(addr));
}
__device__ __forceinline__ void ldsm4t(uint32_t& r0, uint32_t& r1, uint32_t& r2, uint32_t& r3,
                                       uint32_t addr) {
    asm volatile("ldmatrix.sync.aligned.m8n8.x4.trans.shared.b16 {%0,%1,%2,%3}, [%4];"
                 : "=r"(r0), "=r"(r1), "=r"(r2), "=r"(r3) : "r"(addr));
}
__device__ __forceinline__ void mma16816(float* d, const uint32_t* a, uint32_t b0, uint32_t b1) {
    asm volatile(
        "mma.sync.aligned.m16n8k16.row.col.f32.f16.f16.f32 "
        "{%0,%1,%2,%3}, {%4,%5,%6,%7}, {%8,%9}, {%0,%1,%2,%3};"
        : "+f"(d[0]), "+f"(d[1]), "+f"(d[2]), "+f"(d[3])
        : "r"(a[0]), "r"(a[1]), "r"(a[2]), "r"(a[3]), "r"(b0), "r"(b1));
}
__device__ __forceinline__ __half2 h2hi(float a, float b) {
    return __floats2half2_rn(a, b);
}
__device__ __forceinline__ __half2 h2lo(float a, float b) {
    __half2 r;
    r.x = __float2half(a - __half2float(__float2half(a)));
    r.y = __float2half(b - __half2float(__float2half(b)));
    return r;
}

// ===========================================================================
// fp16 GEMM: C[m,n] = A·B^T + bias; K=512; A,B K-contiguous (stride 512).
// TRIPLE=true : A hi/lo + B hi/lo, 3 products (hi·hi + hi·lo + lo·hi).
// TRIPLE=false: A single + B hi/lo, 2 products (A·Bhi + A·Blo).
// 128x128 CTA tile, BK=32, 4 warps (2x2), warp tile 64x64, 2-stage cp.async.
// Round-8 interleaved MMA schedule (proven best).
// ===========================================================================
#define ROWB   80
#define MATB   (128 * ROWB)
#define STGB   (4 * MATB)               // 40960
#define OFF_AH 0
#define OFF_AL MATB
#define OFF_BH (2 * MATB)
#define OFF_BL (3 * MATB)
#define NKCH   16

template <bool TRIPLE>
__global__ __launch_bounds__(128, 2)
void gemm_f16(const h16* __restrict__ Ahi, const h16* __restrict__ Alo,
              const h16* __restrict__ Bhi, const h16* __restrict__ Blo,
              const float* __restrict__ bias, int biasStride,
              float* __restrict__ Cfp, h16* __restrict__ Chi, h16* __restrict__ Clo,
              int ldc, long long bStride)
{
    extern __shared__ char smem[];
    uint32_t sb = smem_u32(smem);
    int tid = threadIdx.x, wid = tid >> 5, lane = tid & 31;
    int n0 = blockIdx.x * 128, m0 = blockIdx.y * 128;
    int batch = m0 >> 12;

    const h16* bh = Bhi + (long long)batch * bStride;
    const h16* bl = Blo + (long long)batch * bStride;

    float acc[4][8][4];
#pragma unroll
    for (int i = 0; i < 4; i++)
#pragma unroll
        for (int j = 0; j < 8; j++)
#pragma unroll
            for (int r = 0; r < 4; r++) acc[i][j][r] = 0.f;

    auto load_stage = [&](int chunk, int stage) {
        uint32_t st = sb + stage * STGB;
        int k0 = chunk * 32;
#pragma unroll
        for (int i = 0; i < 4; i++) {
            int idx = i * 128 + tid;          // 0..511
            int row = idx >> 2, c = idx & 3;
            uint32_t so = (uint32_t)(row * ROWB + c * 16);
            long long ga = (long long)(m0 + row) * 512 + k0 + c * 8;
            long long gb = (long long)(n0 + row) * 512 + k0 + c * 8;
            cp16(st + OFF_AH + so, Ahi + ga);
            if (TRIPLE) cp16(st + OFF_AL + so, Alo + ga);
            cp16(st + OFF_BH + so, bh + gb);
            cp16(st + OFF_BL + so, bl + gb);
        }
        asm volatile("cp.async.commit_group;" ::: "memory");
    };

    load_stage(0, 0);

    int wm = wid >> 1, wn = wid & 1;                 // warp grid 2x2
    uint32_t aRowOff = (uint32_t)((wm * 64 + (lane & 15)) * ROWB + (lane >> 4) * 16);
    uint32_t bRowOff = (uint32_t)((wn * 64 + (lane & 15)) * ROWB + (lane >> 4) * 16);

    for (int c = 0; c < NKCH; c++) {
        if (c + 1 < NKCH) {
            load_stage(c + 1, (c + 1) & 1);
            asm volatile("cp.async.wait_group 1;" ::: "memory");
        } else {
            asm volatile("cp.async.wait_group 0;" ::: "memory");
        }
        __syncthreads();

        uint32_t st = sb + (c & 1) * STGB;
#pragma unroll
        for (int kk = 0; kk < 2; kk++) {
            uint32_t kOff = kk * 32;
            uint32_t aB = st + aRowOff + kOff;
            uint32_t bB = st + bRowOff + kOff;

            uint32_t aH[4][4], aL[4][4];
#pragma unroll
            for (int im = 0; im < 4; im++) {
                ldsm4(aH[im][0], aH[im][1], aH[im][2], aH[im][3], aB + OFF_AH + im * 16 * ROWB);
                if (TRIPLE)
                    ldsm4(aL[im][0], aL[im][1], aL[im][2], aL[im][3], aB + OFF_AL + im * 16 * ROWB);
            }
            uint32_t bH[4][4], bL[4][4];
#pragma unroll
            for (int ib = 0; ib < 4; ib++) {
                ldsm4(bH[ib][0], bH[ib][1], bH[ib][2], bH[ib][3], bB + OFF_BH + ib * 16 * ROWB);
                ldsm4(bL[ib][0], bL[ib][1], bL[ib][2], bL[ib][3], bB + OFF_BL + ib * 16 * ROWB);
            }
#pragma unroll
            for (int im = 0; im < 4; im++) {
#pragma unroll
                for (int jn = 0; jn < 8; jn++) {
                    int ib = jn >> 1, js = jn & 1;
                    mma16816(acc[im][jn], aH[im], bH[ib][js], bH[ib][2 + js]);
                    mma16816(acc[im][jn], aH[im], bL[ib][js], bL[ib][2 + js]);
                    if (TRIPLE)
                        mma16816(acc[im][jn], aL[im], bH[ib][js], bH[ib][2 + js]);
                }
            }
        }
        __syncthreads();
    }

    const float* bb = bias + (long long)batch * biasStride;
    float bcol0[8], bcol1[8];
#pragma unroll
    for (int jn = 0; jn < 8; jn++) {
        int cc = n0 + wn * 64 + jn * 8 + 2 * (lane & 3);
        bcol0[jn] = bb[cc];
        bcol1[jn] = bb[cc + 1];
    }
#pragma unroll
    for (int im = 0; im < 4; im++) {
        int r0 = m0 + wm * 64 + im * 16 + (lane >> 2);
#pragma unroll
        for (int jn = 0; jn < 8; jn++) {
            int cc = n0 + wn * 64 + jn * 8 + 2 * (lane & 3);
            float v00 = acc[im][jn][0] + bcol0[jn];
            float v01 = acc[im][jn][1] + bcol1[jn];
            float v10 = acc[im][jn][2] + bcol0[jn];
            float v11 = acc[im][jn][3] + bcol1[jn];
            if (Chi) {
                *(__half2*)(Chi + (long long)r0 * ldc + cc)       = h2hi(v00, v01);
                *(__half2*)(Clo + (long long)r0 * ldc + cc)       = h2lo(v00, v01);
                *(__half2*)(Chi + (long long)(r0 + 8) * ldc + cc) = h2hi(v10, v11);
                *(__half2*)(Clo + (long long)(r0 + 8) * ldc + cc) = h2lo(v10, v11);
            } else {
                *(float2*)(Cfp + (long long)r0 * ldc + cc)       = make_float2(v00, v01);
                *(float2*)(Cfp + (long long)(r0 + 8) * ldc + cc) = make_float2(v10, v11);
            }
        }
    }
}

// ===========================================================================
// SYRK fp16x3 partials: grid (10 blocks, 4 kchunks, 16 bp); K=1024 each.
// Diagonal blocks (e0==f0) alias B tiles onto A tiles (half the loads).
// ===========================================================================
#define SROWB  272
#define SMATB  (32 * SROWB)             // 8704
#define SSTGB  (4 * SMATB)              // 34816
#define S_AH   0
#define S_AL   SMATB
#define S_BH   (2 * SMATB)
#define S_BL   (3 * SMATB)

__constant__ int c_EB[10] = {0,0,0,0,1,1,1,2,2,3};
__constant__ int c_FB[10] = {0,1,2,3,1,2,3,2,3,3};

__global__ __launch_bounds__(128, 2)
void syrk_partial(const h16* __restrict__ Xhi, const h16* __restrict__ Xlo)
{
    extern __shared__ char smem[];
    uint32_t sb = smem_u32(smem);
    int tid = threadIdx.x, wid = tid >> 5, lane = tid & 31;
    int p = blockIdx.x, kc = blockIdx.y, bp = blockIdx.z;
    int e0 = c_EB[p] * 128, f0 = c_FB[p] * 128;
    bool diag = (e0 == f0);
    long long xbase = (long long)bp * NTOK * 512;

    float acc[4][8][4];
#pragma unroll
    for (int i = 0; i < 4; i++)
#pragma unroll
        for (int j = 0; j < 8; j++)
#pragma unroll
            for (int r = 0; r < 4; r++) acc[i][j][r] = 0.f;

    auto load_stage = [&](int chunk, int stage) {
        uint32_t st = sb + stage * SSTGB;
        int t0 = kc * 1024 + chunk * 32;
#pragma unroll
        for (int i = 0; i < 4; i++) {
            int idx = i * 128 + tid;          // 0..511
            int row = idx >> 4, c = idx & 15;
            uint32_t so = (uint32_t)(row * SROWB + c * 16);
            long long ge = xbase + (long long)(t0 + row) * 512 + e0 + c * 8;
            cp16(st + S_AH + so, Xhi + ge);
            cp16(st + S_AL + so, Xlo + ge);
            if (!diag) {
                long long gf = xbase + (long long)(t0 + row) * 512 + f0 + c * 8;
                cp16(st + S_BH + so, Xhi + gf);
                cp16(st + S_BL + so, Xlo + gf);
            }
        }
        asm volatile("cp.async.commit_group;" ::: "memory");
    };

    load_stage(0, 0);

    int wm = wid >> 1, wn = wid & 1;
    int sub = lane >> 3;
    int nloc = (lane & 7) + ((sub >> 1) << 3);
    uint32_t cpad = (uint32_t)((sub & 1) * 16);
    uint32_t aColB = (uint32_t)((wm * 64) * 2) + cpad;
    uint32_t bColB = (uint32_t)((wn * 64) * 2) + cpad;
    uint32_t offBH = diag ? S_AH : S_BH;
    uint32_t offBL = diag ? S_AL : S_BL;

    const int NCH = 32;    // 1024 tokens / 32
    for (int c = 0; c < NCH; c++) {
        if (c + 1 < NCH) {
            load_stage(c + 1, (c + 1) & 1);
            asm volatile("cp.async.wait_group 1;" ::: "memory");
        } else {
            asm volatile("cp.async.wait_group 0;" ::: "memory");
        }
        __syncthreads();

        uint32_t st = sb + (c & 1) * SSTGB;
#pragma unroll
        for (int kk = 0; kk < 2; kk++) {
            uint32_t rowB = (uint32_t)((kk * 16 + nloc) * SROWB);
            uint32_t aB = st + rowB + aColB;
            uint32_t bB = st + rowB + bColB;

            uint32_t aH[4][4], aL[4][4];
#pragma unroll
            for (int im = 0; im < 4; im++) {
                ldsm4t(aH[im][0], aH[im][1], aH[im][2], aH[im][3], aB + S_AH + im * 32);
                ldsm4t(aL[im][0], aL[im][1], aL[im][2], aL[im][3], aB + S_AL + im * 32);
            }
            uint32_t bH[4][4], bL[4][4];
#pragma unroll
            for (int ib = 0; ib < 4; ib++) {
                ldsm4t(bH[ib][0], bH[ib][1], bH[ib][2], bH[ib][3], bB + offBH + ib * 32);
                ldsm4t(bL[ib][0], bL[ib][1], bL[ib][2], bL[ib][3], bB + offBL + ib * 32);
            }
#pragma unroll
            for (int im = 0; im < 4; im++) {
#pragma unroll
                for (int jn = 0; jn < 8; jn++) {
                    int ib = jn >> 1, js = jn & 1;
                    mma16816(acc[im][jn], aH[im], bH[ib][js], bH[ib][2 + js]);
                    mma16816(acc[im][jn], aH[im], bL[ib][js], bL[ib][2 + js]);
                    mma16816(acc[im][jn], aL[im], bH[ib][js], bH[ib][2 + js]);
                }
            }
        }
        __syncthreads();
    }

    float* dst = g_Sp + (((long long)kc * BP + bp) * 10 + p) * 16384;
#pragma unroll
    for (int im = 0; im < 4; im++) {
        int el = wm * 64 + im * 16 + (lane >> 2);
#pragma unroll
        for (int jn = 0; jn < 8; jn++) {
            int fl = wn * 64 + jn * 8 + 2 * (lane & 3);
            *(float2*)(dst + el * 128 + fl)       = make_float2(acc[im][jn][0], acc[im][jn][1]);
            *(float2*)(dst + (el + 8) * 128 + fl) = make_float2(acc[im][jn][2], acc[im][jn][3]);
        }
    }
}

// ===========================================================================
// SYRK finish: sum 4 partials, write single fp16 (both orientations).
// ===========================================================================
__global__ __launch_bounds__(256)
void syrk_finish()
{
    extern __shared__ float tile[];    // 128 x 129
    int p = blockIdx.x, bp = blockIdx.y;
    int e0 = c_EB[p] * 128, f0 = c_FB[p] * 128;
    int tid = threadIdx.x;

    const float* p0 = g_Sp + (((long long)0 * BP + bp) * 10 + p) * 16384;
    const float* p1 = g_Sp + (((long long)1 * BP + bp) * 10 + p) * 16384;
    const float* p2 = g_Sp + (((long long)2 * BP + bp) * 10 + p) * 16384;
    const float* p3 = g_Sp + (((long long)3 * BP + bp) * 10 + p) * 16384;
    for (int idx = tid; idx < 16384; idx += 256) {
        float s = (p0[idx] + p1[idx]) + (p2[idx] + p3[idx]);
        tile[(idx >> 7) * 129 + (idx & 127)] = s;
    }
    __syncthreads();

    h16* SB = g_Sf16 + (long long)bp * 512 * 512;
    for (int idx = tid; idx < 16384; idx += 256) {
        int r = idx >> 7, c = idx & 127;
        SB[(long long)(e0 + r) * 512 + f0 + c] = __float2half(tile[r * 129 + c]);
    }
    if (e0 != f0) {
        for (int idx = tid; idx < 16384; idx += 256) {
            int r = idx >> 7, c = idx & 127;
            SB[(long long)(f0 + r) * 512 + e0 + c] = __float2half(tile[c * 129 + r]);
        }
    }
}

// ===========================================================================
// fused x split (fp16 hi/lo) + column sums
// ===========================================================================
__global__ __launch_bounds__(256) void split_colsum(const float* __restrict__ x) {
    int bp = blockIdx.x, ch = blockIdx.y, t = threadIdx.x;
    long long base = ((long long)bp * NTOK + ch * 256) * 512 + t * 2;
    float s0 = 0.f, s1 = 0.f;
    for (int n = 0; n < 256; n++) {
        long long idx = base + (long long)n * 512;
        float2 v = *(const float2*)(x + idx);
        s0 += v.x; s1 += v.y;
        ((__half2*)g_xhi)[idx >> 1] = h2hi(v.x, v.y);
        ((__half2*)g_xlo)[idx >> 1] = h2lo(v.x, v.y);
    }
    atomicAdd(&g_s[bp * 512 + t * 2], s0);
    atomicAdd(&g_s[bp * 512 + t * 2 + 1], s1);
}
__global__ void zero_s_kernel() {
    int i = blockIdx.x * blockDim.x + threadIdx.x;
    if (i < BP * 512) g_s[i] = 0.f;
}

// ===========================================================================
// weight splits (fp16 hi/lo)
// ===========================================================================
__global__ __launch_bounds__(256) void split_f16(const float* __restrict__ src,
                                                 h16* __restrict__ hi,
                                                 h16* __restrict__ lo, long long n4)
{
    long long i = (long long)blockIdx.x * 256 + threadIdx.x;
    if (i >= n4) return;
    float4 v = ((const float4*)src)[i];
    ((__half2*)hi)[i * 2]     = h2hi(v.x, v.y);
    ((__half2*)hi)[i * 2 + 1] = h2hi(v.z, v.w);
    ((__half2*)lo)[i * 2]     = h2lo(v.x, v.y);
    ((__half2*)lo)[i * 2 + 1] = h2lo(v.z, v.w);
}
__global__ __launch_bounds__(256) void wvt_split_kernel(const float* __restrict__ wqkv) {
    int i = blockIdx.x * 256 + threadIdx.x;
    if (i >= 512 * 512) return;
    int e = i >> 9, c = i & 511;
    float v = wqkv[(long long)(1024 + c) * 512 + e];
    h16 hi = __float2half(v);
    g_wvthi[i] = hi;
    g_wvtlo[i] = __float2half(v - __half2float(hi));
}

// ===========================================================================
// attention finish per (bp,h); writes attn TRANSPOSED ([e][d]) for make_w2
// ===========================================================================
__global__ __launch_bounds__(256) void attn_from_s(const float* __restrict__ wqkv,
                                                   const float* __restrict__ b_qkv,
                                                   const float* __restrict__ temp)
{
    int bp = blockIdx.x, h = blockIdx.y;
    int tid = threadIdx.x, tr = tid >> 4, tc = tid & 15;

    extern __shared__ float dyn[];
    float* wqs = dyn;                  // 64 x 68
    float* wks = dyn + 4352;
    float* tqs = dyn + 2 * 4352;
    float* tks = dyn + 3 * 4352;
    __shared__ float schunk[64];
    __shared__ float uqv[64], ukv[64], nqv[64], nkv[64], bqs[64], bks[64];

    if (tid < 64)       bqs[tid] = b_qkv[h * 64 + tid];
    else if (tid < 128) bks[tid - 64] = b_qkv[512 + h * 64 + (tid - 64)];

    float acc[4][4];
#pragma unroll
    for (int i = 0; i < 4; i++)
#pragma unroll
        for (int j = 0; j < 4; j++) acc[i][j] = 0.f;
    float uacc = 0.f, nacc = 0.f;

    const float* wq_h = wqkv + (long long)(h * 64) * 512;
    const float* wk_h = wqkv + (long long)(512 + h * 64) * 512;
    const float* T_b  = g_T + (long long)bp * 512 * 1024;
    const float* svec = g_s + bp * 512;

    for (int xc = 0; xc < 8; xc++) {
        __syncthreads();
#pragma unroll
        for (int i = 0; i < 4; i++) {
            int idx4 = i * 256 + tid;
            int row = idx4 >> 4, c4 = (idx4 & 15) * 4;
            *(float4*)&wqs[row * 68 + c4] = *(const float4*)(wq_h + (long long)row * 512 + xc * 64 + c4);
            *(float4*)&wks[row * 68 + c4] = *(const float4*)(wk_h + (long long)row * 512 + xc * 64 + c4);
            const float* trow = T_b + (long long)(xc * 64 + row) * 1024 + h * 64;
            *(float4*)&tqs[row * 68 + c4] = *(const float4*)(trow + c4);
            *(float4*)&tks[row * 68 + c4] = *(const float4*)(trow + 512 + c4);
        }
        if (tid < 64) schunk[tid] = svec[xc * 64 + tid];
        __syncthreads();
#pragma unroll 8
        for (int x = 0; x < 64; x++) {
            float rm[4], rn[4];
#pragma unroll
            for (int i = 0; i < 4; i++) rm[i] = wqs[(tr * 4 + i) * 68 + x];
            float4 r4 = *(const float4*)&tks[x * 68 + tc * 4];
            rn[0] = r4.x; rn[1] = r4.y; rn[2] = r4.z; rn[3] = r4.w;
#pragma unroll
            for (int i = 0; i < 4; i++)
#pragma unroll
                for (int j = 0; j < 4; j++) acc[i][j] += rm[i] * rn[j];
        }
        if (tid < 64) {
            int d = tid;
            for (int x = 0; x < 64; x++) {
                float w = wqs[d * 68 + x];
                uacc += w * schunk[x];
                nacc += w * tqs[x * 68 + d];
            }
        } else if (tid < 128) {
            int d = tid - 64;
            for (int x = 0; x < 64; x++) {
                float w = wks[d * 68 + x];
                uacc += w * schunk[x];
                nacc += w * tks[x * 68 + d];
            }
        }
    }

    if (tid < 64) {
        float b = bqs[tid];
        float n2 = nacc + 2.f * b * uacc + (float)NTOK * b * b;
        nqv[tid] = fmaxf(sqrtf(fmaxf(n2, 0.f)), EPS);
        uqv[tid] = uacc;
    } else if (tid < 128) {
        int d = tid - 64;
        float b = bks[d];
        float n2 = nacc + 2.f * b * uacc + (float)NTOK * b * b;
        nkv[d] = fmaxf(sqrtf(fmaxf(n2, 0.f)), EPS);
        ukv[d] = uacc;
    }
    __syncthreads();

    float tf = temp[h];
    float* Gs = wqs;
#pragma unroll
    for (int i = 0; i < 4; i++) {
        int d = tr * 4 + i;
#pragma unroll
        for (int j = 0; j < 4; j++) {
            int e = tc * 4 + j;
            float G = acc[i][j] + bqs[d] * ukv[e] + bks[e] * uqv[d]
                      + (float)NTOK * bqs[d] * bks[e];
            Gs[d * 64 + e] = G * tf / (nqv[d] * nkv[e]);
        }
    }
    __syncthreads();

    int warp = tid >> 5, lane = tid & 31;
    float* attn_base = g_attnT + ((long long)(bp * HEADS + h) << 12);
    for (int rr = 0; rr < 8; rr++) {
        int r = warp * 8 + rr;      // d index
        float x0 = Gs[r * 64 + lane];
        float x1 = Gs[r * 64 + 32 + lane];
        float m = fmaxf(x0, x1);
#pragma unroll
        for (int o = 16; o > 0; o >>= 1) m = fmaxf(m, __shfl_xor_sync(0xffffffffu, m, o));
        float e0 = expf(x0 - m), e1 = expf(x1 - m);
        float ssum = e0 + e1;
#pragma unroll
        for (int o = 16; o > 0; o >>= 1) ssum += __shfl_xor_sync(0xffffffffu, ssum, o);
        float inv = 1.f / ssum;
        attn_base[lane * 64 + r]        = e0 * inv;
        attn_base[(lane + 32) * 64 + r] = e1 * inv;
    }
}

// ===========================================================================
// W2[bp][f, h*64+e] = sum_d w_out[f, h*64+d]*attnT[bp,h,e,d] -> fp16 hi/lo
// ===========================================================================
__global__ __launch_bounds__(256) void make_w2_kernel(const float* __restrict__ w_out) {
    long long i = (long long)blockIdx.x * 256 + threadIdx.x;
    int c = (int)(i & 511);
    int f = (int)((i >> 9) & 511);
    int bp = (int)(i >> 18);
    int h = c >> 6, e = c & 63;
    const float* wrow = w_out + f * 512 + h * 64;
    const float* arow = g_attnT + ((long long)(bp * HEADS + h) << 12) + e * 64;
    float s = 0.f;
#pragma unroll 16
    for (int d = 0; d < 64; d++) s += wrow[d] * arow[d];
    h16 hi = __float2half(s);
    g_w2hi[i] = hi;
    g_w2lo[i] = __float2half(s - __half2float(hi));
}

// ===========================================================================
// b3: warp-per-row coalesced reduction
// ===========================================================================
__global__ __launch_bounds__(256) void b3_kernel(const float* __restrict__ b_qkv,
                                                 const float* __restrict__ b_out) {
    int row = blockIdx.x * 8 + (threadIdx.x >> 5);
    int lane = threadIdx.x & 31;
    const h16* hi = g_w2hi + (long long)row * 512;
    const h16* lo = g_w2lo + (long long)row * 512;
    const float* bv = b_qkv + 1024;
    float s = 0.f;
#pragma unroll
    for (int i = 0; i < 16; i++) {
        int c = lane + 32 * i;
        s += (__half2float(hi[c]) + __half2float(lo[c])) * bv[c];
    }
#pragma unroll
    for (int o = 16; o > 0; o >>= 1) s += __shfl_xor_sync(0xffffffffu, s, o);
    if (lane == 0) g_b3[row] = s + b_out[row & 511];
}

// ===========================================================================
// launch
// ===========================================================================
extern "C" void kernel_launch(void* const* d_in, const int* in_sizes, int n_in,
                              void* d_out, int out_size)
{
    const float* x     = (const float*)d_in[0];
    const float* wq    = (const float*)d_in[1];
    const float* b_qkv = (const float*)d_in[2];
    const float* temp  = (const float*)d_in[3];
    const float* w_out = (const float*)d_in[4];
    const float* b_out = (const float*)d_in[5];
    float* out = (float*)d_out;

    h16 *xhi_p, *xlo_p, *wqhi_p, *wqlo_p, *Sf_p, *w2hi_p, *w2lo_p;
    h16 *wvthi_p, *wvtlo_p, *w3hi_p, *w3lo_p;
    float *T_p, *b3_p, *zb_p;
    cudaGetSymbolAddress((void**)&xhi_p,  g_xhi);
    cudaGetSymbolAddress((void**)&xlo_p,  g_xlo);
    cudaGetSymbolAddress((void**)&wqhi_p, g_wqhi);
    cudaGetSymbolAddress((void**)&wqlo_p, g_wqlo);
    cudaGetSymbolAddress((void**)&Sf_p,   g_Sf16);
    cudaGetSymbolAddress((void**)&T_p,    g_T);
    cudaGetSymbolAddress((void**)&w2hi_p, g_w2hi);
    cudaGetSymbolAddress((void**)&w2lo_p, g_w2lo);
    cudaGetSymbolAddress((void**)&wvthi_p, g_wvthi);
    cudaGetSymbolAddress((void**)&wvtlo_p, g_wvtlo);
    cudaGetSymbolAddress((void**)&w3hi_p, g_w3hi);
    cudaGetSymbolAddress((void**)&w3lo_p, g_w3lo);
    cudaGetSymbolAddress((void**)&b3_p,   g_b3);
    cudaGetSymbolAddress((void**)&zb_p,   g_zerobias);

    const int GEMM_SMEM = 2 * STGB;      // 81920
    const int SYRK_SMEM = 2 * SSTGB;     // 69632
    const int ATTN_SMEM = 4 * 4352 * 4;  // 69632
    const int FIN_SMEM  = 128 * 129 * 4; // 66048
    cudaFuncSetAttribute(gemm_f16<true>,  cudaFuncAttributeMaxDynamicSharedMemorySize, GEMM_SMEM);
    cudaFuncSetAttribute(gemm_f16<false>, cudaFuncAttributeMaxDynamicSharedMemorySize, GEMM_SMEM);
    cudaFuncSetAttribute(syrk_partial, cudaFuncAttributeMaxDynamicSharedMemorySize, SYRK_SMEM);
    cudaFuncSetAttribute(attn_from_s,  cudaFuncAttributeMaxDynamicSharedMemorySize, ATTN_SMEM);
    cudaFuncSetAttribute(syrk_finish,  cudaFuncAttributeMaxDynamicSharedMemorySize, FIN_SMEM);

    // 1. splits + column sums (single read of x)
    zero_s_kernel<<<(BP * 512 + 255) / 256, 256>>>();
    {
        dim3 grid(BP, NTOK / 256);
        split_colsum<<<grid, 256>>>(x);
    }
    split_f16<<<(1024 * EDIM / 4 + 255) / 256, 256>>>(wq, wqhi_p, wqlo_p, 1024 * EDIM / 4);
    wvt_split_kernel<<<(512 * 512 + 255) / 256, 256>>>(wq);

    // 2. S = X^T X (fp16x3 partials, diag-aliased), reduce + mirror -> fp16
    {
        dim3 grid(10, 4, BP);
        syrk_partial<<<grid, 128, SYRK_SMEM>>>(xhi_p, xlo_p);
    }
    {
        dim3 grid(10, BP);
        syrk_finish<<<grid, 256, FIN_SMEM>>>();
    }

    // 3. T = Sf16·[Wq|Wk]^T  (A single, B hi/lo, 2 products)
    {
        dim3 grid(8, BP * 512 / 128);
        gemm_f16<false><<<grid, 128, GEMM_SMEM>>>(Sf_p, nullptr, wqhi_p, wqlo_p,
                                                  zb_p, 0, T_p, nullptr, nullptr, 1024, 0LL);
    }

    // 4. attention logits + softmax (transposed attn)
    {
        dim3 grid(BP, HEADS);
        attn_from_s<<<grid, 256, ATTN_SMEM>>>(wq, b_qkv, temp);
    }

    // 5. W2; W3 = W2·Wv (full 3-product, fp16 hi/lo out); b3
    make_w2_kernel<<<(BP * EDIM * QKV) / 256, 256>>>(w_out);
    {
        dim3 grid(4, BP * 512 / 128);
        gemm_f16<true><<<grid, 128, GEMM_SMEM>>>(w2hi_p, w2lo_p, wvthi_p, wvtlo_p,
                                                 zb_p, 0, nullptr, w3hi_p, w3lo_p, 512, 0LL);
    }
    b3_kernel<<<(BP * 512) / 8, 256>>>(b_qkv, b_out);

    // 6. out = Xhi_f16 · W3[bp]^T + b3[bp]  (A single, B hi/lo, 2 products)
    {
        dim3 grid(EDIM / 128, MTOT / 128);
        gemm_f16<false><<<grid, 128, GEMM_SMEM>>>(xhi_p, nullptr, w3hi_p, w3lo_p,
                                                  b3_p, 512, out, nullptr, nullptr, 512,
                                                  (long long)512 * 512);
    }
}

// round 11
// speedup vs baseline: 2.0978x; 1.9961x over previous
#include <cuda_runtime.h>
#include <cuda_bf16.h>
#include <cuda_fp16.h>
#include <cstdint>
#include <math.h>

// ---------------- problem constants ----------------
#define NTOK  4096
#define EDIM  512
#define QKV   512
#define HEADS 8
#define DH    64
#define BP    16
#define MTOT  65536
#define EPS   1e-12f

typedef __nv_bfloat16 bf16;
typedef __half h16;

// ---------------- scratch (device globals) ----------------
__device__ bf16   g_xhi[(size_t)MTOT * 512];
__device__ bf16   g_xlo[(size_t)MTOT * 512];
__device__ h16    g_xf16[(size_t)MTOT * 512];     // single fp16 copy of x (final GEMM A)
__device__ bf16   g_wqhi[1024 * EDIM];
__device__ bf16   g_wqlo[1024 * EDIM];
__device__ bf16   g_Shi[BP * 512 * 512];
__device__ bf16   g_Slo[BP * 512 * 512];
__device__ float  g_Sp[(size_t)4 * BP * 10 * 128 * 128];   // SYRK k-partials
__device__ float  g_T[(size_t)BP * 512 * 1024];            // [Tq | Tk] per bp
__device__ float  g_s[BP * 512];
__device__ float  g_attn[BP * HEADS * DH * DH];
__device__ bf16   g_w2hi[BP * EDIM * QKV];
__device__ bf16   g_w2lo[BP * EDIM * QKV];
__device__ bf16   g_wvthi[EDIM * QKV];
__device__ bf16   g_wvtlo[EDIM * QKV];
__device__ h16    g_w3hi[BP * EDIM * EDIM];       // fp16 hi/lo (final GEMM B)
__device__ h16    g_w3lo[BP * EDIM * EDIM];
__device__ float  g_b3[BP * EDIM];
__device__ float  g_zerobias[1024];               // stays zero

// ---------------- PTX helpers ----------------
__device__ __forceinline__ uint32_t smem_u32(const void* p) {
    uint32_t a;
    asm("{ .reg .u64 t; cvta.to.shared.u64 t, %1; cvt.u32.u64 %0, t; }" : "=r"(a) : "l"(p));
    return a;
}
__device__ __forceinline__ void cp16(uint32_t saddr, const void* gptr) {
    asm volatile("cp.async.cg.shared.global [%0], [%1], 16;" :: "r"(saddr), "l"(gptr));
}
__device__ __forceinline__ void ldsm4(uint32_t& r0, uint32_t& r1, uint32_t& r2, uint32_t& r3,
                                      uint32_t addr) {
    asm volatile("ldmatrix.sync.aligned.m8n8.x4.shared.b16 {%0,%1,%2,%3}, [%4];"
                 : "=r"(r0), "=r"(r1), "=r"(r2), "=r"(r3) : "r"(addr));
}
__device__ __forceinline__ void ldsm4t(uint32_t& r0, uint32_t& r1, uint32_t& r2, uint32_t& r3,
                                       uint32_t addr) {
    asm volatile("ldmatrix.sync.aligned.m8n8.x4.trans.shared.b16 {%0,%1,%2,%3}, [%4];"
                 : "=r"(r0), "=r"(r1), "=r"(r2), "=r"(r3) : "r"(addr));
}
__device__ __forceinline__ void mma16816(float* d, const uint32_t* a, uint32_t b0, uint32_t b1) {
    asm volatile(
        "mma.sync.aligned.m16n8k16.row.col.f32.bf16.bf16.f32 "
        "{%0,%1,%2,%3}, {%4,%5,%6,%7}, {%8,%9}, {%0,%1,%2,%3};"
        : "+f"(d[0]), "+f"(d[1]), "+f"(d[2]), "+f"(d[3])
        : "r"(a[0]), "r"(a[1]), "r"(a[2]), "r"(a[3]), "r"(b0), "r"(b1));
}
__device__ __forceinline__ void mma16816h(float* d, const uint32_t* a, uint32_t b0, uint32_t b1) {
    asm volatile(
        "mma.sync.aligned.m16n8k16.row.col.f32.f16.f16.f32 "
        "{%0,%1,%2,%3}, {%4,%5,%6,%7}, {%8,%9}, {%0,%1,%2,%3};"
        : "+f"(d[0]), "+f"(d[1]), "+f"(d[2]), "+f"(d[3])
        : "r"(a[0]), "r"(a[1]), "r"(a[2]), "r"(a[3]), "r"(b0), "r"(b1));
}
__device__ __forceinline__ __nv_bfloat162 hi2(float a, float b) {
    __nv_bfloat162 r; r.x = __float2bfloat16(a); r.y = __float2bfloat16(b); return r;
}
__device__ __forceinline__ __nv_bfloat162 lo2(float a, float b) {
    __nv_bfloat162 r;
    r.x = __float2bfloat16(a - __bfloat162float(__float2bfloat16(a)));
    r.y = __float2bfloat16(b - __bfloat162float(__float2bfloat16(b)));
    return r;
}
__device__ __forceinline__ __half2 h2hi(float a, float b) {
    return __floats2half2_rn(a, b);
}
__device__ __forceinline__ __half2 h2lo(float a, float b) {
    __half2 r;
    r.x = __float2half_rn(a - __half2float(__float2half_rn(a)));
    r.y = __float2half_rn(b - __half2float(__float2half_rn(b)));
    return r;
}

// ===========================================================================
// bf16x3 GEMM (ROUND-8 PROVEN): C = (Ahi+Alo)·(Bhi+Blo)^T + bias; K=512.
// 128x128 CTA tile, BK=32, 4 warps (2x2), warp tile 64x64, 2-stage cp.async.
// fp32 out (Cfp) or fp16 hi/lo out (Chi/Clo — used for W3 only).
// ===========================================================================
#define ROWB   80
#define MATB   (128 * ROWB)
#define STGB   (4 * MATB)               // 40960
#define OFF_AH 0
#define OFF_AL MATB
#define OFF_BH (2 * MATB)
#define OFF_BL (3 * MATB)
#define NKCH   16

__global__ __launch_bounds__(128, 2)
void gemm_bf16x3(const bf16* __restrict__ Ahi, const bf16* __restrict__ Alo,
                 const bf16* __restrict__ Bhi, const bf16* __restrict__ Blo,
                 const float* __restrict__ bias, int biasStride,
                 float* __restrict__ Cfp, h16* __restrict__ Chi, h16* __restrict__ Clo,
                 int ldc, long long bStride)
{
    extern __shared__ char smem[];
    uint32_t sb = smem_u32(smem);
    int tid = threadIdx.x, wid = tid >> 5, lane = tid & 31;
    int n0 = blockIdx.x * 128, m0 = blockIdx.y * 128;
    int batch = m0 >> 12;

    const bf16* bh = Bhi + (long long)batch * bStride;
    const bf16* bl = Blo + (long long)batch * bStride;

    float acc[4][8][4];
#pragma unroll
    for (int i = 0; i < 4; i++)
#pragma unroll
        for (int j = 0; j < 8; j++)
#pragma unroll
            for (int r = 0; r < 4; r++) acc[i][j][r] = 0.f;

    auto load_stage = [&](int chunk, int stage) {
        uint32_t st = sb + stage * STGB;
        int k0 = chunk * 32;
#pragma unroll
        for (int i = 0; i < 4; i++) {
            int idx = i * 128 + tid;          // 0..511
            int row = idx >> 2, c = idx & 3;
            uint32_t so = (uint32_t)(row * ROWB + c * 16);
            long long ga = (long long)(m0 + row) * 512 + k0 + c * 8;
            long long gb = (long long)(n0 + row) * 512 + k0 + c * 8;
            cp16(st + OFF_AH + so, Ahi + ga);
            cp16(st + OFF_AL + so, Alo + ga);
            cp16(st + OFF_BH + so, bh + gb);
            cp16(st + OFF_BL + so, bl + gb);
        }
        asm volatile("cp.async.commit_group;" ::: "memory");
    };

    load_stage(0, 0);

    int wm = wid >> 1, wn = wid & 1;                 // warp grid 2x2
    uint32_t aRowOff = (uint32_t)((wm * 64 + (lane & 15)) * ROWB + (lane >> 4) * 16);
    uint32_t bRowOff = (uint32_t)((wn * 64 + (lane & 15)) * ROWB + (lane >> 4) * 16);

    for (int c = 0; c < NKCH; c++) {
        if (c + 1 < NKCH) {
            load_stage(c + 1, (c + 1) & 1);
            asm volatile("cp.async.wait_group 1;" ::: "memory");
        } else {
            asm volatile("cp.async.wait_group 0;" ::: "memory");
        }
        __syncthreads();

        uint32_t st = sb + (c & 1) * STGB;
#pragma unroll
        for (int kk = 0; kk < 2; kk++) {
            uint32_t kOff = kk * 32;
            uint32_t aB = st + aRowOff + kOff;
            uint32_t bB = st + bRowOff + kOff;

            uint32_t aH[4][4], aL[4][4];
#pragma unroll
            for (int im = 0; im < 4; im++) {
                ldsm4(aH[im][0], aH[im][1], aH[im][2], aH[im][3], aB + OFF_AH + im * 16 * ROWB);
                ldsm4(aL[im][0], aL[im][1], aL[im][2], aL[im][3], aB + OFF_AL + im * 16 * ROWB);
            }
            uint32_t bH[4][4], bL[4][4];
#pragma unroll
            for (int ib = 0; ib < 4; ib++) {
                ldsm4(bH[ib][0], bH[ib][1], bH[ib][2], bH[ib][3], bB + OFF_BH + ib * 16 * ROWB);
                ldsm4(bL[ib][0], bL[ib][1], bL[ib][2], bL[ib][3], bB + OFF_BL + ib * 16 * ROWB);
            }
#pragma unroll
            for (int im = 0; im < 4; im++) {
#pragma unroll
                for (int jn = 0; jn < 8; jn++) {
                    int ib = jn >> 1, js = jn & 1;
                    mma16816(acc[im][jn], aH[im], bH[ib][js], bH[ib][2 + js]);
                    mma16816(acc[im][jn], aH[im], bL[ib][js], bL[ib][2 + js]);
                    mma16816(acc[im][jn], aL[im], bH[ib][js], bH[ib][2 + js]);
                }
            }
        }
        __syncthreads();
    }

    const float* bb = bias + (long long)batch * biasStride;
    float bcol0[8], bcol1[8];
#pragma unroll
    for (int jn = 0; jn < 8; jn++) {
        int cc = n0 + wn * 64 + jn * 8 + 2 * (lane & 3);
        bcol0[jn] = bb[cc];
        bcol1[jn] = bb[cc + 1];
    }
#pragma unroll
    for (int im = 0; im < 4; im++) {
        int r0 = m0 + wm * 64 + im * 16 + (lane >> 2);
#pragma unroll
        for (int jn = 0; jn < 8; jn++) {
            int cc = n0 + wn * 64 + jn * 8 + 2 * (lane & 3);
            float v00 = acc[im][jn][0] + bcol0[jn];
            float v01 = acc[im][jn][1] + bcol1[jn];
            float v10 = acc[im][jn][2] + bcol0[jn];
            float v11 = acc[im][jn][3] + bcol1[jn];
            if (Chi) {
                *(__half2*)(Chi + (long long)r0 * ldc + cc)       = h2hi(v00, v01);
                *(__half2*)(Clo + (long long)r0 * ldc + cc)       = h2lo(v00, v01);
                *(__half2*)(Chi + (long long)(r0 + 8) * ldc + cc) = h2hi(v10, v11);
                *(__half2*)(Clo + (long long)(r0 + 8) * ldc + cc) = h2lo(v10, v11);
            } else {
                *(float2*)(Cfp + (long long)r0 * ldc + cc)       = make_float2(v00, v01);
                *(float2*)(Cfp + (long long)(r0 + 8) * ldc + cc) = make_float2(v10, v11);
            }
        }
    }
}

// ===========================================================================
// fp16 2-product GEMM (final projection only):
// C = A·(Bhi+Blo)^T + bias; A single fp16, K=512. 3 matrices per stage.
// Same proven structure: 128x128 tile, BK=32, 4 warps, 2-stage cp.async.
// ===========================================================================
#define STGB2  (3 * MATB)               // 30720
#define F_A    0
#define F_BH   MATB
#define F_BL   (2 * MATB)

__global__ __launch_bounds__(128, 2)
void gemm_f16x2(const h16* __restrict__ A,
                const h16* __restrict__ Bhi, const h16* __restrict__ Blo,
                const float* __restrict__ bias,
                float* __restrict__ Cfp, int ldc, long long bStride)
{
    extern __shared__ char smem[];
    uint32_t sb = smem_u32(smem);
    int tid = threadIdx.x, wid = tid >> 5, lane = tid & 31;
    int n0 = blockIdx.x * 128, m0 = blockIdx.y * 128;
    int batch = m0 >> 12;

    const h16* bh = Bhi + (long long)batch * bStride;
    const h16* bl = Blo + (long long)batch * bStride;

    float acc[4][8][4];
#pragma unroll
    for (int i = 0; i < 4; i++)
#pragma unroll
        for (int j = 0; j < 8; j++)
#pragma unroll
            for (int r = 0; r < 4; r++) acc[i][j][r] = 0.f;

    auto load_stage = [&](int chunk, int stage) {
        uint32_t st = sb + stage * STGB2;
        int k0 = chunk * 32;
#pragma unroll
        for (int i = 0; i < 4; i++) {
            int idx = i * 128 + tid;          // 0..511
            int row = idx >> 2, c = idx & 3;
            uint32_t so = (uint32_t)(row * ROWB + c * 16);
            long long ga = (long long)(m0 + row) * 512 + k0 + c * 8;
            long long gb = (long long)(n0 + row) * 512 + k0 + c * 8;
            cp16(st + F_A + so, A + ga);
            cp16(st + F_BH + so, bh + gb);
            cp16(st + F_BL + so, bl + gb);
        }
        asm volatile("cp.async.commit_group;" ::: "memory");
    };

    load_stage(0, 0);

    int wm = wid >> 1, wn = wid & 1;
    uint32_t aRowOff = (uint32_t)((wm * 64 + (lane & 15)) * ROWB + (lane >> 4) * 16);
    uint32_t bRowOff = (uint32_t)((wn * 64 + (lane & 15)) * ROWB + (lane >> 4) * 16);

    for (int c = 0; c < NKCH; c++) {
        if (c + 1 < NKCH) {
            load_stage(c + 1, (c + 1) & 1);
            asm volatile("cp.async.wait_group 1;" ::: "memory");
        } else {
            asm volatile("cp.async.wait_group 0;" ::: "memory");
        }
        __syncthreads();

        uint32_t st = sb + (c & 1) * STGB2;
#pragma unroll
        for (int kk = 0; kk < 2; kk++) {
            uint32_t kOff = kk * 32;
            uint32_t aB = st + aRowOff + kOff;
            uint32_t bB = st + bRowOff + kOff;

            uint32_t aF[4][4];
#pragma unroll
            for (int im = 0; im < 4; im++)
                ldsm4(aF[im][0], aF[im][1], aF[im][2], aF[im][3], aB + F_A + im * 16 * ROWB);
            uint32_t bH[4][4], bL[4][4];
#pragma unroll
            for (int ib = 0; ib < 4; ib++) {
                ldsm4(bH[ib][0], bH[ib][1], bH[ib][2], bH[ib][3], bB + F_BH + ib * 16 * ROWB);
                ldsm4(bL[ib][0], bL[ib][1], bL[ib][2], bL[ib][3], bB + F_BL + ib * 16 * ROWB);
            }
#pragma unroll
            for (int im = 0; im < 4; im++) {
#pragma unroll
                for (int jn = 0; jn < 8; jn++) {
                    int ib = jn >> 1, js = jn & 1;
                    mma16816h(acc[im][jn], aF[im], bH[ib][js], bH[ib][2 + js]);
                    mma16816h(acc[im][jn], aF[im], bL[ib][js], bL[ib][2 + js]);
                }
            }
        }
        __syncthreads();
    }

    const float* bb = bias + (long long)batch * 512;
    float bcol0[8], bcol1[8];
#pragma unroll
    for (int jn = 0; jn < 8; jn++) {
        int cc = n0 + wn * 64 + jn * 8 + 2 * (lane & 3);
        bcol0[jn] = bb[cc];
        bcol1[jn] = bb[cc + 1];
    }
#pragma unroll
    for (int im = 0; im < 4; im++) {
        int r0 = m0 + wm * 64 + im * 16 + (lane >> 2);
#pragma unroll
        for (int jn = 0; jn < 8; jn++) {
            int cc = n0 + wn * 64 + jn * 8 + 2 * (lane & 3);
            *(float2*)(Cfp + (long long)r0 * ldc + cc) =
                make_float2(acc[im][jn][0] + bcol0[jn], acc[im][jn][1] + bcol1[jn]);
            *(float2*)(Cfp + (long long)(r0 + 8) * ldc + cc) =
                make_float2(acc[im][jn][2] + bcol0[jn], acc[im][jn][3] + bcol1[jn]);
        }
    }
}

// ===========================================================================
// SYRK bf16x3 partials (ROUND-8 PROVEN): grid (10, 4, 16); K=1024 each.
// ===========================================================================
#define SROWB  272
#define SMATB  (32 * SROWB)             // 8704
#define SSTGB  (4 * SMATB)              // 34816
#define S_AH   0
#define S_AL   SMATB
#define S_BH   (2 * SMATB)
#define S_BL   (3 * SMATB)

__constant__ int c_EB[10] = {0,0,0,0,1,1,1,2,2,3};
__constant__ int c_FB[10] = {0,1,2,3,1,2,3,2,3,3};

__global__ __launch_bounds__(128, 2)
void syrk_partial(const bf16* __restrict__ Xhi, const bf16* __restrict__ Xlo)
{
    extern __shared__ char smem[];
    uint32_t sb = smem_u32(smem);
    int tid = threadIdx.x, wid = tid >> 5, lane = tid & 31;
    int p = blockIdx.x, kc = blockIdx.y, bp = blockIdx.z;
    int e0 = c_EB[p] * 128, f0 = c_FB[p] * 128;
    long long xbase = (long long)bp * NTOK * 512;

    float acc[4][8][4];
#pragma unroll
    for (int i = 0; i < 4; i++)
#pragma unroll
        for (int j = 0; j < 8; j++)
#pragma unroll
            for (int r = 0; r < 4; r++) acc[i][j][r] = 0.f;

    auto load_stage = [&](int chunk, int stage) {
        uint32_t st = sb + stage * SSTGB;
        int t0 = kc * 1024 + chunk * 32;
#pragma unroll
        for (int i = 0; i < 4; i++) {
            int idx = i * 128 + tid;
            int row = idx >> 4, c = idx & 15;
            uint32_t so = (uint32_t)(row * SROWB + c * 16);
            long long ge = xbase + (long long)(t0 + row) * 512 + e0 + c * 8;
            long long gf = xbase + (long long)(t0 + row) * 512 + f0 + c * 8;
            cp16(st + S_AH + so, Xhi + ge);
            cp16(st + S_AL + so, Xlo + ge);
            cp16(st + S_BH + so, Xhi + gf);
            cp16(st + S_BL + so, Xlo + gf);
        }
        asm volatile("cp.async.commit_group;" ::: "memory");
    };

    load_stage(0, 0);

    int wm = wid >> 1, wn = wid & 1;
    int sub = lane >> 3;
    int nloc = (lane & 7) + ((sub >> 1) << 3);
    uint32_t cpad = (uint32_t)((sub & 1) * 16);
    uint32_t aColB = (uint32_t)((wm * 64) * 2) + cpad;
    uint32_t bColB = (uint32_t)((wn * 64) * 2) + cpad;

    const int NCH = 32;
    for (int c = 0; c < NCH; c++) {
        if (c + 1 < NCH) {
            load_stage(c + 1, (c + 1) & 1);
            asm volatile("cp.async.wait_group 1;" ::: "memory");
        } else {
            asm volatile("cp.async.wait_group 0;" ::: "memory");
        }
        __syncthreads();

        uint32_t st = sb + (c & 1) * SSTGB;
#pragma unroll
        for (int kk = 0; kk < 2; kk++) {
            uint32_t rowB = (uint32_t)((kk * 16 + nloc) * SROWB);
            uint32_t aB = st + rowB + aColB;
            uint32_t bB = st + rowB + bColB;

            uint32_t aH[4][4], aL[4][4];
#pragma unroll
            for (int im = 0; im < 4; im++) {
                ldsm4t(aH[im][0], aH[im][1], aH[im][2], aH[im][3], aB + S_AH + im * 32);
                ldsm4t(aL[im][0], aL[im][1], aL[im][2], aL[im][3], aB + S_AL + im * 32);
            }
            uint32_t bH[4][4], bL[4][4];
#pragma unroll
            for (int ib = 0; ib < 4; ib++) {
                ldsm4t(bH[ib][0], bH[ib][1], bH[ib][2], bH[ib][3], bB + S_BH + ib * 32);
                ldsm4t(bL[ib][0], bL[ib][1], bL[ib][2], bL[ib][3], bB + S_BL + ib * 32);
            }
#pragma unroll
            for (int im = 0; im < 4; im++) {
#pragma unroll
                for (int jn = 0; jn < 8; jn++) {
                    int ib = jn >> 1, js = jn & 1;
                    mma16816(acc[im][jn], aH[im], bH[ib][js], bH[ib][2 + js]);
                    mma16816(acc[im][jn], aH[im], bL[ib][js], bL[ib][2 + js]);
                    mma16816(acc[im][jn], aL[im], bH[ib][js], bH[ib][2 + js]);
                }
            }
        }
        __syncthreads();
    }

    float* dst = g_Sp + (((long long)kc * BP + bp) * 10 + p) * 16384;
#pragma unroll
    for (int im = 0; im < 4; im++) {
        int el = wm * 64 + im * 16 + (lane >> 2);
#pragma unroll
        for (int jn = 0; jn < 8; jn++) {
            int fl = wn * 64 + jn * 8 + 2 * (lane & 3);
            *(float2*)(dst + el * 128 + fl)       = make_float2(acc[im][jn][0], acc[im][jn][1]);
            *(float2*)(dst + (el + 8) * 128 + fl) = make_float2(acc[im][jn][2], acc[im][jn][3]);
        }
    }
}

// ===========================================================================
// SYRK finish: sum 4 partials, write bf16 hi/lo (both orientations via smem).
// ===========================================================================
__global__ __launch_bounds__(256)
void syrk_finish()
{
    extern __shared__ float tile[];    // 128 x 129
    int p = blockIdx.x, bp = blockIdx.y;
    int e0 = c_EB[p] * 128, f0 = c_FB[p] * 128;
    int tid = threadIdx.x;

    const float* p0 = g_Sp + (((long long)0 * BP + bp) * 10 + p) * 16384;
    const float* p1 = g_Sp + (((long long)1 * BP + bp) * 10 + p) * 16384;
    const float* p2 = g_Sp + (((long long)2 * BP + bp) * 10 + p) * 16384;
    const float* p3 = g_Sp + (((long long)3 * BP + bp) * 10 + p) * 16384;
    for (int idx = tid; idx < 16384; idx += 256) {
        float s = (p0[idx] + p1[idx]) + (p2[idx] + p3[idx]);
        tile[(idx >> 7) * 129 + (idx & 127)] = s;
    }
    __syncthreads();

    bf16* ShiB = g_Shi + (long long)bp * 512 * 512;
    bf16* SloB = g_Slo + (long long)bp * 512 * 512;
    for (int idx = tid; idx < 16384; idx += 256) {
        int r = idx >> 7, c = idx & 127;
        float v = tile[r * 129 + c];
        bf16 h = __float2bfloat16(v);
        ShiB[(long long)(e0 + r) * 512 + f0 + c] = h;
        SloB[(long long)(e0 + r) * 512 + f0 + c] = __float2bfloat16(v - __bfloat162float(h));
    }
    if (e0 != f0) {
        for (int idx = tid; idx < 16384; idx += 256) {
            int r = idx >> 7, c = idx & 127;
            float v = tile[c * 129 + r];
            bf16 h = __float2bfloat16(v);
            ShiB[(long long)(f0 + r) * 512 + e0 + c] = h;
            SloB[(long long)(f0 + r) * 512 + e0 + c] = __float2bfloat16(v - __bfloat162float(h));
        }
    }
}

// ===========================================================================
// fused x split (bf16 hi/lo + single fp16) + column sums
// ===========================================================================
__global__ __launch_bounds__(256) void split_colsum(const float* __restrict__ x) {
    int bp = blockIdx.x, ch = blockIdx.y, t = threadIdx.x;
    long long base = ((long long)bp * NTOK + ch * 256) * 512 + t * 2;
    float s0 = 0.f, s1 = 0.f;
    for (int n = 0; n < 256; n++) {
        long long idx = base + (long long)n * 512;
        float2 v = *(const float2*)(x + idx);
        s0 += v.x; s1 += v.y;
        ((__nv_bfloat162*)g_xhi)[idx >> 1] = hi2(v.x, v.y);
        ((__nv_bfloat162*)g_xlo)[idx >> 1] = lo2(v.x, v.y);
        ((__half2*)g_xf16)[idx >> 1]       = h2hi(v.x, v.y);
    }
    atomicAdd(&g_s[bp * 512 + t * 2], s0);
    atomicAdd(&g_s[bp * 512 + t * 2 + 1], s1);
}
__global__ void zero_s_kernel() {
    int i = blockIdx.x * blockDim.x + threadIdx.x;
    if (i < BP * 512) g_s[i] = 0.f;
}

// ===========================================================================
// weight splits
// ===========================================================================
__global__ __launch_bounds__(256) void split_bf16(const float* __restrict__ src,
                                                  bf16* __restrict__ hi,
                                                  bf16* __restrict__ lo, long long n4)
{
    long long i = (long long)blockIdx.x * 256 + threadIdx.x;
    if (i >= n4) return;
    float4 v = ((const float4*)src)[i];
    ((__nv_bfloat162*)hi)[i * 2]     = hi2(v.x, v.y);
    ((__nv_bfloat162*)hi)[i * 2 + 1] = hi2(v.z, v.w);
    ((__nv_bfloat162*)lo)[i * 2]     = lo2(v.x, v.y);
    ((__nv_bfloat162*)lo)[i * 2 + 1] = lo2(v.z, v.w);
}
__global__ __launch_bounds__(256) void wvt_split_kernel(const float* __restrict__ wqkv) {
    int i = blockIdx.x * 256 + threadIdx.x;
    if (i >= 512 * 512) return;
    int e = i >> 9, c = i & 511;
    float v = wqkv[(long long)(1024 + c) * 512 + e];
    bf16 hi = __float2bfloat16(v);
    g_wvthi[i] = hi;
    g_wvtlo[i] = __float2bfloat16(v - __bfloat162float(hi));
}

// ===========================================================================
// attention finish per (bp,h)  (ROUND-8 PROVEN, non-transposed attn)
// ===========================================================================
__global__ __launch_bounds__(256) void attn_from_s(const float* __restrict__ wqkv,
                                                   const float* __restrict__ b_qkv,
                                                   const float* __restrict__ temp)
{
    int bp = blockIdx.x, h = blockIdx.y;
    int tid = threadIdx.x, tr = tid >> 4, tc = tid & 15;

    extern __shared__ float dyn[];
    float* wqs = dyn;                  // 64 x 68
    float* wks = dyn + 4352;
    float* tqs = dyn + 2 * 4352;
    float* tks = dyn + 3 * 4352;
    __shared__ float schunk[64];
    __shared__ float uqv[64], ukv[64], nqv[64], nkv[64], bqs[64], bks[64];

    if (tid < 64)       bqs[tid] = b_qkv[h * 64 + tid];
    else if (tid < 128) bks[tid - 64] = b_qkv[512 + h * 64 + (tid - 64)];

    float acc[4][4];
#pragma unroll
    for (int i = 0; i < 4; i++)
#pragma unroll
        for (int j = 0; j < 4; j++) acc[i][j] = 0.f;
    float uacc = 0.f, nacc = 0.f;

    const float* wq_h = wqkv + (long long)(h * 64) * 512;
    const float* wk_h = wqkv + (long long)(512 + h * 64) * 512;
    const float* T_b  = g_T + (long long)bp * 512 * 1024;
    const float* svec = g_s + bp * 512;

    for (int xc = 0; xc < 8; xc++) {
        __syncthreads();
#pragma unroll
        for (int i = 0; i < 4; i++) {
            int idx4 = i * 256 + tid;
            int row = idx4 >> 4, c4 = (idx4 & 15) * 4;
            *(float4*)&wqs[row * 68 + c4] = *(const float4*)(wq_h + (long long)row * 512 + xc * 64 + c4);
            *(float4*)&wks[row * 68 + c4] = *(const float4*)(wk_h + (long long)row * 512 + xc * 64 + c4);
            const float* trow = T_b + (long long)(xc * 64 + row) * 1024 + h * 64;
            *(float4*)&tqs[row * 68 + c4] = *(const float4*)(trow + c4);
            *(float4*)&tks[row * 68 + c4] = *(const float4*)(trow + 512 + c4);
        }
        if (tid < 64) schunk[tid] = svec[xc * 64 + tid];
        __syncthreads();
#pragma unroll 8
        for (int x = 0; x < 64; x++) {
            float rm[4], rn[4];
#pragma unroll
            for (int i = 0; i < 4; i++) rm[i] = wqs[(tr * 4 + i) * 68 + x];
            float4 r4 = *(const float4*)&tks[x * 68 + tc * 4];
            rn[0] = r4.x; rn[1] = r4.y; rn[2] = r4.z; rn[3] = r4.w;
#pragma unroll
            for (int i = 0; i < 4; i++)
#pragma unroll
                for (int j = 0; j < 4; j++) acc[i][j] += rm[i] * rn[j];
        }
        if (tid < 64) {
            int d = tid;
            for (int x = 0; x < 64; x++) {
                float w = wqs[d * 68 + x];
                uacc += w * schunk[x];
                nacc += w * tqs[x * 68 + d];
            }
        } else if (tid < 128) {
            int d = tid - 64;
            for (int x = 0; x < 64; x++) {
                float w = wks[d * 68 + x];
                uacc += w * schunk[x];
                nacc += w * tks[x * 68 + d];
            }
        }
    }

    if (tid < 64) {
        float b = bqs[tid];
        float n2 = nacc + 2.f * b * uacc + (float)NTOK * b * b;
        nqv[tid] = fmaxf(sqrtf(fmaxf(n2, 0.f)), EPS);
        uqv[tid] = uacc;
    } else if (tid < 128) {
        int d = tid - 64;
        float b = bks[d];
        float n2 = nacc + 2.f * b * uacc + (float)NTOK * b * b;
        nkv[d] = fmaxf(sqrtf(fmaxf(n2, 0.f)), EPS);
        ukv[d] = uacc;
    }
    __syncthreads();

    float tf = temp[h];
    float* Gs = wqs;
#pragma unroll
    for (int i = 0; i < 4; i++) {
        int d = tr * 4 + i;
#pragma unroll
        for (int j = 0; j < 4; j++) {
            int e = tc * 4 + j;
            float G = acc[i][j] + bqs[d] * ukv[e] + bks[e] * uqv[d]
                      + (float)NTOK * bqs[d] * bks[e];
            Gs[d * 64 + e] = G * tf / (nqv[d] * nkv[e]);
        }
    }
    __syncthreads();

    int warp = tid >> 5, lane = tid & 31;
    float* attn_base = g_attn + ((long long)(bp * HEADS + h) << 12);
    for (int rr = 0; rr < 8; rr++) {
        int r = warp * 8 + rr;
        float x0 = Gs[r * 64 + lane];
        float x1 = Gs[r * 64 + 32 + lane];
        float m = fmaxf(x0, x1);
#pragma unroll
        for (int o = 16; o > 0; o >>= 1) m = fmaxf(m, __shfl_xor_sync(0xffffffffu, m, o));
        float e0 = expf(x0 - m), e1 = expf(x1 - m);
        float ssum = e0 + e1;
#pragma unroll
        for (int o = 16; o > 0; o >>= 1) ssum += __shfl_xor_sync(0xffffffffu, ssum, o);
        float inv = 1.f / ssum;
        attn_base[r * 64 + lane]      = e0 * inv;
        attn_base[r * 64 + 32 + lane] = e1 * inv;
    }
}

// ===========================================================================
// W2[bp][f, h*64+e] = sum_d w_out[f, h*64+d]*attn[bp,h,d,e] -> bf16 hi/lo
// ===========================================================================
__global__ __launch_bounds__(256) void make_w2_kernel(const float* __restrict__ w_out) {
    long long i = (long long)blockIdx.x * 256 + threadIdx.x;
    int c = (int)(i & 511);
    int f = (int)((i >> 9) & 511);
    int bp = (int)(i >> 18);
    int h = c >> 6, e = c & 63;
    const float* wrow = w_out + f * 512 + h * 64;
    const float* acol = g_attn + ((long long)(bp * HEADS + h) << 12) + e;
    float s = 0.f;
#pragma unroll 16
    for (int d = 0; d < 64; d++) s += wrow[d] * acol[d * 64];
    bf16 hi = __float2bfloat16(s);
    g_w2hi[i] = hi;
    g_w2lo[i] = __float2bfloat16(s - __bfloat162float(hi));
}

// ===========================================================================
// b3: warp-per-row coalesced reduction
// ===========================================================================
__global__ __launch_bounds__(256) void b3_kernel(const float* __restrict__ b_qkv,
                                                 const float* __restrict__ b_out) {
    int row = blockIdx.x * 8 + (threadIdx.x >> 5);
    int lane = threadIdx.x & 31;
    const bf16* hi = g_w2hi + (long long)row * 512;
    const bf16* lo = g_w2lo + (long long)row * 512;
    const float* bv = b_qkv + 1024;
    float s = 0.f;
#pragma unroll
    for (int i = 0; i < 16; i++) {
        int c = lane + 32 * i;
        s += (__bfloat162float(hi[c]) + __bfloat162float(lo[c])) * bv[c];
    }
#pragma unroll
    for (int o = 16; o > 0; o >>= 1) s += __shfl_xor_sync(0xffffffffu, s, o);
    if (lane == 0) g_b3[row] = s + b_out[row & 511];
}

// ===========================================================================
// launch
// ===========================================================================
extern "C" void kernel_launch(void* const* d_in, const int* in_sizes, int n_in,
                              void* d_out, int out_size)
{
    const float* x     = (const float*)d_in[0];
    const float* wq    = (const float*)d_in[1];
    const float* b_qkv = (const float*)d_in[2];
    const float* temp  = (const float*)d_in[3];
    const float* w_out = (const float*)d_in[4];
    const float* b_out = (const float*)d_in[5];
    float* out = (float*)d_out;

    bf16 *xhi_p, *xlo_p, *wqhi_p, *wqlo_p, *Shi_p, *Slo_p, *w2hi_p, *w2lo_p;
    bf16 *wvthi_p, *wvtlo_p;
    h16 *xf_p, *w3hi_p, *w3lo_p;
    float *T_p, *b3_p, *zb_p;
    cudaGetSymbolAddress((void**)&xhi_p,  g_xhi);
    cudaGetSymbolAddress((void**)&xlo_p,  g_xlo);
    cudaGetSymbolAddress((void**)&xf_p,   g_xf16);
    cudaGetSymbolAddress((void**)&wqhi_p, g_wqhi);
    cudaGetSymbolAddress((void**)&wqlo_p, g_wqlo);
    cudaGetSymbolAddress((void**)&Shi_p,  g_Shi);
    cudaGetSymbolAddress((void**)&Slo_p,  g_Slo);
    cudaGetSymbolAddress((void**)&T_p,    g_T);
    cudaGetSymbolAddress((void**)&w2hi_p, g_w2hi);
    cudaGetSymbolAddress((void**)&w2lo_p, g_w2lo);
    cudaGetSymbolAddress((void**)&wvthi_p, g_wvthi);
    cudaGetSymbolAddress((void**)&wvtlo_p, g_wvtlo);
    cudaGetSymbolAddress((void**)&w3hi_p, g_w3hi);
    cudaGetSymbolAddress((void**)&w3lo_p, g_w3lo);
    cudaGetSymbolAddress((void**)&b3_p,   g_b3);
    cudaGetSymbolAddress((void**)&zb_p,   g_zerobias);

    const int GEMM_SMEM = 2 * STGB;      // 81920
    const int GEM2_SMEM = 2 * STGB2;     // 61440
    const int SYRK_SMEM = 2 * SSTGB;     // 69632
    const int ATTN_SMEM = 4 * 4352 * 4;  // 69632
    const int FIN_SMEM  = 128 * 129 * 4; // 66048
    cudaFuncSetAttribute(gemm_bf16x3,  cudaFuncAttributeMaxDynamicSharedMemorySize, GEMM_SMEM);
    cudaFuncSetAttribute(gemm_f16x2,   cudaFuncAttributeMaxDynamicSharedMemorySize, GEM2_SMEM);
    cudaFuncSetAttribute(syrk_partial, cudaFuncAttributeMaxDynamicSharedMemorySize, SYRK_SMEM);
    cudaFuncSetAttribute(attn_from_s,  cudaFuncAttributeMaxDynamicSharedMemorySize, ATTN_SMEM);
    cudaFuncSetAttribute(syrk_finish,  cudaFuncAttributeMaxDynamicSharedMemorySize, FIN_SMEM);

    // 1. splits + column sums (single read of x)
    zero_s_kernel<<<(BP * 512 + 255) / 256, 256>>>();
    {
        dim3 grid(BP, NTOK / 256);
        split_colsum<<<grid, 256>>>(x);
    }
    split_bf16<<<(1024 * EDIM / 4 + 255) / 256, 256>>>(wq, wqhi_p, wqlo_p, 1024 * EDIM / 4);
    wvt_split_kernel<<<(512 * 512 + 255) / 256, 256>>>(wq);

    // 2. S = X^T X: balanced k-split partials, then reduce+mirror+split
    {
        dim3 grid(10, 4, BP);
        syrk_partial<<<grid, 128, SYRK_SMEM>>>(xhi_p, xlo_p);
    }
    {
        dim3 grid(10, BP);
        syrk_finish<<<grid, 256, FIN_SMEM>>>();
    }

    // 3. T = S·[Wq|Wk]^T
    {
        dim3 grid(8, BP * 512 / 128);
        gemm_bf16x3<<<grid, 128, GEMM_SMEM>>>(Shi_p, Slo_p, wqhi_p, wqlo_p,
                                              zb_p, 0, T_p, nullptr, nullptr, 1024, 0LL);
    }

    // 4. attention logits + softmax
    {
        dim3 grid(BP, HEADS);
        attn_from_s<<<grid, 256, ATTN_SMEM>>>(wq, b_qkv, temp);
    }

    // 5. W2; W3 = W2·Wv (fp16 hi/lo out); b3
    make_w2_kernel<<<(BP * EDIM * QKV) / 256, 256>>>(w_out);
    {
        dim3 grid(4, BP * 512 / 128);
        gemm_bf16x3<<<grid, 128, GEMM_SMEM>>>(w2hi_p, w2lo_p, wvthi_p, wvtlo_p,
                                              zb_p, 0, nullptr, w3hi_p, w3lo_p, 512, 0LL);
    }
    b3_kernel<<<(BP * 512) / 8, 256>>>(b_qkv, b_out);

    // 6. out = x_f16 · W3[bp]^T + b3[bp]  (single-A, 2 products, 3 matrices)
    {
        dim3 grid(EDIM / 128, MTOT / 128);
        gemm_f16x2<<<grid, 128, GEM2_SMEM>>>(xf_p, w3hi_p, w3lo_p,
                                             b3_p, out, 512, (long long)512 * 512);
    }
}

// round 12
// speedup vs baseline: 2.3684x; 1.1290x over previous
#include <cuda_runtime.h>
#include <cuda_bf16.h>
#include <cuda_fp16.h>
#include <cstdint>
#include <math.h>

// ---------------- problem constants ----------------
#define NTOK  4096
#define EDIM  512
#define QKV   512
#define HEADS 8
#define DH    64
#define BP    16
#define MTOT  65536
#define EPS   1e-12f

typedef __nv_bfloat16 bf16;
typedef __half h16;

// ---------------- scratch (device globals) ----------------
__device__ bf16   g_xhi[(size_t)MTOT * 512];
__device__ bf16   g_xlo[(size_t)MTOT * 512];
__device__ h16    g_xf16[(size_t)MTOT * 512];     // single fp16 copy of x (final GEMM A)
__device__ bf16   g_wqhi[1024 * EDIM];
__device__ bf16   g_wqlo[1024 * EDIM];
__device__ bf16   g_Shi[BP * 512 * 512];
__device__ bf16   g_Slo[BP * 512 * 512];
__device__ float  g_Sp[(size_t)4 * BP * 10 * 128 * 128];   // SYRK k-partials
__device__ float  g_T[(size_t)BP * 512 * 1024];            // [Tq | Tk] per bp
__device__ float  g_s[BP * 512];
__device__ float  g_attn[BP * HEADS * DH * DH];
__device__ bf16   g_w2hi[BP * EDIM * QKV];
__device__ bf16   g_w2lo[BP * EDIM * QKV];
__device__ bf16   g_wvthi[EDIM * QKV];
__device__ bf16   g_wvtlo[EDIM * QKV];
__device__ h16    g_w3f16[BP * EDIM * EDIM];      // single fp16 (final GEMM B)
__device__ float  g_b3[BP * EDIM];
__device__ float  g_zerobias[1024];               // stays zero

// ---------------- PTX helpers ----------------
__device__ __forceinline__ uint32_t smem_u32(const void* p) {
    uint32_t a;
    asm("{ .reg .u64 t; cvta.to.shared.u64 t, %1; cvt.u32.u64 %0, t; }" : "=r"(a) : "l"(p));
    return a;
}
__device__ __forceinline__ void cp16(uint32_t saddr, const void* gptr) {
    asm volatile("cp.async.cg.shared.global [%0], [%1], 16;" :: "r"(saddr), "l"(gptr));
}
__device__ __forceinline__ void ldsm4(uint32_t& r0, uint32_t& r1, uint32_t& r2, uint32_t& r3,
                                      uint32_t addr) {
    asm volatile("ldmatrix.sync.aligned.m8n8.x4.shared.b16 {%0,%1,%2,%3}, [%4];"
                 : "=r"(r0), "=r"(r1), "=r"(r2), "=r"(r3) : "r"(addr));
}
__device__ __forceinline__ void ldsm4t(uint32_t& r0, uint32_t& r1, uint32_t& r2, uint32_t& r3,
                                       uint32_t addr) {
    asm volatile("ldmatrix.sync.aligned.m8n8.x4.trans.shared.b16 {%0,%1,%2,%3}, [%4];"
                 : "=r"(r0), "=r"(r1), "=r"(r2), "=r"(r3) : "r"(addr));
}
__device__ __forceinline__ void mma16816(float* d, const uint32_t* a, uint32_t b0, uint32_t b1) {
    asm volatile(
        "mma.sync.aligned.m16n8k16.row.col.f32.bf16.bf16.f32 "
        "{%0,%1,%2,%3}, {%4,%5,%6,%7}, {%8,%9}, {%0,%1,%2,%3};"
        : "+f"(d[0]), "+f"(d[1]), "+f"(d[2]), "+f"(d[3])
        : "r"(a[0]), "r"(a[1]), "r"(a[2]), "r"(a[3]), "r"(b0), "r"(b1));
}
__device__ __forceinline__ void mma16816h(float* d, const uint32_t* a, uint32_t b0, uint32_t b1) {
    asm volatile(
        "mma.sync.aligned.m16n8k16.row.col.f32.f16.f16.f32 "
        "{%0,%1,%2,%3}, {%4,%5,%6,%7}, {%8,%9}, {%0,%1,%2,%3};"
        : "+f"(d[0]), "+f"(d[1]), "+f"(d[2]), "+f"(d[3])
        : "r"(a[0]), "r"(a[1]), "r"(a[2]), "r"(a[3]), "r"(b0), "r"(b1));
}
__device__ __forceinline__ __nv_bfloat162 hi2(float a, float b) {
    __nv_bfloat162 r; r.x = __float2bfloat16(a); r.y = __float2bfloat16(b); return r;
}
__device__ __forceinline__ __nv_bfloat162 lo2(float a, float b) {
    __nv_bfloat162 r;
    r.x = __float2bfloat16(a - __bfloat162float(__float2bfloat16(a)));
    r.y = __float2bfloat16(b - __bfloat162float(__float2bfloat16(b)));
    return r;
}
__device__ __forceinline__ __half2 h2hi(float a, float b) {
    return __floats2half2_rn(a, b);
}

// ===========================================================================
// bf16x3 GEMM (ROUND-8 PROVEN): C = (Ahi+Alo)·(Bhi+Blo)^T + bias; K=512.
// fp32 out (Cfp) or single-fp16 out (Chi — used for W3 only).
// ===========================================================================
#define ROWB   80
#define MATB   (128 * ROWB)
#define STGB   (4 * MATB)               // 40960
#define OFF_AH 0
#define OFF_AL MATB
#define OFF_BH (2 * MATB)
#define OFF_BL (3 * MATB)
#define NKCH   16

__global__ __launch_bounds__(128, 2)
void gemm_bf16x3(const bf16* __restrict__ Ahi, const bf16* __restrict__ Alo,
                 const bf16* __restrict__ Bhi, const bf16* __restrict__ Blo,
                 const float* __restrict__ bias, int biasStride,
                 float* __restrict__ Cfp, h16* __restrict__ Chi,
                 int ldc, long long bStride)
{
    extern __shared__ char smem[];
    uint32_t sb = smem_u32(smem);
    int tid = threadIdx.x, wid = tid >> 5, lane = tid & 31;
    int n0 = blockIdx.x * 128, m0 = blockIdx.y * 128;
    int batch = m0 >> 12;

    const bf16* bh = Bhi + (long long)batch * bStride;
    const bf16* bl = Blo + (long long)batch * bStride;

    float acc[4][8][4];
#pragma unroll
    for (int i = 0; i < 4; i++)
#pragma unroll
        for (int j = 0; j < 8; j++)
#pragma unroll
            for (int r = 0; r < 4; r++) acc[i][j][r] = 0.f;

    auto load_stage = [&](int chunk, int stage) {
        uint32_t st = sb + stage * STGB;
        int k0 = chunk * 32;
#pragma unroll
        for (int i = 0; i < 4; i++) {
            int idx = i * 128 + tid;          // 0..511
            int row = idx >> 2, c = idx & 3;
            uint32_t so = (uint32_t)(row * ROWB + c * 16);
            long long ga = (long long)(m0 + row) * 512 + k0 + c * 8;
            long long gb = (long long)(n0 + row) * 512 + k0 + c * 8;
            cp16(st + OFF_AH + so, Ahi + ga);
            cp16(st + OFF_AL + so, Alo + ga);
            cp16(st + OFF_BH + so, bh + gb);
            cp16(st + OFF_BL + so, bl + gb);
        }
        asm volatile("cp.async.commit_group;" ::: "memory");
    };

    load_stage(0, 0);

    int wm = wid >> 1, wn = wid & 1;                 // warp grid 2x2
    uint32_t aRowOff = (uint32_t)((wm * 64 + (lane & 15)) * ROWB + (lane >> 4) * 16);
    uint32_t bRowOff = (uint32_t)((wn * 64 + (lane & 15)) * ROWB + (lane >> 4) * 16);

    for (int c = 0; c < NKCH; c++) {
        if (c + 1 < NKCH) {
            load_stage(c + 1, (c + 1) & 1);
            asm volatile("cp.async.wait_group 1;" ::: "memory");
        } else {
            asm volatile("cp.async.wait_group 0;" ::: "memory");
        }
        __syncthreads();

        uint32_t st = sb + (c & 1) * STGB;
#pragma unroll
        for (int kk = 0; kk < 2; kk++) {
            uint32_t kOff = kk * 32;
            uint32_t aB = st + aRowOff + kOff;
            uint32_t bB = st + bRowOff + kOff;

            uint32_t aH[4][4], aL[4][4];
#pragma unroll
            for (int im = 0; im < 4; im++) {
                ldsm4(aH[im][0], aH[im][1], aH[im][2], aH[im][3], aB + OFF_AH + im * 16 * ROWB);
                ldsm4(aL[im][0], aL[im][1], aL[im][2], aL[im][3], aB + OFF_AL + im * 16 * ROWB);
            }
            uint32_t bH[4][4], bL[4][4];
#pragma unroll
            for (int ib = 0; ib < 4; ib++) {
                ldsm4(bH[ib][0], bH[ib][1], bH[ib][2], bH[ib][3], bB + OFF_BH + ib * 16 * ROWB);
                ldsm4(bL[ib][0], bL[ib][1], bL[ib][2], bL[ib][3], bB + OFF_BL + ib * 16 * ROWB);
            }
#pragma unroll
            for (int im = 0; im < 4; im++) {
#pragma unroll
                for (int jn = 0; jn < 8; jn++) {
                    int ib = jn >> 1, js = jn & 1;
                    mma16816(acc[im][jn], aH[im], bH[ib][js], bH[ib][2 + js]);
                    mma16816(acc[im][jn], aH[im], bL[ib][js], bL[ib][2 + js]);
                    mma16816(acc[im][jn], aL[im], bH[ib][js], bH[ib][2 + js]);
                }
            }
        }
        __syncthreads();
    }

    const float* bb = bias + (long long)batch * biasStride;
    float bcol0[8], bcol1[8];
#pragma unroll
    for (int jn = 0; jn < 8; jn++) {
        int cc = n0 + wn * 64 + jn * 8 + 2 * (lane & 3);
        bcol0[jn] = bb[cc];
        bcol1[jn] = bb[cc + 1];
    }
#pragma unroll
    for (int im = 0; im < 4; im++) {
        int r0 = m0 + wm * 64 + im * 16 + (lane >> 2);
#pragma unroll
        for (int jn = 0; jn < 8; jn++) {
            int cc = n0 + wn * 64 + jn * 8 + 2 * (lane & 3);
            float v00 = acc[im][jn][0] + bcol0[jn];
            float v01 = acc[im][jn][1] + bcol1[jn];
            float v10 = acc[im][jn][2] + bcol0[jn];
            float v11 = acc[im][jn][3] + bcol1[jn];
            if (Chi) {
                *(__half2*)(Chi + (long long)r0 * ldc + cc)       = h2hi(v00, v01);
                *(__half2*)(Chi + (long long)(r0 + 8) * ldc + cc) = h2hi(v10, v11);
            } else {
                *(float2*)(Cfp + (long long)r0 * ldc + cc)       = make_float2(v00, v01);
                *(float2*)(Cfp + (long long)(r0 + 8) * ldc + cc) = make_float2(v10, v11);
            }
        }
    }
}

// ===========================================================================
// fp16 single x single GEMM (final projection): C = A·B^T + bias.
// 2 matrices per stage, 1 MMA product. Same proven pipeline skeleton.
// ===========================================================================
#define STGB1  (2 * MATB)               // 20480
#define G_A    0
#define G_B    MATB

__global__ __launch_bounds__(128, 2)
void gemm_f16x1(const h16* __restrict__ A, const h16* __restrict__ B,
                const float* __restrict__ bias,
                float* __restrict__ Cfp, int ldc, long long bStride)
{
    extern __shared__ char smem[];
    uint32_t sb = smem_u32(smem);
    int tid = threadIdx.x, wid = tid >> 5, lane = tid & 31;
    int n0 = blockIdx.x * 128, m0 = blockIdx.y * 128;
    int batch = m0 >> 12;

    const h16* bb_ = B + (long long)batch * bStride;

    float acc[4][8][4];
#pragma unroll
    for (int i = 0; i < 4; i++)
#pragma unroll
        for (int j = 0; j < 8; j++)
#pragma unroll
            for (int r = 0; r < 4; r++) acc[i][j][r] = 0.f;

    auto load_stage = [&](int chunk, int stage) {
        uint32_t st = sb + stage * STGB1;
        int k0 = chunk * 32;
#pragma unroll
        for (int i = 0; i < 4; i++) {
            int idx = i * 128 + tid;
            int row = idx >> 2, c = idx & 3;
            uint32_t so = (uint32_t)(row * ROWB + c * 16);
            long long ga = (long long)(m0 + row) * 512 + k0 + c * 8;
            long long gb = (long long)(n0 + row) * 512 + k0 + c * 8;
            cp16(st + G_A + so, A + ga);
            cp16(st + G_B + so, bb_ + gb);
        }
        asm volatile("cp.async.commit_group;" ::: "memory");
    };

    load_stage(0, 0);

    int wm = wid >> 1, wn = wid & 1;
    uint32_t aRowOff = (uint32_t)((wm * 64 + (lane & 15)) * ROWB + (lane >> 4) * 16);
    uint32_t bRowOff = (uint32_t)((wn * 64 + (lane & 15)) * ROWB + (lane >> 4) * 16);

    for (int c = 0; c < NKCH; c++) {
        if (c + 1 < NKCH) {
            load_stage(c + 1, (c + 1) & 1);
            asm volatile("cp.async.wait_group 1;" ::: "memory");
        } else {
            asm volatile("cp.async.wait_group 0;" ::: "memory");
        }
        __syncthreads();

        uint32_t st = sb + (c & 1) * STGB1;
#pragma unroll
        for (int kk = 0; kk < 2; kk++) {
            uint32_t kOff = kk * 32;
            uint32_t aB = st + aRowOff + kOff;
            uint32_t bB = st + bRowOff + kOff;

            uint32_t aF[4][4];
#pragma unroll
            for (int im = 0; im < 4; im++)
                ldsm4(aF[im][0], aF[im][1], aF[im][2], aF[im][3], aB + G_A + im * 16 * ROWB);
            uint32_t bF[4][4];
#pragma unroll
            for (int ib = 0; ib < 4; ib++)
                ldsm4(bF[ib][0], bF[ib][1], bF[ib][2], bF[ib][3], bB + G_B + ib * 16 * ROWB);
#pragma unroll
            for (int im = 0; im < 4; im++) {
#pragma unroll
                for (int jn = 0; jn < 8; jn++) {
                    int ib = jn >> 1, js = jn & 1;
                    mma16816h(acc[im][jn], aF[im], bF[ib][js], bF[ib][2 + js]);
                }
            }
        }
        __syncthreads();
    }

    const float* bb = bias + (long long)batch * 512;
    float bcol0[8], bcol1[8];
#pragma unroll
    for (int jn = 0; jn < 8; jn++) {
        int cc = n0 + wn * 64 + jn * 8 + 2 * (lane & 3);
        bcol0[jn] = bb[cc];
        bcol1[jn] = bb[cc + 1];
    }
#pragma unroll
    for (int im = 0; im < 4; im++) {
        int r0 = m0 + wm * 64 + im * 16 + (lane >> 2);
#pragma unroll
        for (int jn = 0; jn < 8; jn++) {
            int cc = n0 + wn * 64 + jn * 8 + 2 * (lane & 3);
            *(float2*)(Cfp + (long long)r0 * ldc + cc) =
                make_float2(acc[im][jn][0] + bcol0[jn], acc[im][jn][1] + bcol1[jn]);
            *(float2*)(Cfp + (long long)(r0 + 8) * ldc + cc) =
                make_float2(acc[im][jn][2] + bcol0[jn], acc[im][jn][3] + bcol1[jn]);
        }
    }
}

// ===========================================================================
// SYRK bf16x3 partials: grid (10, 4, 16); K=1024 each.
// Diagonal blocks (e0==f0) alias B tiles onto A tiles (half the fill bytes).
// ===========================================================================
#define SROWB  272
#define SMATB  (32 * SROWB)             // 8704
#define SSTGB  (4 * SMATB)              // 34816
#define S_AH   0
#define S_AL   SMATB
#define S_BH   (2 * SMATB)
#define S_BL   (3 * SMATB)

__constant__ int c_EB[10] = {0,0,0,0,1,1,1,2,2,3};
__constant__ int c_FB[10] = {0,1,2,3,1,2,3,2,3,3};

__global__ __launch_bounds__(128, 2)
void syrk_partial(const bf16* __restrict__ Xhi, const bf16* __restrict__ Xlo)
{
    extern __shared__ char smem[];
    uint32_t sb = smem_u32(smem);
    int tid = threadIdx.x, wid = tid >> 5, lane = tid & 31;
    int p = blockIdx.x, kc = blockIdx.y, bp = blockIdx.z;
    int e0 = c_EB[p] * 128, f0 = c_FB[p] * 128;
    bool diag = (e0 == f0);
    long long xbase = (long long)bp * NTOK * 512;

    float acc[4][8][4];
#pragma unroll
    for (int i = 0; i < 4; i++)
#pragma unroll
        for (int j = 0; j < 8; j++)
#pragma unroll
            for (int r = 0; r < 4; r++) acc[i][j][r] = 0.f;

    auto load_stage = [&](int chunk, int stage) {
        uint32_t st = sb + stage * SSTGB;
        int t0 = kc * 1024 + chunk * 32;
#pragma unroll
        for (int i = 0; i < 4; i++) {
            int idx = i * 128 + tid;
            int row = idx >> 4, c = idx & 15;
            uint32_t so = (uint32_t)(row * SROWB + c * 16);
            long long ge = xbase + (long long)(t0 + row) * 512 + e0 + c * 8;
            cp16(st + S_AH + so, Xhi + ge);
            cp16(st + S_AL + so, Xlo + ge);
            if (!diag) {
                long long gf = xbase + (long long)(t0 + row) * 512 + f0 + c * 8;
                cp16(st + S_BH + so, Xhi + gf);
                cp16(st + S_BL + so, Xlo + gf);
            }
        }
        asm volatile("cp.async.commit_group;" ::: "memory");
    };

    load_stage(0, 0);

    int wm = wid >> 1, wn = wid & 1;
    int sub = lane >> 3;
    int nloc = (lane & 7) + ((sub >> 1) << 3);
    uint32_t cpad = (uint32_t)((sub & 1) * 16);
    uint32_t aColB = (uint32_t)((wm * 64) * 2) + cpad;
    uint32_t bColB = (uint32_t)((wn * 64) * 2) + cpad;
    uint32_t offBH = diag ? (uint32_t)S_AH : (uint32_t)S_BH;
    uint32_t offBL = diag ? (uint32_t)S_AL : (uint32_t)S_BL;

    const int NCH = 32;
    for (int c = 0; c < NCH; c++) {
        if (c + 1 < NCH) {
            load_stage(c + 1, (c + 1) & 1);
            asm volatile("cp.async.wait_group 1;" ::: "memory");
        } else {
            asm volatile("cp.async.wait_group 0;" ::: "memory");
        }
        __syncthreads();

        uint32_t st = sb + (c & 1) * SSTGB;
#pragma unroll
        for (int kk = 0; kk < 2; kk++) {
            uint32_t rowB = (uint32_t)((kk * 16 + nloc) * SROWB);
            uint32_t aB = st + rowB + aColB;
            uint32_t bB = st + rowB + bColB;

            uint32_t aH[4][4], aL[4][4];
#pragma unroll
            for (int im = 0; im < 4; im++) {
                ldsm4t(aH[im][0], aH[im][1], aH[im][2], aH[im][3], aB + S_AH + im * 32);
                ldsm4t(aL[im][0], aL[im][1], aL[im][2], aL[im][3], aB + S_AL + im * 32);
            }
            uint32_t bH[4][4], bL[4][4];
#pragma unroll
            for (int ib = 0; ib < 4; ib++) {
                ldsm4t(bH[ib][0], bH[ib][1], bH[ib][2], bH[ib][3], bB + offBH + ib * 32);
                ldsm4t(bL[ib][0], bL[ib][1], bL[ib][2], bL[ib][3], bB + offBL + ib * 32);
            }
#pragma unroll
            for (int im = 0; im < 4; im++) {
#pragma unroll
                for (int jn = 0; jn < 8; jn++) {
                    int ib = jn >> 1, js = jn & 1;
                    mma16816(acc[im][jn], aH[im], bH[ib][js], bH[ib][2 + js]);
                    mma16816(acc[im][jn], aH[im], bL[ib][js], bL[ib][2 + js]);
                    mma16816(acc[im][jn], aL[im], bH[ib][js], bH[ib][2 + js]);
                }
            }
        }
        __syncthreads();
    }

    float* dst = g_Sp + (((long long)kc * BP + bp) * 10 + p) * 16384;
#pragma unroll
    for (int im = 0; im < 4; im++) {
        int el = wm * 64 + im * 16 + (lane >> 2);
#pragma unroll
        for (int jn = 0; jn < 8; jn++) {
            int fl = wn * 64 + jn * 8 + 2 * (lane & 3);
            *(float2*)(dst + el * 128 + fl)       = make_float2(acc[im][jn][0], acc[im][jn][1]);
            *(float2*)(dst + (el + 8) * 128 + fl) = make_float2(acc[im][jn][2], acc[im][jn][3]);
        }
    }
}

// ===========================================================================
// SYRK finish: sum 4 partials, write bf16 hi/lo (both orientations via smem).
// ===========================================================================
__global__ __launch_bounds__(256)
void syrk_finish()
{
    extern __shared__ float tile[];    // 128 x 129
    int p = blockIdx.x, bp = blockIdx.y;
    int e0 = c_EB[p] * 128, f0 = c_FB[p] * 128;
    int tid = threadIdx.x;

    const float* p0 = g_Sp + (((long long)0 * BP + bp) * 10 + p) * 16384;
    const float* p1 = g_Sp + (((long long)1 * BP + bp) * 10 + p) * 16384;
    const float* p2 = g_Sp + (((long long)2 * BP + bp) * 10 + p) * 16384;
    const float* p3 = g_Sp + (((long long)3 * BP + bp) * 10 + p) * 16384;
    for (int idx = tid; idx < 16384; idx += 256) {
        float s = (p0[idx] + p1[idx]) + (p2[idx] + p3[idx]);
        tile[(idx >> 7) * 129 + (idx & 127)] = s;
    }
    __syncthreads();

    bf16* ShiB = g_Shi + (long long)bp * 512 * 512;
    bf16* SloB = g_Slo + (long long)bp * 512 * 512;
    for (int idx = tid; idx < 16384; idx += 256) {
        int r = idx >> 7, c = idx & 127;
        float v = tile[r * 129 + c];
        bf16 h = __float2bfloat16(v);
        ShiB[(long long)(e0 + r) * 512 + f0 + c] = h;
        SloB[(long long)(e0 + r) * 512 + f0 + c] = __float2bfloat16(v - __bfloat162float(h));
    }
    if (e0 != f0) {
        for (int idx = tid; idx < 16384; idx += 256) {
            int r = idx >> 7, c = idx & 127;
            float v = tile[c * 129 + r];
            bf16 h = __float2bfloat16(v);
            ShiB[(long long)(f0 + r) * 512 + e0 + c] = h;
            SloB[(long long)(f0 + r) * 512 + e0 + c] = __float2bfloat16(v - __bfloat162float(h));
        }
    }
}

// ===========================================================================
// fused x split (bf16 hi/lo + single fp16) + column sums
// ===========================================================================
__global__ __launch_bounds__(256) void split_colsum(const float* __restrict__ x) {
    int bp = blockIdx.x, ch = blockIdx.y, t = threadIdx.x;
    long long base = ((long long)bp * NTOK + ch * 256) * 512 + t * 2;
    float s0 = 0.f, s1 = 0.f;
    for (int n = 0; n < 256; n++) {
        long long idx = base + (long long)n * 512;
        float2 v = *(const float2*)(x + idx);
        s0 += v.x; s1 += v.y;
        ((__nv_bfloat162*)g_xhi)[idx >> 1] = hi2(v.x, v.y);
        ((__nv_bfloat162*)g_xlo)[idx >> 1] = lo2(v.x, v.y);
        ((__half2*)g_xf16)[idx >> 1]       = h2hi(v.x, v.y);
    }
    atomicAdd(&g_s[bp * 512 + t * 2], s0);
    atomicAdd(&g_s[bp * 512 + t * 2 + 1], s1);
}
__global__ void zero_s_kernel() {
    int i = blockIdx.x * blockDim.x + threadIdx.x;
    if (i < BP * 512) g_s[i] = 0.f;
}

// ===========================================================================
// weight splits
// ===========================================================================
__global__ __launch_bounds__(256) void split_bf16(const float* __restrict__ src,
                                                  bf16* __restrict__ hi,
                                                  bf16* __restrict__ lo, long long n4)
{
    long long i = (long long)blockIdx.x * 256 + threadIdx.x;
    if (i >= n4) return;
    float4 v = ((const float4*)src)[i];
    ((__nv_bfloat162*)hi)[i * 2]     = hi2(v.x, v.y);
    ((__nv_bfloat162*)hi)[i * 2 + 1] = hi2(v.z, v.w);
    ((__nv_bfloat162*)lo)[i * 2]     = lo2(v.x, v.y);
    ((__nv_bfloat162*)lo)[i * 2 + 1] = lo2(v.z, v.w);
}
__global__ __launch_bounds__(256) void wvt_split_kernel(const float* __restrict__ wqkv) {
    int i = blockIdx.x * 256 + threadIdx.x;
    if (i >= 512 * 512) return;
    int e = i >> 9, c = i & 511;
    float v = wqkv[(long long)(1024 + c) * 512 + e];
    bf16 hi = __float2bfloat16(v);
    g_wvthi[i] = hi;
    g_wvtlo[i] = __float2bfloat16(v - __bfloat162float(hi));
}

// ===========================================================================
// attention finish per (bp,h)
// ===========================================================================
__global__ __launch_bounds__(256) void attn_from_s(const float* __restrict__ wqkv,
                                                   const float* __restrict__ b_qkv,
                                                   const float* __restrict__ temp)
{
    int bp = blockIdx.x, h = blockIdx.y;
    int tid = threadIdx.x, tr = tid >> 4, tc = tid & 15;

    extern __shared__ float dyn[];
    float* wqs = dyn;                  // 64 x 68
    float* wks = dyn + 4352;
    float* tqs = dyn + 2 * 4352;
    float* tks = dyn + 3 * 4352;
    __shared__ float schunk[64];
    __shared__ float uqv[64], ukv[64], nqv[64], nkv[64], bqs[64], bks[64];

    if (tid < 64)       bqs[tid] = b_qkv[h * 64 + tid];
    else if (tid < 128) bks[tid - 64] = b_qkv[512 + h * 64 + (tid - 64)];

    float acc[4][4];
#pragma unroll
    for (int i = 0; i < 4; i++)
#pragma unroll
        for (int j = 0; j < 4; j++) acc[i][j] = 0.f;
    float uacc = 0.f, nacc = 0.f;

    const float* wq_h = wqkv + (long long)(h * 64) * 512;
    const float* wk_h = wqkv + (long long)(512 + h * 64) * 512;
    const float* T_b  = g_T + (long long)bp * 512 * 1024;
    const float* svec = g_s + bp * 512;

    for (int xc = 0; xc < 8; xc++) {
        __syncthreads();
#pragma unroll
        for (int i = 0; i < 4; i++) {
            int idx4 = i * 256 + tid;
            int row = idx4 >> 4, c4 = (idx4 & 15) * 4;
            *(float4*)&wqs[row * 68 + c4] = *(const float4*)(wq_h + (long long)row * 512 + xc * 64 + c4);
            *(float4*)&wks[row * 68 + c4] = *(const float4*)(wk_h + (long long)row * 512 + xc * 64 + c4);
            const float* trow = T_b + (long long)(xc * 64 + row) * 1024 + h * 64;
            *(float4*)&tqs[row * 68 + c4] = *(const float4*)(trow + c4);
            *(float4*)&tks[row * 68 + c4] = *(const float4*)(trow + 512 + c4);
        }
        if (tid < 64) schunk[tid] = svec[xc * 64 + tid];
        __syncthreads();
#pragma unroll 8
        for (int x = 0; x < 64; x++) {
            float rm[4], rn[4];
#pragma unroll
            for (int i = 0; i < 4; i++) rm[i] = wqs[(tr * 4 + i) * 68 + x];
            float4 r4 = *(const float4*)&tks[x * 68 + tc * 4];
            rn[0] = r4.x; rn[1] = r4.y; rn[2] = r4.z; rn[3] = r4.w;
#pragma unroll
            for (int i = 0; i < 4; i++)
#pragma unroll
                for (int j = 0; j < 4; j++) acc[i][j] += rm[i] * rn[j];
        }
        if (tid < 64) {
            int d = tid;
            for (int x = 0; x < 64; x++) {
                float w = wqs[d * 68 + x];
                uacc += w * schunk[x];
                nacc += w * tqs[x * 68 + d];
            }
        } else if (tid < 128) {
            int d = tid - 64;
            for (int x = 0; x < 64; x++) {
                float w = wks[d * 68 + x];
                uacc += w * schunk[x];
                nacc += w * tks[x * 68 + d];
            }
        }
    }

    if (tid < 64) {
        float b = bqs[tid];
        float n2 = nacc + 2.f * b * uacc + (float)NTOK * b * b;
        nqv[tid] = fmaxf(sqrtf(fmaxf(n2, 0.f)), EPS);
        uqv[tid] = uacc;
    } else if (tid < 128) {
        int d = tid - 64;
        float b = bks[d];
        float n2 = nacc + 2.f * b * uacc + (float)NTOK * b * b;
        nkv[d] = fmaxf(sqrtf(fmaxf(n2, 0.f)), EPS);
        ukv[d] = uacc;
    }
    __syncthreads();

    float tf = temp[h];
    float* Gs = wqs;
#pragma unroll
    for (int i = 0; i < 4; i++) {
        int d = tr * 4 + i;
#pragma unroll
        for (int j = 0; j < 4; j++) {
            int e = tc * 4 + j;
            float G = acc[i][j] + bqs[d] * ukv[e] + bks[e] * uqv[d]
                      + (float)NTOK * bqs[d] * bks[e];
            Gs[d * 64 + e] = G * tf / (nqv[d] * nkv[e]);
        }
    }
    __syncthreads();

    int warp = tid >> 5, lane = tid & 31;
    float* attn_base = g_attn + ((long long)(bp * HEADS + h) << 12);
    for (int rr = 0; rr < 8; rr++) {
        int r = warp * 8 + rr;
        float x0 = Gs[r * 64 + lane];
        float x1 = Gs[r * 64 + 32 + lane];
        float m = fmaxf(x0, x1);
#pragma unroll
        for (int o = 16; o > 0; o >>= 1) m = fmaxf(m, __shfl_xor_sync(0xffffffffu, m, o));
        float e0 = expf(x0 - m), e1 = expf(x1 - m);
        float ssum = e0 + e1;
#pragma unroll
        for (int o = 16; o > 0; o >>= 1) ssum += __shfl_xor_sync(0xffffffffu, ssum, o);
        float inv = 1.f / ssum;
        attn_base[r * 64 + lane]      = e0 * inv;
        attn_base[r * 64 + 32 + lane] = e1 * inv;
    }
}

// ===========================================================================
// W2[bp][f, h*64+e] = sum_d w_out[f, h*64+d]*attn[bp,h,d,e] -> bf16 hi/lo
// ===========================================================================
__global__ __launch_bounds__(256) void make_w2_kernel(const float* __restrict__ w_out) {
    long long i = (long long)blockIdx.x * 256 + threadIdx.x;
    int c = (int)(i & 511);
    int f = (int)((i >> 9) & 511);
    int bp = (int)(i >> 18);
    int h = c >> 6, e = c & 63;
    const float* wrow = w_out + f * 512 + h * 64;
    const float* acol = g_attn + ((long long)(bp * HEADS + h) << 12) + e;
    float s = 0.f;
#pragma unroll 16
    for (int d = 0; d < 64; d++) s += wrow[d] * acol[d * 64];
    bf16 hi = __float2bfloat16(s);
    g_w2hi[i] = hi;
    g_w2lo[i] = __float2bfloat16(s - __bfloat162float(hi));
}

// ===========================================================================
// b3: warp-per-row coalesced reduction
// ===========================================================================
__global__ __launch_bounds__(256) void b3_kernel(const float* __restrict__ b_qkv,
                                                 const float* __restrict__ b_out) {
    int row = blockIdx.x * 8 + (threadIdx.x >> 5);
    int lane = threadIdx.x & 31;
    const bf16* hi = g_w2hi + (long long)row * 512;
    const bf16* lo = g_w2lo + (long long)row * 512;
    const float* bv = b_qkv + 1024;
    float s = 0.f;
#pragma unroll
    for (int i = 0; i < 16; i++) {
        int c = lane + 32 * i;
        s += (__bfloat162float(hi[c]) + __bfloat162float(lo[c])) * bv[c];
    }
#pragma unroll
    for (int o = 16; o > 0; o >>= 1) s += __shfl_xor_sync(0xffffffffu, s, o);
    if (lane == 0) g_b3[row] = s + b_out[row & 511];
}

// ===========================================================================
// launch
// ===========================================================================
extern "C" void kernel_launch(void* const* d_in, const int* in_sizes, int n_in,
                              void* d_out, int out_size)
{
    const float* x     = (const float*)d_in[0];
    const float* wq    = (const float*)d_in[1];
    const float* b_qkv = (const float*)d_in[2];
    const float* temp  = (const float*)d_in[3];
    const float* w_out = (const float*)d_in[4];
    const float* b_out = (const float*)d_in[5];
    float* out = (float*)d_out;

    bf16 *xhi_p, *xlo_p, *wqhi_p, *wqlo_p, *Shi_p, *Slo_p, *w2hi_p, *w2lo_p;
    bf16 *wvthi_p, *wvtlo_p;
    h16 *xf_p, *w3f_p;
    float *T_p, *b3_p, *zb_p;
    cudaGetSymbolAddress((void**)&xhi_p,  g_xhi);
    cudaGetSymbolAddress((void**)&xlo_p,  g_xlo);
    cudaGetSymbolAddress((void**)&xf_p,   g_xf16);
    cudaGetSymbolAddress((void**)&wqhi_p, g_wqhi);
    cudaGetSymbolAddress((void**)&wqlo_p, g_wqlo);
    cudaGetSymbolAddress((void**)&Shi_p,  g_Shi);
    cudaGetSymbolAddress((void**)&Slo_p,  g_Slo);
    cudaGetSymbolAddress((void**)&T_p,    g_T);
    cudaGetSymbolAddress((void**)&w2hi_p, g_w2hi);
    cudaGetSymbolAddress((void**)&w2lo_p, g_w2lo);
    cudaGetSymbolAddress((void**)&wvthi_p, g_wvthi);
    cudaGetSymbolAddress((void**)&wvtlo_p, g_wvtlo);
    cudaGetSymbolAddress((void**)&w3f_p,  g_w3f16);
    cudaGetSymbolAddress((void**)&b3_p,   g_b3);
    cudaGetSymbolAddress((void**)&zb_p,   g_zerobias);

    const int GEMM_SMEM = 2 * STGB;      // 81920
    const int GEM1_SMEM = 2 * STGB1;     // 40960
    const int SYRK_SMEM = 2 * SSTGB;     // 69632
    const int ATTN_SMEM = 4 * 4352 * 4;  // 69632
    const int FIN_SMEM  = 128 * 129 * 4; // 66048
    cudaFuncSetAttribute(gemm_bf16x3,  cudaFuncAttributeMaxDynamicSharedMemorySize, GEMM_SMEM);
    cudaFuncSetAttribute(gemm_f16x1,   cudaFuncAttributeMaxDynamicSharedMemorySize, GEM1_SMEM);
    cudaFuncSetAttribute(syrk_partial, cudaFuncAttributeMaxDynamicSharedMemorySize, SYRK_SMEM);
    cudaFuncSetAttribute(attn_from_s,  cudaFuncAttributeMaxDynamicSharedMemorySize, ATTN_SMEM);
    cudaFuncSetAttribute(syrk_finish,  cudaFuncAttributeMaxDynamicSharedMemorySize, FIN_SMEM);

    // 1. splits + column sums (single read of x)
    zero_s_kernel<<<(BP * 512 + 255) / 256, 256>>>();
    {
        dim3 grid(BP, NTOK / 256);
        split_colsum<<<grid, 256>>>(x);
    }
    split_bf16<<<(1024 * EDIM / 4 + 255) / 256, 256>>>(wq, wqhi_p, wqlo_p, 1024 * EDIM / 4);
    wvt_split_kernel<<<(512 * 512 + 255) / 256, 256>>>(wq);

    // 2. S = X^T X: balanced k-split partials (diag-aliased), reduce+mirror+split
    {
        dim3 grid(10, 4, BP);
        syrk_partial<<<grid, 128, SYRK_SMEM>>>(xhi_p, xlo_p);
    }
    {
        dim3 grid(10, BP);
        syrk_finish<<<grid, 256, FIN_SMEM>>>();
    }

    // 3. T = S·[Wq|Wk]^T
    {
        dim3 grid(8, BP * 512 / 128);
        gemm_bf16x3<<<grid, 128, GEMM_SMEM>>>(Shi_p, Slo_p, wqhi_p, wqlo_p,
                                              zb_p, 0, T_p, nullptr, 1024, 0LL);
    }

    // 4. attention logits + softmax
    {
        dim3 grid(BP, HEADS);
        attn_from_s<<<grid, 256, ATTN_SMEM>>>(wq, b_qkv, temp);
    }

    // 5. W2; W3 = W2·Wv (single fp16 out); b3
    make_w2_kernel<<<(BP * EDIM * QKV) / 256, 256>>>(w_out);
    {
        dim3 grid(4, BP * 512 / 128);
        gemm_bf16x3<<<grid, 128, GEMM_SMEM>>>(w2hi_p, w2lo_p, wvthi_p, wvtlo_p,
                                              zb_p, 0, nullptr, w3f_p, 512, 0LL);
    }
    b3_kernel<<<(BP * 512) / 8, 256>>>(b_qkv, b_out);

    // 6. out = x_f16 · W3_f16[bp]^T + b3[bp]  (2 matrices, 1 product)
    {
        dim3 grid(EDIM / 128, MTOT / 128);
        gemm_f16x1<<<grid, 128, GEM1_SMEM>>>(xf_p, w3f_p, b3_p, out, 512,
                                             (long long)512 * 512);
    }
}

// round 13
// speedup vs baseline: 2.4452x; 1.0324x over previous
#include <cuda_runtime.h>
#include <cuda_bf16.h>
#include <cuda_fp16.h>
#include <cstdint>
#include <math.h>

// ---------------- problem constants ----------------
#define NTOK  4096
#define EDIM  512
#define QKV   512
#define HEADS 8
#define DH    64
#define BP    16
#define MTOT  65536
#define EPS   1e-12f

typedef __nv_bfloat16 bf16;
typedef __half h16;

// ---------------- scratch (device globals) ----------------
__device__ bf16   g_xhi[(size_t)MTOT * 512];
__device__ bf16   g_xlo[(size_t)MTOT * 512];
__device__ h16    g_xf16[(size_t)MTOT * 512];     // single fp16 x (final GEMM A)
__device__ h16    g_wqf16hi[1024 * EDIM];         // Wq|Wk fp16 hi/lo (T GEMM B)
__device__ h16    g_wqf16lo[1024 * EDIM];
__device__ h16    g_Sf16[BP * 512 * 512];         // S single fp16 (T GEMM A)
__device__ float  g_Sp[(size_t)4 * BP * 10 * 128 * 128];   // SYRK k-partials
__device__ float  g_T[(size_t)BP * 512 * 1024];            // [Tq | Tk] per bp
__device__ float  g_s[BP * 512];
__device__ float  g_attn[BP * HEADS * DH * DH];
__device__ bf16   g_w2hi[BP * EDIM * QKV];
__device__ bf16   g_w2lo[BP * EDIM * QKV];
__device__ bf16   g_wvthi[EDIM * QKV];
__device__ bf16   g_wvtlo[EDIM * QKV];
__device__ h16    g_w3f16[BP * EDIM * EDIM];      // single fp16 (final GEMM B)
__device__ float  g_b3[BP * EDIM];
__device__ float  g_zerobias[1024];               // stays zero

// ---------------- PTX helpers ----------------
__device__ __forceinline__ uint32_t smem_u32(const void* p) {
    uint32_t a;
    asm("{ .reg .u64 t; cvta.to.shared.u64 t, %1; cvt.u32.u64 %0, t; }" : "=r"(a) : "l"(p));
    return a;
}
__device__ __forceinline__ void cp16(uint32_t saddr, const void* gptr) {
    asm volatile("cp.async.cg.shared.global [%0], [%1], 16;" :: "r"(saddr), "l"(gptr));
}
__device__ __forceinline__ void ldsm4(uint32_t& r0, uint32_t& r1, uint32_t& r2, uint32_t& r3,
                                      uint32_t addr) {
    asm volatile("ldmatrix.sync.aligned.m8n8.x4.shared.b16 {%0,%1,%2,%3}, [%4];"
                 : "=r"(r0), "=r"(r1), "=r"(r2), "=r"(r3) : "r"(addr));
}
__device__ __forceinline__ void ldsm4t(uint32_t& r0, uint32_t& r1, uint32_t& r2, uint32_t& r3,
                                       uint32_t addr) {
    asm volatile("ldmatrix.sync.aligned.m8n8.x4.trans.shared.b16 {%0,%1,%2,%3}, [%4];"
                 : "=r"(r0), "=r"(r1), "=r"(r2), "=r"(r3) : "r"(addr));
}
__device__ __forceinline__ void mma16816(float* d, const uint32_t* a, uint32_t b0, uint32_t b1) {
    asm volatile(
        "mma.sync.aligned.m16n8k16.row.col.f32.bf16.bf16.f32 "
        "{%0,%1,%2,%3}, {%4,%5,%6,%7}, {%8,%9}, {%0,%1,%2,%3};"
        : "+f"(d[0]), "+f"(d[1]), "+f"(d[2]), "+f"(d[3])
        : "r"(a[0]), "r"(a[1]), "r"(a[2]), "r"(a[3]), "r"(b0), "r"(b1));
}
__device__ __forceinline__ void mma16816h(float* d, const uint32_t* a, uint32_t b0, uint32_t b1) {
    asm volatile(
        "mma.sync.aligned.m16n8k16.row.col.f32.f16.f16.f32 "
        "{%0,%1,%2,%3}, {%4,%5,%6,%7}, {%8,%9}, {%0,%1,%2,%3};"
        : "+f"(d[0]), "+f"(d[1]), "+f"(d[2]), "+f"(d[3])
        : "r"(a[0]), "r"(a[1]), "r"(a[2]), "r"(a[3]), "r"(b0), "r"(b1));
}
__device__ __forceinline__ __nv_bfloat162 hi2(float a, float b) {
    __nv_bfloat162 r; r.x = __float2bfloat16(a); r.y = __float2bfloat16(b); return r;
}
__device__ __forceinline__ __nv_bfloat162 lo2(float a, float b) {
    __nv_bfloat162 r;
    r.x = __float2bfloat16(a - __bfloat162float(__float2bfloat16(a)));
    r.y = __float2bfloat16(b - __bfloat162float(__float2bfloat16(b)));
    return r;
}
__device__ __forceinline__ __half2 h2hi(float a, float b) {
    return __floats2half2_rn(a, b);
}
__device__ __forceinline__ __half2 h2lo(float a, float b) {
    __half2 r;
    r.x = __float2half_rn(a - __half2float(__float2half_rn(a)));
    r.y = __float2half_rn(b - __half2float(__float2half_rn(b)));
    return r;
}

// ===========================================================================
// bf16x3 GEMM (R8-PROVEN): C = (Ahi+Alo)·(Bhi+Blo)^T + bias; K=512.
// fp32 out (Cfp) or single-fp16 out (Chi — used for W3 only).
// ===========================================================================
#define ROWB   80
#define MATB   (128 * ROWB)
#define STGB   (4 * MATB)               // 40960
#define OFF_AH 0
#define OFF_AL MATB
#define OFF_BH (2 * MATB)
#define OFF_BL (3 * MATB)
#define NKCH   16

__global__ __launch_bounds__(128, 2)
void gemm_bf16x3(const bf16* __restrict__ Ahi, const bf16* __restrict__ Alo,
                 const bf16* __restrict__ Bhi, const bf16* __restrict__ Blo,
                 const float* __restrict__ bias, int biasStride,
                 float* __restrict__ Cfp, h16* __restrict__ Chi,
                 int ldc, long long bStride)
{
    extern __shared__ char smem[];
    uint32_t sb = smem_u32(smem);
    int tid = threadIdx.x, wid = tid >> 5, lane = tid & 31;
    int n0 = blockIdx.x * 128, m0 = blockIdx.y * 128;
    int batch = m0 >> 12;

    const bf16* bh = Bhi + (long long)batch * bStride;
    const bf16* bl = Blo + (long long)batch * bStride;

    float acc[4][8][4];
#pragma unroll
    for (int i = 0; i < 4; i++)
#pragma unroll
        for (int j = 0; j < 8; j++)
#pragma unroll
            for (int r = 0; r < 4; r++) acc[i][j][r] = 0.f;

    auto load_stage = [&](int chunk, int stage) {
        uint32_t st = sb + stage * STGB;
        int k0 = chunk * 32;
#pragma unroll
        for (int i = 0; i < 4; i++) {
            int idx = i * 128 + tid;
            int row = idx >> 2, c = idx & 3;
            uint32_t so = (uint32_t)(row * ROWB + c * 16);
            long long ga = (long long)(m0 + row) * 512 + k0 + c * 8;
            long long gb = (long long)(n0 + row) * 512 + k0 + c * 8;
            cp16(st + OFF_AH + so, Ahi + ga);
            cp16(st + OFF_AL + so, Alo + ga);
            cp16(st + OFF_BH + so, bh + gb);
            cp16(st + OFF_BL + so, bl + gb);
        }
        asm volatile("cp.async.commit_group;" ::: "memory");
    };

    load_stage(0, 0);

    int wm = wid >> 1, wn = wid & 1;
    uint32_t aRowOff = (uint32_t)((wm * 64 + (lane & 15)) * ROWB + (lane >> 4) * 16);
    uint32_t bRowOff = (uint32_t)((wn * 64 + (lane & 15)) * ROWB + (lane >> 4) * 16);

    for (int c = 0; c < NKCH; c++) {
        if (c + 1 < NKCH) {
            load_stage(c + 1, (c + 1) & 1);
            asm volatile("cp.async.wait_group 1;" ::: "memory");
        } else {
            asm volatile("cp.async.wait_group 0;" ::: "memory");
        }
        __syncthreads();

        uint32_t st = sb + (c & 1) * STGB;
#pragma unroll
        for (int kk = 0; kk < 2; kk++) {
            uint32_t kOff = kk * 32;
            uint32_t aB = st + aRowOff + kOff;
            uint32_t bB = st + bRowOff + kOff;

            uint32_t aH[4][4], aL[4][4];
#pragma unroll
            for (int im = 0; im < 4; im++) {
                ldsm4(aH[im][0], aH[im][1], aH[im][2], aH[im][3], aB + OFF_AH + im * 16 * ROWB);
                ldsm4(aL[im][0], aL[im][1], aL[im][2], aL[im][3], aB + OFF_AL + im * 16 * ROWB);
            }
            uint32_t bH[4][4], bL[4][4];
#pragma unroll
            for (int ib = 0; ib < 4; ib++) {
                ldsm4(bH[ib][0], bH[ib][1], bH[ib][2], bH[ib][3], bB + OFF_BH + ib * 16 * ROWB);
                ldsm4(bL[ib][0], bL[ib][1], bL[ib][2], bL[ib][3], bB + OFF_BL + ib * 16 * ROWB);
            }
#pragma unroll
            for (int im = 0; im < 4; im++) {
#pragma unroll
                for (int jn = 0; jn < 8; jn++) {
                    int ib = jn >> 1, js = jn & 1;
                    mma16816(acc[im][jn], aH[im], bH[ib][js], bH[ib][2 + js]);
                    mma16816(acc[im][jn], aH[im], bL[ib][js], bL[ib][2 + js]);
                    mma16816(acc[im][jn], aL[im], bH[ib][js], bH[ib][2 + js]);
                }
            }
        }
        __syncthreads();
    }

    const float* bb = bias + (long long)batch * biasStride;
    float bcol0[8], bcol1[8];
#pragma unroll
    for (int jn = 0; jn < 8; jn++) {
        int cc = n0 + wn * 64 + jn * 8 + 2 * (lane & 3);
        bcol0[jn] = bb[cc];
        bcol1[jn] = bb[cc + 1];
    }
#pragma unroll
    for (int im = 0; im < 4; im++) {
        int r0 = m0 + wm * 64 + im * 16 + (lane >> 2);
#pragma unroll
        for (int jn = 0; jn < 8; jn++) {
            int cc = n0 + wn * 64 + jn * 8 + 2 * (lane & 3);
            float v00 = acc[im][jn][0] + bcol0[jn];
            float v01 = acc[im][jn][1] + bcol1[jn];
            float v10 = acc[im][jn][2] + bcol0[jn];
            float v11 = acc[im][jn][3] + bcol1[jn];
            if (Chi) {
                *(__half2*)(Chi + (long long)r0 * ldc + cc)       = h2hi(v00, v01);
                *(__half2*)(Chi + (long long)(r0 + 8) * ldc + cc) = h2hi(v10, v11);
            } else {
                *(float2*)(Cfp + (long long)r0 * ldc + cc)       = make_float2(v00, v01);
                *(float2*)(Cfp + (long long)(r0 + 8) * ldc + cc) = make_float2(v10, v11);
            }
        }
    }
}

// ===========================================================================
// T GEMM: C = A·(Bhi+Blo)^T  (A single fp16, B fp16 hi/lo, 2 products).
// 128x128 tile, 128 threads, 3 matrices/stage. (R11-proven skeleton.)
// ===========================================================================
#define STGB2  (3 * MATB)               // 30720
#define T_A    0
#define T_BH   MATB
#define T_BL   (2 * MATB)

__global__ __launch_bounds__(128, 2)
void gemm_T(const h16* __restrict__ A,
            const h16* __restrict__ Bhi, const h16* __restrict__ Blo,
            float* __restrict__ Cfp, int ldc)
{
    extern __shared__ char smem[];
    uint32_t sb = smem_u32(smem);
    int tid = threadIdx.x, wid = tid >> 5, lane = tid & 31;
    int n0 = blockIdx.x * 128, m0 = blockIdx.y * 128;

    float acc[4][8][4];
#pragma unroll
    for (int i = 0; i < 4; i++)
#pragma unroll
        for (int j = 0; j < 8; j++)
#pragma unroll
            for (int r = 0; r < 4; r++) acc[i][j][r] = 0.f;

    auto load_stage = [&](int chunk, int stage) {
        uint32_t st = sb + stage * STGB2;
        int k0 = chunk * 32;
#pragma unroll
        for (int i = 0; i < 4; i++) {
            int idx = i * 128 + tid;
            int row = idx >> 2, c = idx & 3;
            uint32_t so = (uint32_t)(row * ROWB + c * 16);
            long long ga = (long long)(m0 + row) * 512 + k0 + c * 8;
            long long gb = (long long)(n0 + row) * 512 + k0 + c * 8;
            cp16(st + T_A + so, A + ga);
            cp16(st + T_BH + so, Bhi + gb);
            cp16(st + T_BL + so, Blo + gb);
        }
        asm volatile("cp.async.commit_group;" ::: "memory");
    };

    load_stage(0, 0);

    int wm = wid >> 1, wn = wid & 1;
    uint32_t aRowOff = (uint32_t)((wm * 64 + (lane & 15)) * ROWB + (lane >> 4) * 16);
    uint32_t bRowOff = (uint32_t)((wn * 64 + (lane & 15)) * ROWB + (lane >> 4) * 16);

    for (int c = 0; c < NKCH; c++) {
        if (c + 1 < NKCH) {
            load_stage(c + 1, (c + 1) & 1);
            asm volatile("cp.async.wait_group 1;" ::: "memory");
        } else {
            asm volatile("cp.async.wait_group 0;" ::: "memory");
        }
        __syncthreads();

        uint32_t st = sb + (c & 1) * STGB2;
#pragma unroll
        for (int kk = 0; kk < 2; kk++) {
            uint32_t kOff = kk * 32;
            uint32_t aB = st + aRowOff + kOff;
            uint32_t bB = st + bRowOff + kOff;

            uint32_t aF[4][4];
#pragma unroll
            for (int im = 0; im < 4; im++)
                ldsm4(aF[im][0], aF[im][1], aF[im][2], aF[im][3], aB + T_A + im * 16 * ROWB);
            uint32_t bH[4][4], bL[4][4];
#pragma unroll
            for (int ib = 0; ib < 4; ib++) {
                ldsm4(bH[ib][0], bH[ib][1], bH[ib][2], bH[ib][3], bB + T_BH + ib * 16 * ROWB);
                ldsm4(bL[ib][0], bL[ib][1], bL[ib][2], bL[ib][3], bB + T_BL + ib * 16 * ROWB);
            }
#pragma unroll
            for (int im = 0; im < 4; im++) {
#pragma unroll
                for (int jn = 0; jn < 8; jn++) {
                    int ib = jn >> 1, js = jn & 1;
                    mma16816h(acc[im][jn], aF[im], bH[ib][js], bH[ib][2 + js]);
                    mma16816h(acc[im][jn], aF[im], bL[ib][js], bL[ib][2 + js]);
                }
            }
        }
        __syncthreads();
    }

#pragma unroll
    for (int im = 0; im < 4; im++) {
        int r0 = m0 + wm * 64 + im * 16 + (lane >> 2);
#pragma unroll
        for (int jn = 0; jn < 8; jn++) {
            int cc = n0 + wn * 64 + jn * 8 + 2 * (lane & 3);
            *(float2*)(Cfp + (long long)r0 * ldc + cc) =
                make_float2(acc[im][jn][0], acc[im][jn][1]);
            *(float2*)(Cfp + (long long)(r0 + 8) * ldc + cc) =
                make_float2(acc[im][jn][2], acc[im][jn][3]);
        }
    }
}

// ===========================================================================
// Final GEMM: C = A·B^T + bias; single fp16 x single fp16, 256x128 CTA tile.
// 256 threads, 8 warps (4m x 2n), warp tile 64x64, 2-stage, 1 CTA/SM.
// ===========================================================================
#define F_STG  (384 * ROWB)             // 30720
#define F_OFFA 0
#define F_OFFB (256 * ROWB)             // 20480

__global__ __launch_bounds__(256, 1)
void gemm_final(const h16* __restrict__ A, const h16* __restrict__ B,
                const float* __restrict__ bias,
                float* __restrict__ Cfp, int ldc, long long bStride)
{
    extern __shared__ char smem[];
    uint32_t sb = smem_u32(smem);
    int tid = threadIdx.x, wid = tid >> 5, lane = tid & 31;
    int n0 = blockIdx.x * 128, m0 = blockIdx.y * 256;
    int batch = m0 >> 12;

    const h16* bb_ = B + (long long)batch * bStride;

    float acc[4][8][4];
#pragma unroll
    for (int i = 0; i < 4; i++)
#pragma unroll
        for (int j = 0; j < 8; j++)
#pragma unroll
            for (int r = 0; r < 4; r++) acc[i][j][r] = 0.f;

    auto load_stage = [&](int chunk, int stage) {
        uint32_t st = sb + stage * F_STG;
        int k0 = chunk * 32;
#pragma unroll
        for (int i = 0; i < 6; i++) {
            int idx = i * 256 + tid;          // 0..1535
            int row = idx >> 2, c = idx & 3;  // 384 rows x 4 16B-chunks
            if (row < 256) {
                cp16(st + F_OFFA + (uint32_t)(row * ROWB + c * 16),
                     A + (long long)(m0 + row) * 512 + k0 + c * 8);
            } else {
                int r2 = row - 256;
                cp16(st + F_OFFB + (uint32_t)(r2 * ROWB + c * 16),
                     bb_ + (long long)(n0 + r2) * 512 + k0 + c * 8);
            }
        }
        asm volatile("cp.async.commit_group;" ::: "memory");
    };

    load_stage(0, 0);

    int wm = wid >> 1, wn = wid & 1;       // warp grid 4m x 2n
    uint32_t aRowOff = (uint32_t)(F_OFFA + (wm * 64 + (lane & 15)) * ROWB + (lane >> 4) * 16);
    uint32_t bRowOff = (uint32_t)(F_OFFB + (wn * 64 + (lane & 15)) * ROWB + (lane >> 4) * 16);

    for (int c = 0; c < NKCH; c++) {
        if (c + 1 < NKCH) {
            load_stage(c + 1, (c + 1) & 1);
            asm volatile("cp.async.wait_group 1;" ::: "memory");
        } else {
            asm volatile("cp.async.wait_group 0;" ::: "memory");
        }
        __syncthreads();

        uint32_t st = sb + (c & 1) * F_STG;
#pragma unroll
        for (int kk = 0; kk < 2; kk++) {
            uint32_t kOff = kk * 32;
            uint32_t aB = st + aRowOff + kOff;
            uint32_t bB = st + bRowOff + kOff;

            uint32_t aF[4][4];
#pragma unroll
            for (int im = 0; im < 4; im++)
                ldsm4(aF[im][0], aF[im][1], aF[im][2], aF[im][3], aB + im * 16 * ROWB);
            uint32_t bF[4][4];
#pragma unroll
            for (int ib = 0; ib < 4; ib++)
                ldsm4(bF[ib][0], bF[ib][1], bF[ib][2], bF[ib][3], bB + ib * 16 * ROWB);
#pragma unroll
            for (int im = 0; im < 4; im++) {
#pragma unroll
                for (int jn = 0; jn < 8; jn++) {
                    int ib = jn >> 1, js = jn & 1;
                    mma16816h(acc[im][jn], aF[im], bF[ib][js], bF[ib][2 + js]);
                }
            }
        }
        __syncthreads();
    }

    const float* bb = bias + (long long)batch * 512;
    float bcol0[8], bcol1[8];
#pragma unroll
    for (int jn = 0; jn < 8; jn++) {
        int cc = n0 + wn * 64 + jn * 8 + 2 * (lane & 3);
        bcol0[jn] = bb[cc];
        bcol1[jn] = bb[cc + 1];
    }
#pragma unroll
    for (int im = 0; im < 4; im++) {
        int r0 = m0 + wm * 64 + im * 16 + (lane >> 2);
#pragma unroll
        for (int jn = 0; jn < 8; jn++) {
            int cc = n0 + wn * 64 + jn * 8 + 2 * (lane & 3);
            *(float2*)(Cfp + (long long)r0 * ldc + cc) =
                make_float2(acc[im][jn][0] + bcol0[jn], acc[im][jn][1] + bcol1[jn]);
            *(float2*)(Cfp + (long long)(r0 + 8) * ldc + cc) =
                make_float2(acc[im][jn][2] + bcol0[jn], acc[im][jn][3] + bcol1[jn]);
        }
    }
}

// ===========================================================================
// SYRK bf16x3 partials: grid (10, 4, 16); K=1024 each. Diag blocks aliased.
// ===========================================================================
#define SROWB  272
#define SMATB  (32 * SROWB)             // 8704
#define SSTGB  (4 * SMATB)              // 34816
#define S_AH   0
#define S_AL   SMATB
#define S_BH   (2 * SMATB)
#define S_BL   (3 * SMATB)

__constant__ int c_EB[10] = {0,0,0,0,1,1,1,2,2,3};
__constant__ int c_FB[10] = {0,1,2,3,1,2,3,2,3,3};

__global__ __launch_bounds__(128, 2)
void syrk_partial(const bf16* __restrict__ Xhi, const bf16* __restrict__ Xlo)
{
    extern __shared__ char smem[];
    uint32_t sb = smem_u32(smem);
    int tid = threadIdx.x, wid = tid >> 5, lane = tid & 31;
    int p = blockIdx.x, kc = blockIdx.y, bp = blockIdx.z;
    int e0 = c_EB[p] * 128, f0 = c_FB[p] * 128;
    bool diag = (e0 == f0);
    long long xbase = (long long)bp * NTOK * 512;

    float acc[4][8][4];
#pragma unroll
    for (int i = 0; i < 4; i++)
#pragma unroll
        for (int j = 0; j < 8; j++)
#pragma unroll
            for (int r = 0; r < 4; r++) acc[i][j][r] = 0.f;

    auto load_stage = [&](int chunk, int stage) {
        uint32_t st = sb + stage * SSTGB;
        int t0 = kc * 1024 + chunk * 32;
#pragma unroll
        for (int i = 0; i < 4; i++) {
            int idx = i * 128 + tid;
            int row = idx >> 4, c = idx & 15;
            uint32_t so = (uint32_t)(row * SROWB + c * 16);
            long long ge = xbase + (long long)(t0 + row) * 512 + e0 + c * 8;
            cp16(st + S_AH + so, Xhi + ge);
            cp16(st + S_AL + so, Xlo + ge);
            if (!diag) {
                long long gf = xbase + (long long)(t0 + row) * 512 + f0 + c * 8;
                cp16(st + S_BH + so, Xhi + gf);
                cp16(st + S_BL + so, Xlo + gf);
            }
        }
        asm volatile("cp.async.commit_group;" ::: "memory");
    };

    load_stage(0, 0);

    int wm = wid >> 1, wn = wid & 1;
    int sub = lane >> 3;
    int nloc = (lane & 7) + ((sub >> 1) << 3);
    uint32_t cpad = (uint32_t)((sub & 1) * 16);
    uint32_t aColB = (uint32_t)((wm * 64) * 2) + cpad;
    uint32_t bColB = (uint32_t)((wn * 64) * 2) + cpad;
    uint32_t offBH = diag ? (uint32_t)S_AH : (uint32_t)S_BH;
    uint32_t offBL = diag ? (uint32_t)S_AL : (uint32_t)S_BL;

    const int NCH = 32;
    for (int c = 0; c < NCH; c++) {
        if (c + 1 < NCH) {
            load_stage(c + 1, (c + 1) & 1);
            asm volatile("cp.async.wait_group 1;" ::: "memory");
        } else {
            asm volatile("cp.async.wait_group 0;" ::: "memory");
        }
        __syncthreads();

        uint32_t st = sb + (c & 1) * SSTGB;
#pragma unroll
        for (int kk = 0; kk < 2; kk++) {
            uint32_t rowB = (uint32_t)((kk * 16 + nloc) * SROWB);
            uint32_t aB = st + rowB + aColB;
            uint32_t bB = st + rowB + bColB;

            uint32_t aH[4][4], aL[4][4];
#pragma unroll
            for (int im = 0; im < 4; im++) {
                ldsm4t(aH[im][0], aH[im][1], aH[im][2], aH[im][3], aB + S_AH + im * 32);
                ldsm4t(aL[im][0], aL[im][1], aL[im][2], aL[im][3], aB + S_AL + im * 32);
            }
            uint32_t bH[4][4], bL[4][4];
#pragma unroll
            for (int ib = 0; ib < 4; ib++) {
                ldsm4t(bH[ib][0], bH[ib][1], bH[ib][2], bH[ib][3], bB + offBH + ib * 32);
                ldsm4t(bL[ib][0], bL[ib][1], bL[ib][2], bL[ib][3], bB + offBL + ib * 32);
            }
#pragma unroll
            for (int im = 0; im < 4; im++) {
#pragma unroll
                for (int jn = 0; jn < 8; jn++) {
                    int ib = jn >> 1, js = jn & 1;
                    mma16816(acc[im][jn], aH[im], bH[ib][js], bH[ib][2 + js]);
                    mma16816(acc[im][jn], aH[im], bL[ib][js], bL[ib][2 + js]);
                    mma16816(acc[im][jn], aL[im], bH[ib][js], bH[ib][2 + js]);
                }
            }
        }
        __syncthreads();
    }

    float* dst = g_Sp + (((long long)kc * BP + bp) * 10 + p) * 16384;
#pragma unroll
    for (int im = 0; im < 4; im++) {
        int el = wm * 64 + im * 16 + (lane >> 2);
#pragma unroll
        for (int jn = 0; jn < 8; jn++) {
            int fl = wn * 64 + jn * 8 + 2 * (lane & 3);
            *(float2*)(dst + el * 128 + fl)       = make_float2(acc[im][jn][0], acc[im][jn][1]);
            *(float2*)(dst + (el + 8) * 128 + fl) = make_float2(acc[im][jn][2], acc[im][jn][3]);
        }
    }
}

// ===========================================================================
// SYRK finish: sum 4 partials, write single fp16 S (both orientations).
// ===========================================================================
__global__ __launch_bounds__(256)
void syrk_finish()
{
    extern __shared__ float tile[];    // 128 x 129
    int p = blockIdx.x, bp = blockIdx.y;
    int e0 = c_EB[p] * 128, f0 = c_FB[p] * 128;
    int tid = threadIdx.x;

    const float* p0 = g_Sp + (((long long)0 * BP + bp) * 10 + p) * 16384;
    const float* p1 = g_Sp + (((long long)1 * BP + bp) * 10 + p) * 16384;
    const float* p2 = g_Sp + (((long long)2 * BP + bp) * 10 + p) * 16384;
    const float* p3 = g_Sp + (((long long)3 * BP + bp) * 10 + p) * 16384;
    for (int idx = tid; idx < 16384; idx += 256) {
        float s = (p0[idx] + p1[idx]) + (p2[idx] + p3[idx]);
        tile[(idx >> 7) * 129 + (idx & 127)] = s;
    }
    __syncthreads();

    h16* SB = g_Sf16 + (long long)bp * 512 * 512;
    for (int idx = tid; idx < 16384; idx += 256) {
        int r = idx >> 7, c = idx & 127;
        SB[(long long)(e0 + r) * 512 + f0 + c] = __float2half_rn(tile[r * 129 + c]);
    }
    if (e0 != f0) {
        for (int idx = tid; idx < 16384; idx += 256) {
            int r = idx >> 7, c = idx & 127;
            SB[(long long)(f0 + r) * 512 + e0 + c] = __float2half_rn(tile[c * 129 + r]);
        }
    }
}

// ===========================================================================
// fused x split (bf16 hi/lo + single fp16) + column sums
// ===========================================================================
__global__ __launch_bounds__(256) void split_colsum(const float* __restrict__ x) {
    int bp = blockIdx.x, ch = blockIdx.y, t = threadIdx.x;
    long long base = ((long long)bp * NTOK + ch * 256) * 512 + t * 2;
    float s0 = 0.f, s1 = 0.f;
    for (int n = 0; n < 256; n++) {
        long long idx = base + (long long)n * 512;
        float2 v = *(const float2*)(x + idx);
        s0 += v.x; s1 += v.y;
        ((__nv_bfloat162*)g_xhi)[idx >> 1] = hi2(v.x, v.y);
        ((__nv_bfloat162*)g_xlo)[idx >> 1] = lo2(v.x, v.y);
        ((__half2*)g_xf16)[idx >> 1]       = h2hi(v.x, v.y);
    }
    atomicAdd(&g_s[bp * 512 + t * 2], s0);
    atomicAdd(&g_s[bp * 512 + t * 2 + 1], s1);
}
__global__ void zero_s_kernel() {
    int i = blockIdx.x * blockDim.x + threadIdx.x;
    if (i < BP * 512) g_s[i] = 0.f;
}

// ===========================================================================
// weight splits
// ===========================================================================
__global__ __launch_bounds__(256) void split_f16(const float* __restrict__ src,
                                                 h16* __restrict__ hi,
                                                 h16* __restrict__ lo, long long n4)
{
    long long i = (long long)blockIdx.x * 256 + threadIdx.x;
    if (i >= n4) return;
    float4 v = ((const float4*)src)[i];
    ((__half2*)hi)[i * 2]     = h2hi(v.x, v.y);
    ((__half2*)hi)[i * 2 + 1] = h2hi(v.z, v.w);
    ((__half2*)lo)[i * 2]     = h2lo(v.x, v.y);
    ((__half2*)lo)[i * 2 + 1] = h2lo(v.z, v.w);
}
__global__ __launch_bounds__(256) void wvt_split_kernel(const float* __restrict__ wqkv) {
    int i = blockIdx.x * 256 + threadIdx.x;
    if (i >= 512 * 512) return;
    int e = i >> 9, c = i & 511;
    float v = wqkv[(long long)(1024 + c) * 512 + e];
    bf16 hi = __float2bfloat16(v);
    g_wvthi[i] = hi;
    g_wvtlo[i] = __float2bfloat16(v - __bfloat162float(hi));
}

// ===========================================================================
// attention finish per (bp,h)
// ===========================================================================
__global__ __launch_bounds__(256) void attn_from_s(const float* __restrict__ wqkv,
                                                   const float* __restrict__ b_qkv,
                                                   const float* __restrict__ temp)
{
    int bp = blockIdx.x, h = blockIdx.y;
    int tid = threadIdx.x, tr = tid >> 4, tc = tid & 15;

    extern __shared__ float dyn[];
    float* wqs = dyn;                  // 64 x 68
    float* wks = dyn + 4352;
    float* tqs = dyn + 2 * 4352;
    float* tks = dyn + 3 * 4352;
    __shared__ float schunk[64];
    __shared__ float uqv[64], ukv[64], nqv[64], nkv[64], bqs[64], bks[64];

    if (tid < 64)       bqs[tid] = b_qkv[h * 64 + tid];
    else if (tid < 128) bks[tid - 64] = b_qkv[512 + h * 64 + (tid - 64)];

    float acc[4][4];
#pragma unroll
    for (int i = 0; i < 4; i++)
#pragma unroll
        for (int j = 0; j < 4; j++) acc[i][j] = 0.f;
    float uacc = 0.f, nacc = 0.f;

    const float* wq_h = wqkv + (long long)(h * 64) * 512;
    const float* wk_h = wqkv + (long long)(512 + h * 64) * 512;
    const float* T_b  = g_T + (long long)bp * 512 * 1024;
    const float* svec = g_s + bp * 512;

    for (int xc = 0; xc < 8; xc++) {
        __syncthreads();
#pragma unroll
        for (int i = 0; i < 4; i++) {
            int idx4 = i * 256 + tid;
            int row = idx4 >> 4, c4 = (idx4 & 15) * 4;
            *(float4*)&wqs[row * 68 + c4] = *(const float4*)(wq_h + (long long)row * 512 + xc * 64 + c4);
            *(float4*)&wks[row * 68 + c4] = *(const float4*)(wk_h + (long long)row * 512 + xc * 64 + c4);
            const float* trow = T_b + (long long)(xc * 64 + row) * 1024 + h * 64;
            *(float4*)&tqs[row * 68 + c4] = *(const float4*)(trow + c4);
            *(float4*)&tks[row * 68 + c4] = *(const float4*)(trow + 512 + c4);
        }
        if (tid < 64) schunk[tid] = svec[xc * 64 + tid];
        __syncthreads();
#pragma unroll 8
        for (int x = 0; x < 64; x++) {
            float rm[4], rn[4];
#pragma unroll
            for (int i = 0; i < 4; i++) rm[i] = wqs[(tr * 4 + i) * 68 + x];
            float4 r4 = *(const float4*)&tks[x * 68 + tc * 4];
            rn[0] = r4.x; rn[1] = r4.y; rn[2] = r4.z; rn[3] = r4.w;
#pragma unroll
            for (int i = 0; i < 4; i++)
#pragma unroll
                for (int j = 0; j < 4; j++) acc[i][j] += rm[i] * rn[j];
        }
        if (tid < 64) {
            int d = tid;
            for (int x = 0; x < 64; x++) {
                float w = wqs[d * 68 + x];
                uacc += w * schunk[x];
                nacc += w * tqs[x * 68 + d];
            }
        } else if (tid < 128) {
            int d = tid - 64;
            for (int x = 0; x < 64; x++) {
                float w = wks[d * 68 + x];
                uacc += w * schunk[x];
                nacc += w * tks[x * 68 + d];
            }
        }
    }

    if (tid < 64) {
        float b = bqs[tid];
        float n2 = nacc + 2.f * b * uacc + (float)NTOK * b * b;
        nqv[tid] = fmaxf(sqrtf(fmaxf(n2, 0.f)), EPS);
        uqv[tid] = uacc;
    } else if (tid < 128) {
        int d = tid - 64;
        float b = bks[d];
        float n2 = nacc + 2.f * b * uacc + (float)NTOK * b * b;
        nkv[d] = fmaxf(sqrtf(fmaxf(n2, 0.f)), EPS);
        ukv[d] = uacc;
    }
    __syncthreads();

    float tf = temp[h];
    float* Gs = wqs;
#pragma unroll
    for (int i = 0; i < 4; i++) {
        int d = tr * 4 + i;
#pragma unroll
        for (int j = 0; j < 4; j++) {
            int e = tc * 4 + j;
            float G = acc[i][j] + bqs[d] * ukv[e] + bks[e] * uqv[d]
                      + (float)NTOK * bqs[d] * bks[e];
            Gs[d * 64 + e] = G * tf / (nqv[d] * nkv[e]);
        }
    }
    __syncthreads();

    int warp = tid >> 5, lane = tid & 31;
    float* attn_base = g_attn + ((long long)(bp * HEADS + h) << 12);
    for (int rr = 0; rr < 8; rr++) {
        int r = warp * 8 + rr;
        float x0 = Gs[r * 64 + lane];
        float x1 = Gs[r * 64 + 32 + lane];
        float m = fmaxf(x0, x1);
#pragma unroll
        for (int o = 16; o > 0; o >>= 1) m = fmaxf(m, __shfl_xor_sync(0xffffffffu, m, o));
        float e0 = expf(x0 - m), e1 = expf(x1 - m);
        float ssum = e0 + e1;
#pragma unroll
        for (int o = 16; o > 0; o >>= 1) ssum += __shfl_xor_sync(0xffffffffu, ssum, o);
        float inv = 1.f / ssum;
        attn_base[r * 64 + lane]      = e0 * inv;
        attn_base[r * 64 + 32 + lane] = e1 * inv;
    }
}

// ===========================================================================
// W2[bp][f, h*64+e] = sum_d w_out[f, h*64+d]*attn[bp,h,d,e] -> bf16 hi/lo
// ===========================================================================
__global__ __launch_bounds__(256) void make_w2_kernel(const float* __restrict__ w_out) {
    long long i = (long long)blockIdx.x * 256 + threadIdx.x;
    int c = (int)(i & 511);
    int f = (int)((i >> 9) & 511);
    int bp = (int)(i >> 18);
    int h = c >> 6, e = c & 63;
    const float* wrow = w_out + f * 512 + h * 64;
    const float* acol = g_attn + ((long long)(bp * HEADS + h) << 12) + e;
    float s = 0.f;
#pragma unroll 16
    for (int d = 0; d < 64; d++) s += wrow[d] * acol[d * 64];
    bf16 hi = __float2bfloat16(s);
    g_w2hi[i] = hi;
    g_w2lo[i] = __float2bfloat16(s - __bfloat162float(hi));
}

// ===========================================================================
// b3: warp-per-row coalesced reduction
// ===========================================================================
__global__ __launch_bounds__(256) void b3_kernel(const float* __restrict__ b_qkv,
                                                 const float* __restrict__ b_out) {
    int row = blockIdx.x * 8 + (threadIdx.x >> 5);
    int lane = threadIdx.x & 31;
    const bf16* hi = g_w2hi + (long long)row * 512;
    const bf16* lo = g_w2lo + (long long)row * 512;
    const float* bv = b_qkv + 1024;
    float s = 0.f;
#pragma unroll
    for (int i = 0; i < 16; i++) {
        int c = lane + 32 * i;
        s += (__bfloat162float(hi[c]) + __bfloat162float(lo[c])) * bv[c];
    }
#pragma unroll
    for (int o = 16; o > 0; o >>= 1) s += __shfl_xor_sync(0xffffffffu, s, o);
    if (lane == 0) g_b3[row] = s + b_out[row & 511];
}

// ===========================================================================
// launch
// ===========================================================================
extern "C" void kernel_launch(void* const* d_in, const int* in_sizes, int n_in,
                              void* d_out, int out_size)
{
    const float* x     = (const float*)d_in[0];
    const float* wq    = (const float*)d_in[1];
    const float* b_qkv = (const float*)d_in[2];
    const float* temp  = (const float*)d_in[3];
    const float* w_out = (const float*)d_in[4];
    const float* b_out = (const float*)d_in[5];
    float* out = (float*)d_out;

    bf16 *xhi_p, *xlo_p, *w2hi_p, *w2lo_p, *wvthi_p, *wvtlo_p;
    h16 *xf_p, *wqfhi_p, *wqflo_p, *Sf_p, *w3f_p;
    float *T_p, *b3_p, *zb_p;
    cudaGetSymbolAddress((void**)&xhi_p,  g_xhi);
    cudaGetSymbolAddress((void**)&xlo_p,  g_xlo);
    cudaGetSymbolAddress((void**)&xf_p,   g_xf16);
    cudaGetSymbolAddress((void**)&wqfhi_p, g_wqf16hi);
    cudaGetSymbolAddress((void**)&wqflo_p, g_wqf16lo);
    cudaGetSymbolAddress((void**)&Sf_p,   g_Sf16);
    cudaGetSymbolAddress((void**)&T_p,    g_T);
    cudaGetSymbolAddress((void**)&w2hi_p, g_w2hi);
    cudaGetSymbolAddress((void**)&w2lo_p, g_w2lo);
    cudaGetSymbolAddress((void**)&wvthi_p, g_wvthi);
    cudaGetSymbolAddress((void**)&wvtlo_p, g_wvtlo);
    cudaGetSymbolAddress((void**)&w3f_p,  g_w3f16);
    cudaGetSymbolAddress((void**)&b3_p,   g_b3);
    cudaGetSymbolAddress((void**)&zb_p,   g_zerobias);

    const int GEMM_SMEM = 2 * STGB;      // 81920
    const int GEMT_SMEM = 2 * STGB2;     // 61440
    const int GEMF_SMEM = 2 * F_STG;     // 61440
    const int SYRK_SMEM = 2 * SSTGB;     // 69632
    const int ATTN_SMEM = 4 * 4352 * 4;  // 69632
    const int FIN_SMEM  = 128 * 129 * 4; // 66048
    cudaFuncSetAttribute(gemm_bf16x3,  cudaFuncAttributeMaxDynamicSharedMemorySize, GEMM_SMEM);
    cudaFuncSetAttribute(gemm_T,       cudaFuncAttributeMaxDynamicSharedMemorySize, GEMT_SMEM);
    cudaFuncSetAttribute(gemm_final,   cudaFuncAttributeMaxDynamicSharedMemorySize, GEMF_SMEM);
    cudaFuncSetAttribute(syrk_partial, cudaFuncAttributeMaxDynamicSharedMemorySize, SYRK_SMEM);
    cudaFuncSetAttribute(attn_from_s,  cudaFuncAttributeMaxDynamicSharedMemorySize, ATTN_SMEM);
    cudaFuncSetAttribute(syrk_finish,  cudaFuncAttributeMaxDynamicSharedMemorySize, FIN_SMEM);

    // 1. splits + column sums (single read of x)
    zero_s_kernel<<<(BP * 512 + 255) / 256, 256>>>();
    {
        dim3 grid(BP, NTOK / 256);
        split_colsum<<<grid, 256>>>(x);
    }
    split_f16<<<(1024 * EDIM / 4 + 255) / 256, 256>>>(wq, wqfhi_p, wqflo_p, 1024 * EDIM / 4);
    wvt_split_kernel<<<(512 * 512 + 255) / 256, 256>>>(wq);

    // 2. S = X^T X: k-split partials (diag-aliased), reduce+mirror -> fp16
    {
        dim3 grid(10, 4, BP);
        syrk_partial<<<grid, 128, SYRK_SMEM>>>(xhi_p, xlo_p);
    }
    {
        dim3 grid(10, BP);
        syrk_finish<<<grid, 256, FIN_SMEM>>>();
    }

    // 3. T = Sf16·[Wq|Wk]^T  (A single fp16, B fp16 hi/lo, 2 products)
    {
        dim3 grid(8, BP * 512 / 128);
        gemm_T<<<grid, 128, GEMT_SMEM>>>(Sf_p, wqfhi_p, wqflo_p, T_p, 1024);
    }

    // 4. attention logits + softmax
    {
        dim3 grid(BP, HEADS);
        attn_from_s<<<grid, 256, ATTN_SMEM>>>(wq, b_qkv, temp);
    }

    // 5. W2; W3 = W2·Wv (single fp16 out); b3
    make_w2_kernel<<<(BP * EDIM * QKV) / 256, 256>>>(w_out);
    {
        dim3 grid(4, BP * 512 / 128);
        gemm_bf16x3<<<grid, 128, GEMM_SMEM>>>(w2hi_p, w2lo_p, wvthi_p, wvtlo_p,
                                              zb_p, 0, nullptr, w3f_p, 512, 0LL);
    }
    b3_kernel<<<(BP * 512) / 8, 256>>>(b_qkv, b_out);

    // 6. out = x_f16 · W3_f16[bp]^T + b3[bp]  (256x128 tiles, 1 product)
    {
        dim3 grid(EDIM / 128, MTOT / 256);
        gemm_final<<<grid, 256, GEMF_SMEM>>>(xf_p, w3f_p, b3_p, out, 512,
                                             (long long)512 * 512);
    }
}

// round 14
// speedup vs baseline: 2.5596x; 1.0468x over previous
#include <cuda_runtime.h>
#include <cuda_bf16.h>
#include <cuda_fp16.h>
#include <cstdint>
#include <math.h>

// ---------------- problem constants ----------------
#define NTOK  4096
#define EDIM  512
#define QKV   512
#define HEADS 8
#define DH    64
#define BP    16
#define MTOT  65536
#define EPS   1e-12f

typedef __nv_bfloat16 bf16;
typedef __half h16;

// ---------------- scratch (device globals) ----------------
__device__ bf16   g_xhi[(size_t)MTOT * 512];      // bf16 hi/lo x (SYRK)
__device__ bf16   g_xlo[(size_t)MTOT * 512];
__device__ h16    g_xf16[(size_t)MTOT * 512];     // single fp16 x (final GEMM A)
__device__ h16    g_wqf16hi[1024 * EDIM];         // Wq|Wk fp16 hi/lo (T GEMM B)
__device__ h16    g_wqf16lo[1024 * EDIM];
__device__ h16    g_Sf16[BP * 512 * 512];         // S single fp16 (T GEMM A)
__device__ float  g_Sp[(size_t)4 * BP * 10 * 128 * 128];   // SYRK k-partials
__device__ float  g_T[(size_t)BP * 512 * 1024];            // [Tq | Tk] per bp
__device__ float  g_s[BP * 512];
__device__ float  g_attn[BP * HEADS * DH * DH];
__device__ h16    g_w2f16[BP * EDIM * QKV];       // W2 single fp16
__device__ h16    g_wvtf16[EDIM * QKV];           // Wv^T single fp16
__device__ h16    g_w3f16[BP * EDIM * EDIM];      // W3 single fp16 (final GEMM B)
__device__ float  g_b3[BP * EDIM];

// ---------------- PTX helpers ----------------
__device__ __forceinline__ uint32_t smem_u32(const void* p) {
    uint32_t a;
    asm("{ .reg .u64 t; cvta.to.shared.u64 t, %1; cvt.u32.u64 %0, t; }" : "=r"(a) : "l"(p));
    return a;
}
__device__ __forceinline__ void cp16(uint32_t saddr, const void* gptr) {
    asm volatile("cp.async.cg.shared.global [%0], [%1], 16;" :: "r"(saddr), "l"(gptr));
}
__device__ __forceinline__ void ldsm4(uint32_t& r0, uint32_t& r1, uint32_t& r2, uint32_t& r3,
                                      uint32_t addr) {
    asm volatile("ldmatrix.sync.aligned.m8n8.x4.shared.b16 {%0,%1,%2,%3}, [%4];"
                 : "=r"(r0), "=r"(r1), "=r"(r2), "=r"(r3) : "r"(addr));
}
__device__ __forceinline__ void ldsm4t(uint32_t& r0, uint32_t& r1, uint32_t& r2, uint32_t& r3,
                                       uint32_t addr) {
    asm volatile("ldmatrix.sync.aligned.m8n8.x4.trans.shared.b16 {%0,%1,%2,%3}, [%4];"
                 : "=r"(r0), "=r"(r1), "=r"(r2), "=r"(r3) : "r"(addr));
}
__device__ __forceinline__ void mma16816(float* d, const uint32_t* a, uint32_t b0, uint32_t b1) {
    asm volatile(
        "mma.sync.aligned.m16n8k16.row.col.f32.bf16.bf16.f32 "
        "{%0,%1,%2,%3}, {%4,%5,%6,%7}, {%8,%9}, {%0,%1,%2,%3};"
        : "+f"(d[0]), "+f"(d[1]), "+f"(d[2]), "+f"(d[3])
        : "r"(a[0]), "r"(a[1]), "r"(a[2]), "r"(a[3]), "r"(b0), "r"(b1));
}
__device__ __forceinline__ void mma16816h(float* d, const uint32_t* a, uint32_t b0, uint32_t b1) {
    asm volatile(
        "mma.sync.aligned.m16n8k16.row.col.f32.f16.f16.f32 "
        "{%0,%1,%2,%3}, {%4,%5,%6,%7}, {%8,%9}, {%0,%1,%2,%3};"
        : "+f"(d[0]), "+f"(d[1]), "+f"(d[2]), "+f"(d[3])
        : "r"(a[0]), "r"(a[1]), "r"(a[2]), "r"(a[3]), "r"(b0), "r"(b1));
}
__device__ __forceinline__ __nv_bfloat162 hi2(float a, float b) {
    __nv_bfloat162 r; r.x = __float2bfloat16(a); r.y = __float2bfloat16(b); return r;
}
__device__ __forceinline__ __nv_bfloat162 lo2(float a, float b) {
    __nv_bfloat162 r;
    r.x = __float2bfloat16(a - __bfloat162float(__float2bfloat16(a)));
    r.y = __float2bfloat16(b - __bfloat162float(__float2bfloat16(b)));
    return r;
}
__device__ __forceinline__ __half2 h2hi(float a, float b) {
    return __floats2half2_rn(a, b);
}
__device__ __forceinline__ __half2 h2lo(float a, float b) {
    __half2 r;
    r.x = __float2half_rn(a - __half2float(__float2half_rn(a)));
    r.y = __float2half_rn(b - __half2float(__float2half_rn(b)));
    return r;
}

#define ROWB   80
#define MATB   (128 * ROWB)
#define NKCH   16

// ===========================================================================
// T GEMM: C = A·(Bhi+Blo)^T  (A single fp16, B fp16 hi/lo, 2 products).
// 128x128 tile, 128 threads, 3-STAGE cp.async (R4-proven pattern), 2 CTA/SM.
// ===========================================================================
#define STGB2  (3 * MATB)               // 30720/stage
#define T_A    0
#define T_BH   MATB
#define T_BL   (2 * MATB)

__global__ __launch_bounds__(128, 2)
void gemm_T(const h16* __restrict__ A,
            const h16* __restrict__ Bhi, const h16* __restrict__ Blo,
            float* __restrict__ Cfp, int ldc)
{
    extern __shared__ char smem[];
    uint32_t sb = smem_u32(smem);
    int tid = threadIdx.x, wid = tid >> 5, lane = tid & 31;
    int n0 = blockIdx.x * 128, m0 = blockIdx.y * 128;

    float acc[4][8][4];
#pragma unroll
    for (int i = 0; i < 4; i++)
#pragma unroll
        for (int j = 0; j < 8; j++)
#pragma unroll
            for (int r = 0; r < 4; r++) acc[i][j][r] = 0.f;

    auto load_stage = [&](int chunk, int stage) {
        uint32_t st = sb + stage * STGB2;
        int k0 = chunk * 32;
#pragma unroll
        for (int i = 0; i < 4; i++) {
            int idx = i * 128 + tid;
            int row = idx >> 2, c = idx & 3;
            uint32_t so = (uint32_t)(row * ROWB + c * 16);
            long long ga = (long long)(m0 + row) * 512 + k0 + c * 8;
            long long gb = (long long)(n0 + row) * 512 + k0 + c * 8;
            cp16(st + T_A + so, A + ga);
            cp16(st + T_BH + so, Bhi + gb);
            cp16(st + T_BL + so, Blo + gb);
        }
        asm volatile("cp.async.commit_group;" ::: "memory");
    };

    load_stage(0, 0);
    load_stage(1, 1);

    int wm = wid >> 1, wn = wid & 1;
    uint32_t aRowOff = (uint32_t)((wm * 64 + (lane & 15)) * ROWB + (lane >> 4) * 16);
    uint32_t bRowOff = (uint32_t)((wn * 64 + (lane & 15)) * ROWB + (lane >> 4) * 16);

    for (int c = 0; c < NKCH; c++) {
        if (c < NKCH - 1) asm volatile("cp.async.wait_group 1;" ::: "memory");
        else              asm volatile("cp.async.wait_group 0;" ::: "memory");
        __syncthreads();
        if (c + 2 < NKCH) load_stage(c + 2, (c + 2) % 3);

        uint32_t st = sb + (c % 3) * STGB2;
#pragma unroll
        for (int kk = 0; kk < 2; kk++) {
            uint32_t kOff = kk * 32;
            uint32_t aB = st + aRowOff + kOff;
            uint32_t bB = st + bRowOff + kOff;

            uint32_t aF[4][4];
#pragma unroll
            for (int im = 0; im < 4; im++)
                ldsm4(aF[im][0], aF[im][1], aF[im][2], aF[im][3], aB + T_A + im * 16 * ROWB);
            uint32_t bH[4][4], bL[4][4];
#pragma unroll
            for (int ib = 0; ib < 4; ib++) {
                ldsm4(bH[ib][0], bH[ib][1], bH[ib][2], bH[ib][3], bB + T_BH + ib * 16 * ROWB);
                ldsm4(bL[ib][0], bL[ib][1], bL[ib][2], bL[ib][3], bB + T_BL + ib * 16 * ROWB);
            }
#pragma unroll
            for (int im = 0; im < 4; im++) {
#pragma unroll
                for (int jn = 0; jn < 8; jn++) {
                    int ib = jn >> 1, js = jn & 1;
                    mma16816h(acc[im][jn], aF[im], bH[ib][js], bH[ib][2 + js]);
                    mma16816h(acc[im][jn], aF[im], bL[ib][js], bL[ib][2 + js]);
                }
            }
        }
    }

#pragma unroll
    for (int im = 0; im < 4; im++) {
        int r0 = m0 + wm * 64 + im * 16 + (lane >> 2);
#pragma unroll
        for (int jn = 0; jn < 8; jn++) {
            int cc = n0 + wn * 64 + jn * 8 + 2 * (lane & 3);
            *(float2*)(Cfp + (long long)r0 * ldc + cc) =
                make_float2(acc[im][jn][0], acc[im][jn][1]);
            *(float2*)(Cfp + (long long)(r0 + 8) * ldc + cc) =
                make_float2(acc[im][jn][2], acc[im][jn][3]);
        }
    }
}

// ===========================================================================
// W3 GEMM: C = A·B^T (single fp16 x single fp16, 1 product), fp16 out.
// 128x128 tile, 128 threads, 3-stage, 2 CTA/SM. A batched by row block.
// ===========================================================================
#define STGW   (2 * MATB)               // 20480/stage
#define W_A    0
#define W_B    MATB

__global__ __launch_bounds__(128, 2)
void gemm_w3(const h16* __restrict__ A, const h16* __restrict__ B,
             h16* __restrict__ Ch, int ldc)
{
    extern __shared__ char smem[];
    uint32_t sb = smem_u32(smem);
    int tid = threadIdx.x, wid = tid >> 5, lane = tid & 31;
    int n0 = blockIdx.x * 128, m0 = blockIdx.y * 128;

    float acc[4][8][4];
#pragma unroll
    for (int i = 0; i < 4; i++)
#pragma unroll
        for (int j = 0; j < 8; j++)
#pragma unroll
            for (int r = 0; r < 4; r++) acc[i][j][r] = 0.f;

    auto load_stage = [&](int chunk, int stage) {
        uint32_t st = sb + stage * STGW;
        int k0 = chunk * 32;
#pragma unroll
        for (int i = 0; i < 4; i++) {
            int idx = i * 128 + tid;
            int row = idx >> 2, c = idx & 3;
            uint32_t so = (uint32_t)(row * ROWB + c * 16);
            cp16(st + W_A + so, A + (long long)(m0 + row) * 512 + k0 + c * 8);
            cp16(st + W_B + so, B + (long long)(n0 + row) * 512 + k0 + c * 8);
        }
        asm volatile("cp.async.commit_group;" ::: "memory");
    };

    load_stage(0, 0);
    load_stage(1, 1);

    int wm = wid >> 1, wn = wid & 1;
    uint32_t aRowOff = (uint32_t)((wm * 64 + (lane & 15)) * ROWB + (lane >> 4) * 16);
    uint32_t bRowOff = (uint32_t)((wn * 64 + (lane & 15)) * ROWB + (lane >> 4) * 16);

    for (int c = 0; c < NKCH; c++) {
        if (c < NKCH - 1) asm volatile("cp.async.wait_group 1;" ::: "memory");
        else              asm volatile("cp.async.wait_group 0;" ::: "memory");
        __syncthreads();
        if (c + 2 < NKCH) load_stage(c + 2, (c + 2) % 3);

        uint32_t st = sb + (c % 3) * STGW;
#pragma unroll
        for (int kk = 0; kk < 2; kk++) {
            uint32_t kOff = kk * 32;
            uint32_t aB = st + aRowOff + kOff;
            uint32_t bB = st + bRowOff + kOff;

            uint32_t aF[4][4];
#pragma unroll
            for (int im = 0; im < 4; im++)
                ldsm4(aF[im][0], aF[im][1], aF[im][2], aF[im][3], aB + W_A + im * 16 * ROWB);
            uint32_t bF[4][4];
#pragma unroll
            for (int ib = 0; ib < 4; ib++)
                ldsm4(bF[ib][0], bF[ib][1], bF[ib][2], bF[ib][3], bB + W_B + ib * 16 * ROWB);
#pragma unroll
            for (int im = 0; im < 4; im++) {
#pragma unroll
                for (int jn = 0; jn < 8; jn++) {
                    int ib = jn >> 1, js = jn & 1;
                    mma16816h(acc[im][jn], aF[im], bF[ib][js], bF[ib][2 + js]);
                }
            }
        }
    }

#pragma unroll
    for (int im = 0; im < 4; im++) {
        int r0 = m0 + wm * 64 + im * 16 + (lane >> 2);
#pragma unroll
        for (int jn = 0; jn < 8; jn++) {
            int cc = n0 + wn * 64 + jn * 8 + 2 * (lane & 3);
            *(__half2*)(Ch + (long long)r0 * ldc + cc)       = h2hi(acc[im][jn][0], acc[im][jn][1]);
            *(__half2*)(Ch + (long long)(r0 + 8) * ldc + cc) = h2hi(acc[im][jn][2], acc[im][jn][3]);
        }
    }
}

// ===========================================================================
// Final GEMM: C = A·B^T + bias; single fp16 x single fp16, 256x128 CTA tile.
// 256 threads, 8 warps (4m x 2n), warp tile 64x64, 3-STAGE, 1 CTA/SM.
// ===========================================================================
#define F_STG  (384 * ROWB)             // 30720/stage
#define F_OFFA 0
#define F_OFFB (256 * ROWB)             // 20480

__global__ __launch_bounds__(256, 1)
void gemm_final(const h16* __restrict__ A, const h16* __restrict__ B,
                const float* __restrict__ bias,
                float* __restrict__ Cfp, int ldc, long long bStride)
{
    extern __shared__ char smem[];
    uint32_t sb = smem_u32(smem);
    int tid = threadIdx.x, wid = tid >> 5, lane = tid & 31;
    int n0 = blockIdx.x * 128, m0 = blockIdx.y * 256;
    int batch = m0 >> 12;

    const h16* bb_ = B + (long long)batch * bStride;

    float acc[4][8][4];
#pragma unroll
    for (int i = 0; i < 4; i++)
#pragma unroll
        for (int j = 0; j < 8; j++)
#pragma unroll
            for (int r = 0; r < 4; r++) acc[i][j][r] = 0.f;

    auto load_stage = [&](int chunk, int stage) {
        uint32_t st = sb + stage * F_STG;
        int k0 = chunk * 32;
#pragma unroll
        for (int i = 0; i < 6; i++) {
            int idx = i * 256 + tid;          // 0..1535
            int row = idx >> 2, c = idx & 3;  // 384 rows x 4 16B-chunks
            if (row < 256) {
                cp16(st + F_OFFA + (uint32_t)(row * ROWB + c * 16),
                     A + (long long)(m0 + row) * 512 + k0 + c * 8);
            } else {
                int r2 = row - 256;
                cp16(st + F_OFFB + (uint32_t)(r2 * ROWB + c * 16),
                     bb_ + (long long)(n0 + r2) * 512 + k0 + c * 8);
            }
        }
        asm volatile("cp.async.commit_group;" ::: "memory");
    };

    load_stage(0, 0);
    load_stage(1, 1);

    int wm = wid >> 1, wn = wid & 1;       // warp grid 4m x 2n
    uint32_t aRowOff = (uint32_t)(F_OFFA + (wm * 64 + (lane & 15)) * ROWB + (lane >> 4) * 16);
    uint32_t bRowOff = (uint32_t)(F_OFFB + (wn * 64 + (lane & 15)) * ROWB + (lane >> 4) * 16);

    for (int c = 0; c < NKCH; c++) {
        if (c < NKCH - 1) asm volatile("cp.async.wait_group 1;" ::: "memory");
        else              asm volatile("cp.async.wait_group 0;" ::: "memory");
        __syncthreads();
        if (c + 2 < NKCH) load_stage(c + 2, (c + 2) % 3);

        uint32_t st = sb + (c % 3) * F_STG;
#pragma unroll
        for (int kk = 0; kk < 2; kk++) {
            uint32_t kOff = kk * 32;
            uint32_t aB = st + aRowOff + kOff;
            uint32_t bB = st + bRowOff + kOff;

            uint32_t aF[4][4];
#pragma unroll
            for (int im = 0; im < 4; im++)
                ldsm4(aF[im][0], aF[im][1], aF[im][2], aF[im][3], aB + im * 16 * ROWB);
            uint32_t bF[4][4];
#pragma unroll
            for (int ib = 0; ib < 4; ib++)
                ldsm4(bF[ib][0], bF[ib][1], bF[ib][2], bF[ib][3], bB + ib * 16 * ROWB);
#pragma unroll
            for (int im = 0; im < 4; im++) {
#pragma unroll
                for (int jn = 0; jn < 8; jn++) {
                    int ib = jn >> 1, js = jn & 1;
                    mma16816h(acc[im][jn], aF[im], bF[ib][js], bF[ib][2 + js]);
                }
            }
        }
    }

    const float* bb = bias + (long long)batch * 512;
    float bcol0[8], bcol1[8];
#pragma unroll
    for (int jn = 0; jn < 8; jn++) {
        int cc = n0 + wn * 64 + jn * 8 + 2 * (lane & 3);
        bcol0[jn] = bb[cc];
        bcol1[jn] = bb[cc + 1];
    }
#pragma unroll
    for (int im = 0; im < 4; im++) {
        int r0 = m0 + wm * 64 + im * 16 + (lane >> 2);
#pragma unroll
        for (int jn = 0; jn < 8; jn++) {
            int cc = n0 + wn * 64 + jn * 8 + 2 * (lane & 3);
            *(float2*)(Cfp + (long long)r0 * ldc + cc) =
                make_float2(acc[im][jn][0] + bcol0[jn], acc[im][jn][1] + bcol1[jn]);
            *(float2*)(Cfp + (long long)(r0 + 8) * ldc + cc) =
                make_float2(acc[im][jn][2] + bcol0[jn], acc[im][jn][3] + bcol1[jn]);
        }
    }
}

// ===========================================================================
// SYRK bf16x3 partials: grid (10, 4, 16); K=1024 each. Diag blocks aliased.
// ===========================================================================
#define SROWB  272
#define SMATB  (32 * SROWB)             // 8704
#define SSTGB  (4 * SMATB)              // 34816
#define S_AH   0
#define S_AL   SMATB
#define S_BH   (2 * SMATB)
#define S_BL   (3 * SMATB)

__constant__ int c_EB[10] = {0,0,0,0,1,1,1,2,2,3};
__constant__ int c_FB[10] = {0,1,2,3,1,2,3,2,3,3};

__global__ __launch_bounds__(128, 2)
void syrk_partial(const bf16* __restrict__ Xhi, const bf16* __restrict__ Xlo)
{
    extern __shared__ char smem[];
    uint32_t sb = smem_u32(smem);
    int tid = threadIdx.x, wid = tid >> 5, lane = tid & 31;
    int p = blockIdx.x, kc = blockIdx.y, bp = blockIdx.z;
    int e0 = c_EB[p] * 128, f0 = c_FB[p] * 128;
    bool diag = (e0 == f0);
    long long xbase = (long long)bp * NTOK * 512;

    float acc[4][8][4];
#pragma unroll
    for (int i = 0; i < 4; i++)
#pragma unroll
        for (int j = 0; j < 8; j++)
#pragma unroll
            for (int r = 0; r < 4; r++) acc[i][j][r] = 0.f;

    auto load_stage = [&](int chunk, int stage) {
        uint32_t st = sb + stage * SSTGB;
        int t0 = kc * 1024 + chunk * 32;
#pragma unroll
        for (int i = 0; i < 4; i++) {
            int idx = i * 128 + tid;
            int row = idx >> 4, c = idx & 15;
            uint32_t so = (uint32_t)(row * SROWB + c * 16);
            long long ge = xbase + (long long)(t0 + row) * 512 + e0 + c * 8;
            cp16(st + S_AH + so, Xhi + ge);
            cp16(st + S_AL + so, Xlo + ge);
            if (!diag) {
                long long gf = xbase + (long long)(t0 + row) * 512 + f0 + c * 8;
                cp16(st + S_BH + so, Xhi + gf);
                cp16(st + S_BL + so, Xlo + gf);
            }
        }
        asm volatile("cp.async.commit_group;" ::: "memory");
    };

    load_stage(0, 0);

    int wm = wid >> 1, wn = wid & 1;
    int sub = lane >> 3;
    int nloc = (lane & 7) + ((sub >> 1) << 3);
    uint32_t cpad = (uint32_t)((sub & 1) * 16);
    uint32_t aColB = (uint32_t)((wm * 64) * 2) + cpad;
    uint32_t bColB = (uint32_t)((wn * 64) * 2) + cpad;
    uint32_t offBH = diag ? (uint32_t)S_AH : (uint32_t)S_BH;
    uint32_t offBL = diag ? (uint32_t)S_AL : (uint32_t)S_BL;

    const int NCH = 32;
    for (int c = 0; c < NCH; c++) {
        if (c + 1 < NCH) {
            load_stage(c + 1, (c + 1) & 1);
            asm volatile("cp.async.wait_group 1;" ::: "memory");
        } else {
            asm volatile("cp.async.wait_group 0;" ::: "memory");
        }
        __syncthreads();

        uint32_t st = sb + (c & 1) * SSTGB;
#pragma unroll
        for (int kk = 0; kk < 2; kk++) {
            uint32_t rowB = (uint32_t)((kk * 16 + nloc) * SROWB);
            uint32_t aB = st + rowB + aColB;
            uint32_t bB = st + rowB + bColB;

            uint32_t aH[4][4], aL[4][4];
#pragma unroll
            for (int im = 0; im < 4; im++) {
                ldsm4t(aH[im][0], aH[im][1], aH[im][2], aH[im][3], aB + S_AH + im * 32);
                ldsm4t(aL[im][0], aL[im][1], aL[im][2], aL[im][3], aB + S_AL + im * 32);
            }
            uint32_t bH[4][4], bL[4][4];
#pragma unroll
            for (int ib = 0; ib < 4; ib++) {
                ldsm4t(bH[ib][0], bH[ib][1], bH[ib][2], bH[ib][3], bB + offBH + ib * 32);
                ldsm4t(bL[ib][0], bL[ib][1], bL[ib][2], bL[ib][3], bB + offBL + ib * 32);
            }
#pragma unroll
            for (int im = 0; im < 4; im++) {
#pragma unroll
                for (int jn = 0; jn < 8; jn++) {
                    int ib = jn >> 1, js = jn & 1;
                    mma16816(acc[im][jn], aH[im], bH[ib][js], bH[ib][2 + js]);
                    mma16816(acc[im][jn], aH[im], bL[ib][js], bL[ib][2 + js]);
                    mma16816(acc[im][jn], aL[im], bH[ib][js], bH[ib][2 + js]);
                }
            }
        }
        __syncthreads();
    }

    float* dst = g_Sp + (((long long)kc * BP + bp) * 10 + p) * 16384;
#pragma unroll
    for (int im = 0; im < 4; im++) {
        int el = wm * 64 + im * 16 + (lane >> 2);
#pragma unroll
        for (int jn = 0; jn < 8; jn++) {
            int fl = wn * 64 + jn * 8 + 2 * (lane & 3);
            *(float2*)(dst + el * 128 + fl)       = make_float2(acc[im][jn][0], acc[im][jn][1]);
            *(float2*)(dst + (el + 8) * 128 + fl) = make_float2(acc[im][jn][2], acc[im][jn][3]);
        }
    }
}

// ===========================================================================
// SYRK finish: sum 4 partials, write single fp16 S (both orientations).
// ===========================================================================
__global__ __launch_bounds__(256)
void syrk_finish()
{
    extern __shared__ float tile[];    // 128 x 129
    int p = blockIdx.x, bp = blockIdx.y;
    int e0 = c_EB[p] * 128, f0 = c_FB[p] * 128;
    int tid = threadIdx.x;

    const float* p0 = g_Sp + (((long long)0 * BP + bp) * 10 + p) * 16384;
    const float* p1 = g_Sp + (((long long)1 * BP + bp) * 10 + p) * 16384;
    const float* p2 = g_Sp + (((long long)2 * BP + bp) * 10 + p) * 16384;
    const float* p3 = g_Sp + (((long long)3 * BP + bp) * 10 + p) * 16384;
    for (int idx = tid; idx < 16384; idx += 256) {
        float s = (p0[idx] + p1[idx]) + (p2[idx] + p3[idx]);
        tile[(idx >> 7) * 129 + (idx & 127)] = s;
    }
    __syncthreads();

    h16* SB = g_Sf16 + (long long)bp * 512 * 512;
    for (int idx = tid; idx < 16384; idx += 256) {
        int r = idx >> 7, c = idx & 127;
        SB[(long long)(e0 + r) * 512 + f0 + c] = __float2half_rn(tile[r * 129 + c]);
    }
    if (e0 != f0) {
        for (int idx = tid; idx < 16384; idx += 256) {
            int r = idx >> 7, c = idx & 127;
            SB[(long long)(f0 + r) * 512 + e0 + c] = __float2half_rn(tile[c * 129 + r]);
        }
    }
}

// ===========================================================================
// fused x split (bf16 hi/lo + single fp16) + column sums
// ===========================================================================
__global__ __launch_bounds__(256) void split_colsum(const float* __restrict__ x) {
    int bp = blockIdx.x, ch = blockIdx.y, t = threadIdx.x;
    long long base = ((long long)bp * NTOK + ch * 256) * 512 + t * 2;
    float s0 = 0.f, s1 = 0.f;
    for (int n = 0; n < 256; n++) {
        long long idx = base + (long long)n * 512;
        float2 v = *(const float2*)(x + idx);
        s0 += v.x; s1 += v.y;
        ((__nv_bfloat162*)g_xhi)[idx >> 1] = hi2(v.x, v.y);
        ((__nv_bfloat162*)g_xlo)[idx >> 1] = lo2(v.x, v.y);
        ((__half2*)g_xf16)[idx >> 1]       = h2hi(v.x, v.y);
    }
    atomicAdd(&g_s[bp * 512 + t * 2], s0);
    atomicAdd(&g_s[bp * 512 + t * 2 + 1], s1);
}
__global__ void zero_s_kernel() {
    int i = blockIdx.x * blockDim.x + threadIdx.x;
    if (i < BP * 512) g_s[i] = 0.f;
}

// ===========================================================================
// weight splits
// ===========================================================================
__global__ __launch_bounds__(256) void split_f16(const float* __restrict__ src,
                                                 h16* __restrict__ hi,
                                                 h16* __restrict__ lo, long long n4)
{
    long long i = (long long)blockIdx.x * 256 + threadIdx.x;
    if (i >= n4) return;
    float4 v = ((const float4*)src)[i];
    ((__half2*)hi)[i * 2]     = h2hi(v.x, v.y);
    ((__half2*)hi)[i * 2 + 1] = h2hi(v.z, v.w);
    ((__half2*)lo)[i * 2]     = h2lo(v.x, v.y);
    ((__half2*)lo)[i * 2 + 1] = h2lo(v.z, v.w);
}
__global__ __launch_bounds__(256) void wvt_split_kernel(const float* __restrict__ wqkv) {
    int i = blockIdx.x * 256 + threadIdx.x;
    if (i >= 512 * 512) return;
    int e = i >> 9, c = i & 511;
    g_wvtf16[i] = __float2half_rn(wqkv[(long long)(1024 + c) * 512 + e]);
}

// ===========================================================================
// attention finish per (bp,h)
// ===========================================================================
__global__ __launch_bounds__(256) void attn_from_s(const float* __restrict__ wqkv,
                                                   const float* __restrict__ b_qkv,
                                                   const float* __restrict__ temp)
{
    int bp = blockIdx.x, h = blockIdx.y;
    int tid = threadIdx.x, tr = tid >> 4, tc = tid & 15;

    extern __shared__ float dyn[];
    float* wqs = dyn;                  // 64 x 68
    float* wks = dyn + 4352;
    float* tqs = dyn + 2 * 4352;
    float* tks = dyn + 3 * 4352;
    __shared__ float schunk[64];
    __shared__ float uqv[64], ukv[64], nqv[64], nkv[64], bqs[64], bks[64];

    if (tid < 64)       bqs[tid] = b_qkv[h * 64 + tid];
    else if (tid < 128) bks[tid - 64] = b_qkv[512 + h * 64 + (tid - 64)];

    float acc[4][4];
#pragma unroll
    for (int i = 0; i < 4; i++)
#pragma unroll
        for (int j = 0; j < 4; j++) acc[i][j] = 0.f;
    float uacc = 0.f, nacc = 0.f;

    const float* wq_h = wqkv + (long long)(h * 64) * 512;
    const float* wk_h = wqkv + (long long)(512 + h * 64) * 512;
    const float* T_b  = g_T + (long long)bp * 512 * 1024;
    const float* svec = g_s + bp * 512;

    for (int xc = 0; xc < 8; xc++) {
        __syncthreads();
#pragma unroll
        for (int i = 0; i < 4; i++) {
            int idx4 = i * 256 + tid;
            int row = idx4 >> 4, c4 = (idx4 & 15) * 4;
            *(float4*)&wqs[row * 68 + c4] = *(const float4*)(wq_h + (long long)row * 512 + xc * 64 + c4);
            *(float4*)&wks[row * 68 + c4] = *(const float4*)(wk_h + (long long)row * 512 + xc * 64 + c4);
            const float* trow = T_b + (long long)(xc * 64 + row) * 1024 + h * 64;
            *(float4*)&tqs[row * 68 + c4] = *(const float4*)(trow + c4);
            *(float4*)&tks[row * 68 + c4] = *(const float4*)(trow + 512 + c4);
        }
        if (tid < 64) schunk[tid] = svec[xc * 64 + tid];
        __syncthreads();
#pragma unroll 8
        for (int x = 0; x < 64; x++) {
            float rm[4], rn[4];
#pragma unroll
            for (int i = 0; i < 4; i++) rm[i] = wqs[(tr * 4 + i) * 68 + x];
            float4 r4 = *(const float4*)&tks[x * 68 + tc * 4];
            rn[0] = r4.x; rn[1] = r4.y; rn[2] = r4.z; rn[3] = r4.w;
#pragma unroll
            for (int i = 0; i < 4; i++)
#pragma unroll
                for (int j = 0; j < 4; j++) acc[i][j] += rm[i] * rn[j];
        }
        if (tid < 64) {
            int d = tid;
            for (int x = 0; x < 64; x++) {
                float w = wqs[d * 68 + x];
                uacc += w * schunk[x];
                nacc += w * tqs[x * 68 + d];
            }
        } else if (tid < 128) {
            int d = tid - 64;
            for (int x = 0; x < 64; x++) {
                float w = wks[d * 68 + x];
                uacc += w * schunk[x];
                nacc += w * tks[x * 68 + d];
            }
        }
    }

    if (tid < 64) {
        float b = bqs[tid];
        float n2 = nacc + 2.f * b * uacc + (float)NTOK * b * b;
        nqv[tid] = fmaxf(sqrtf(fmaxf(n2, 0.f)), EPS);
        uqv[tid] = uacc;
    } else if (tid < 128) {
        int d = tid - 64;
        float b = bks[d];
        float n2 = nacc + 2.f * b * uacc + (float)NTOK * b * b;
        nkv[d] = fmaxf(sqrtf(fmaxf(n2, 0.f)), EPS);
        ukv[d] = uacc;
    }
    __syncthreads();

    float tf = temp[h];
    float* Gs = wqs;
#pragma unroll
    for (int i = 0; i < 4; i++) {
        int d = tr * 4 + i;
#pragma unroll
        for (int j = 0; j < 4; j++) {
            int e = tc * 4 + j;
            float G = acc[i][j] + bqs[d] * ukv[e] + bks[e] * uqv[d]
                      + (float)NTOK * bqs[d] * bks[e];
            Gs[d * 64 + e] = G * tf / (nqv[d] * nkv[e]);
        }
    }
    __syncthreads();

    int warp = tid >> 5, lane = tid & 31;
    float* attn_base = g_attn + ((long long)(bp * HEADS + h) << 12);
    for (int rr = 0; rr < 8; rr++) {
        int r = warp * 8 + rr;
        float x0 = Gs[r * 64 + lane];
        float x1 = Gs[r * 64 + 32 + lane];
        float m = fmaxf(x0, x1);
#pragma unroll
        for (int o = 16; o > 0; o >>= 1) m = fmaxf(m, __shfl_xor_sync(0xffffffffu, m, o));
        float e0 = expf(x0 - m), e1 = expf(x1 - m);
        float ssum = e0 + e1;
#pragma unroll
        for (int o = 16; o > 0; o >>= 1) ssum += __shfl_xor_sync(0xffffffffu, ssum, o);
        float inv = 1.f / ssum;
        attn_base[r * 64 + lane]      = e0 * inv;
        attn_base[r * 64 + 32 + lane] = e1 * inv;
    }
}

// ===========================================================================
// W2[bp][f, h*64+e] = sum_d w_out[f, h*64+d]*attn[bp,h,d,e] -> single fp16
// ===========================================================================
__global__ __launch_bounds__(256) void make_w2_kernel(const float* __restrict__ w_out) {
    long long i = (long long)blockIdx.x * 256 + threadIdx.x;
    int c = (int)(i & 511);
    int f = (int)((i >> 9) & 511);
    int bp = (int)(i >> 18);
    int h = c >> 6, e = c & 63;
    const float* wrow = w_out + f * 512 + h * 64;
    const float* acol = g_attn + ((long long)(bp * HEADS + h) << 12) + e;
    float s = 0.f;
#pragma unroll 16
    for (int d = 0; d < 64; d++) s += wrow[d] * acol[d * 64];
    g_w2f16[i] = __float2half_rn(s);
}

// ===========================================================================
// b3: warp-per-row coalesced reduction (reads w2 fp16 single)
// ===========================================================================
__global__ __launch_bounds__(256) void b3_kernel(const float* __restrict__ b_qkv,
                                                 const float* __restrict__ b_out) {
    int row = blockIdx.x * 8 + (threadIdx.x >> 5);
    int lane = threadIdx.x & 31;
    const h16* w2 = g_w2f16 + (long long)row * 512;
    const float* bv = b_qkv + 1024;
    float s = 0.f;
#pragma unroll
    for (int i = 0; i < 16; i++) {
        int c = lane + 32 * i;
        s += __half2float(w2[c]) * bv[c];
    }
#pragma unroll
    for (int o = 16; o > 0; o >>= 1) s += __shfl_xor_sync(0xffffffffu, s, o);
    if (lane == 0) g_b3[row] = s + b_out[row & 511];
}

// ===========================================================================
// launch
// ===========================================================================
extern "C" void kernel_launch(void* const* d_in, const int* in_sizes, int n_in,
                              void* d_out, int out_size)
{
    const float* x     = (const float*)d_in[0];
    const float* wq    = (const float*)d_in[1];
    const float* b_qkv = (const float*)d_in[2];
    const float* temp  = (const float*)d_in[3];
    const float* w_out = (const float*)d_in[4];
    const float* b_out = (const float*)d_in[5];
    float* out = (float*)d_out;

    bf16 *xhi_p, *xlo_p;
    h16 *xf_p, *wqfhi_p, *wqflo_p, *Sf_p, *w2f_p, *wvtf_p, *w3f_p;
    float *T_p, *b3_p;
    cudaGetSymbolAddress((void**)&xhi_p,  g_xhi);
    cudaGetSymbolAddress((void**)&xlo_p,  g_xlo);
    cudaGetSymbolAddress((void**)&xf_p,   g_xf16);
    cudaGetSymbolAddress((void**)&wqfhi_p, g_wqf16hi);
    cudaGetSymbolAddress((void**)&wqflo_p, g_wqf16lo);
    cudaGetSymbolAddress((void**)&Sf_p,   g_Sf16);
    cudaGetSymbolAddress((void**)&T_p,    g_T);
    cudaGetSymbolAddress((void**)&w2f_p,  g_w2f16);
    cudaGetSymbolAddress((void**)&wvtf_p, g_wvtf16);
    cudaGetSymbolAddress((void**)&w3f_p,  g_w3f16);
    cudaGetSymbolAddress((void**)&b3_p,   g_b3);

    const int GEMT_SMEM = 3 * STGB2;     // 92160
    const int GEMW_SMEM = 3 * STGW;      // 61440
    const int GEMF_SMEM = 3 * F_STG;     // 92160
    const int SYRK_SMEM = 2 * SSTGB;     // 69632
    const int ATTN_SMEM = 4 * 4352 * 4;  // 69632
    const int FIN_SMEM  = 128 * 129 * 4; // 66048
    cudaFuncSetAttribute(gemm_T,       cudaFuncAttributeMaxDynamicSharedMemorySize, GEMT_SMEM);
    cudaFuncSetAttribute(gemm_w3,      cudaFuncAttributeMaxDynamicSharedMemorySize, GEMW_SMEM);
    cudaFuncSetAttribute(gemm_final,   cudaFuncAttributeMaxDynamicSharedMemorySize, GEMF_SMEM);
    cudaFuncSetAttribute(syrk_partial, cudaFuncAttributeMaxDynamicSharedMemorySize, SYRK_SMEM);
    cudaFuncSetAttribute(attn_from_s,  cudaFuncAttributeMaxDynamicSharedMemorySize, ATTN_SMEM);
    cudaFuncSetAttribute(syrk_finish,  cudaFuncAttributeMaxDynamicSharedMemorySize, FIN_SMEM);

    // 1. splits + column sums (single read of x)
    zero_s_kernel<<<(BP * 512 + 255) / 256, 256>>>();
    {
        dim3 grid(BP, NTOK / 256);
        split_colsum<<<grid, 256>>>(x);
    }
    split_f16<<<(1024 * EDIM / 4 + 255) / 256, 256>>>(wq, wqfhi_p, wqflo_p, 1024 * EDIM / 4);
    wvt_split_kernel<<<(512 * 512 + 255) / 256, 256>>>(wq);

    // 2. S = X^T X: k-split partials (diag-aliased), reduce+mirror -> fp16
    {
        dim3 grid(10, 4, BP);
        syrk_partial<<<grid, 128, SYRK_SMEM>>>(xhi_p, xlo_p);
    }
    {
        dim3 grid(10, BP);
        syrk_finish<<<grid, 256, FIN_SMEM>>>();
    }

    // 3. T = Sf16·[Wq|Wk]^T  (A single fp16, B fp16 hi/lo, 2 products, 3-stage)
    {
        dim3 grid(8, BP * 512 / 128);
        gemm_T<<<grid, 128, GEMT_SMEM>>>(Sf_p, wqfhi_p, wqflo_p, T_p, 1024);
    }

    // 4. attention logits + softmax
    {
        dim3 grid(BP, HEADS);
        attn_from_s<<<grid, 256, ATTN_SMEM>>>(wq, b_qkv, temp);
    }

    // 5. W2 (fp16 single); W3 = W2·Wv (single x single, fp16 out); b3
    make_w2_kernel<<<(BP * EDIM * QKV) / 256, 256>>>(w_out);
    {
        dim3 grid(4, BP * 512 / 128);
        gemm_w3<<<grid, 128, GEMW_SMEM>>>(w2f_p, wvtf_p, w3f_p, 512);
    }
    b3_kernel<<<(BP * 512) / 8, 256>>>(b_qkv, b_out);

    // 6. out = x_f16 · W3_f16[bp]^T + b3[bp]  (256x128 tiles, 3-stage, 1 product)
    {
        dim3 grid(EDIM / 128, MTOT / 256);
        gemm_final<<<grid, 256, GEMF_SMEM>>>(xf_p, w3f_p, b3_p, out, 512,
                                             (long long)512 * 512);
    }
}

// round 15
// speedup vs baseline: 2.7054x; 1.0570x over previous
#include <cuda_runtime.h>
#include <cuda_fp16.h>
#include <cstdint>
#include <math.h>

// ---------------- problem constants ----------------
#define NTOK  4096
#define EDIM  512
#define QKV   512
#define HEADS 8
#define DH    64
#define BP    16
#define MTOT  65536
#define EPS   1e-12f

typedef __half h16;

// ---------------- scratch (device globals) ----------------
__device__ h16    g_xf16[(size_t)MTOT * 512];     // fp16 hi of x (SYRK A/B hi, final GEMM A)
__device__ h16    g_xf16lo[(size_t)MTOT * 512];   // fp16 lo of x (SYRK)
__device__ h16    g_wqf16[1024 * EDIM];           // Wq|Wk single fp16 (T GEMM B)
__device__ h16    g_Sf16[BP * 512 * 512];         // S single fp16 (T GEMM A)
__device__ float  g_Sp[(size_t)4 * BP * 10 * 128 * 128];   // SYRK k-partials
__device__ float  g_T[(size_t)BP * 512 * 1024];            // [Tq | Tk] per bp
__device__ float  g_s[BP * 512];
__device__ float  g_attn[BP * HEADS * DH * DH];
__device__ h16    g_w2f16[BP * EDIM * QKV];       // W2 single fp16
__device__ h16    g_wvtf16[EDIM * QKV];           // Wv^T single fp16
__device__ h16    g_w3f16[BP * EDIM * EDIM];      // W3 single fp16 (final GEMM B)
__device__ float  g_b3[BP * EDIM];

// ---------------- PTX helpers ----------------
__device__ __forceinline__ uint32_t smem_u32(const void* p) {
    uint32_t a;
    asm("{ .reg .u64 t; cvta.to.shared.u64 t, %1; cvt.u32.u64 %0, t; }" : "=r"(a) : "l"(p));
    return a;
}
__device__ __forceinline__ void cp16(uint32_t saddr, const void* gptr) {
    asm volatile("cp.async.cg.shared.global [%0], [%1], 16;" :: "r"(saddr), "l"(gptr));
}
__device__ __forceinline__ void ldsm4(uint32_t& r0, uint32_t& r1, uint32_t& r2, uint32_t& r3,
                                      uint32_t addr) {
    asm volatile("ldmatrix.sync.aligned.m8n8.x4.shared.b16 {%0,%1,%2,%3}, [%4];"
                 : "=r"(r0), "=r"(r1), "=r"(r2), "=r"(r3) : "r"(addr));
}
__device__ __forceinline__ void ldsm4t(uint32_t& r0, uint32_t& r1, uint32_t& r2, uint32_t& r3,
                                       uint32_t addr) {
    asm volatile("ldmatrix.sync.aligned.m8n8.x4.trans.shared.b16 {%0,%1,%2,%3}, [%4];"
                 : "=r"(r0), "=r"(r1), "=r"(r2), "=r"(r3) : "r"(addr));
}
__device__ __forceinline__ void mma16816h(float* d, const uint32_t* a, uint32_t b0, uint32_t b1) {
    asm volatile(
        "mma.sync.aligned.m16n8k16.row.col.f32.f16.f16.f32 "
        "{%0,%1,%2,%3}, {%4,%5,%6,%7}, {%8,%9}, {%0,%1,%2,%3};"
        : "+f"(d[0]), "+f"(d[1]), "+f"(d[2]), "+f"(d[3])
        : "r"(a[0]), "r"(a[1]), "r"(a[2]), "r"(a[3]), "r"(b0), "r"(b1));
}
__device__ __forceinline__ __half2 h2hi(float a, float b) {
    return __floats2half2_rn(a, b);
}
__device__ __forceinline__ __half2 h2lo(float a, float b) {
    __half2 r;
    r.x = __float2half_rn(a - __half2float(__float2half_rn(a)));
    r.y = __float2half_rn(b - __half2float(__float2half_rn(b)));
    return r;
}

#define ROWB   80
#define MATB   (128 * ROWB)
#define NKCH   16

// ===========================================================================
// single x single fp16 GEMM (T GEMM and W3 GEMM): C = A·B^T, 1 product.
// 128x128 tile, 128 threads, 3-stage, 2 CTA/SM. Output fp32 (Cfp) or fp16 (Ch).
// ===========================================================================
#define STGW   (2 * MATB)               // 20480/stage
#define W_A    0
#define W_B    MATB

__global__ __launch_bounds__(128, 2)
void gemm_ss(const h16* __restrict__ A, const h16* __restrict__ B,
             float* __restrict__ Cfp, h16* __restrict__ Ch, int ldc)
{
    extern __shared__ char smem[];
    uint32_t sb = smem_u32(smem);
    int tid = threadIdx.x, wid = tid >> 5, lane = tid & 31;
    int n0 = blockIdx.x * 128, m0 = blockIdx.y * 128;

    float acc[4][8][4];
#pragma unroll
    for (int i = 0; i < 4; i++)
#pragma unroll
        for (int j = 0; j < 8; j++)
#pragma unroll
            for (int r = 0; r < 4; r++) acc[i][j][r] = 0.f;

    auto load_stage = [&](int chunk, int stage) {
        uint32_t st = sb + stage * STGW;
        int k0 = chunk * 32;
#pragma unroll
        for (int i = 0; i < 4; i++) {
            int idx = i * 128 + tid;
            int row = idx >> 2, c = idx & 3;
            uint32_t so = (uint32_t)(row * ROWB + c * 16);
            cp16(st + W_A + so, A + (long long)(m0 + row) * 512 + k0 + c * 8);
            cp16(st + W_B + so, B + (long long)(n0 + row) * 512 + k0 + c * 8);
        }
        asm volatile("cp.async.commit_group;" ::: "memory");
    };

    load_stage(0, 0);
    load_stage(1, 1);

    int wm = wid >> 1, wn = wid & 1;
    uint32_t aRowOff = (uint32_t)((wm * 64 + (lane & 15)) * ROWB + (lane >> 4) * 16);
    uint32_t bRowOff = (uint32_t)((wn * 64 + (lane & 15)) * ROWB + (lane >> 4) * 16);

    for (int c = 0; c < NKCH; c++) {
        if (c < NKCH - 1) asm volatile("cp.async.wait_group 1;" ::: "memory");
        else              asm volatile("cp.async.wait_group 0;" ::: "memory");
        __syncthreads();
        if (c + 2 < NKCH) load_stage(c + 2, (c + 2) % 3);

        uint32_t st = sb + (c % 3) * STGW;
#pragma unroll
        for (int kk = 0; kk < 2; kk++) {
            uint32_t kOff = kk * 32;
            uint32_t aB = st + aRowOff + kOff;
            uint32_t bB = st + bRowOff + kOff;

            uint32_t aF[4][4];
#pragma unroll
            for (int im = 0; im < 4; im++)
                ldsm4(aF[im][0], aF[im][1], aF[im][2], aF[im][3], aB + W_A + im * 16 * ROWB);
            uint32_t bF[4][4];
#pragma unroll
            for (int ib = 0; ib < 4; ib++)
                ldsm4(bF[ib][0], bF[ib][1], bF[ib][2], bF[ib][3], bB + W_B + ib * 16 * ROWB);
#pragma unroll
            for (int im = 0; im < 4; im++) {
#pragma unroll
                for (int jn = 0; jn < 8; jn++) {
                    int ib = jn >> 1, js = jn & 1;
                    mma16816h(acc[im][jn], aF[im], bF[ib][js], bF[ib][2 + js]);
                }
            }
        }
    }

#pragma unroll
    for (int im = 0; im < 4; im++) {
        int r0 = m0 + wm * 64 + im * 16 + (lane >> 2);
#pragma unroll
        for (int jn = 0; jn < 8; jn++) {
            int cc = n0 + wn * 64 + jn * 8 + 2 * (lane & 3);
            if (Ch) {
                *(__half2*)(Ch + (long long)r0 * ldc + cc)       = h2hi(acc[im][jn][0], acc[im][jn][1]);
                *(__half2*)(Ch + (long long)(r0 + 8) * ldc + cc) = h2hi(acc[im][jn][2], acc[im][jn][3]);
            } else {
                *(float2*)(Cfp + (long long)r0 * ldc + cc) =
                    make_float2(acc[im][jn][0], acc[im][jn][1]);
                *(float2*)(Cfp + (long long)(r0 + 8) * ldc + cc) =
                    make_float2(acc[im][jn][2], acc[im][jn][3]);
            }
        }
    }
}

// ===========================================================================
// Final GEMM: C = A·B^T + bias; single fp16 x single fp16, 256x128 CTA tile.
// 256 threads, 8 warps (4m x 2n), warp tile 64x64, 3-stage, 1 CTA/SM.
// ===========================================================================
#define F_STG  (384 * ROWB)             // 30720/stage
#define F_OFFA 0
#define F_OFFB (256 * ROWB)             // 20480

__global__ __launch_bounds__(256, 1)
void gemm_final(const h16* __restrict__ A, const h16* __restrict__ B,
                const float* __restrict__ bias,
                float* __restrict__ Cfp, int ldc, long long bStride)
{
    extern __shared__ char smem[];
    uint32_t sb = smem_u32(smem);
    int tid = threadIdx.x, wid = tid >> 5, lane = tid & 31;
    int n0 = blockIdx.x * 128, m0 = blockIdx.y * 256;
    int batch = m0 >> 12;

    const h16* bb_ = B + (long long)batch * bStride;

    float acc[4][8][4];
#pragma unroll
    for (int i = 0; i < 4; i++)
#pragma unroll
        for (int j = 0; j < 8; j++)
#pragma unroll
            for (int r = 0; r < 4; r++) acc[i][j][r] = 0.f;

    auto load_stage = [&](int chunk, int stage) {
        uint32_t st = sb + stage * F_STG;
        int k0 = chunk * 32;
#pragma unroll
        for (int i = 0; i < 6; i++) {
            int idx = i * 256 + tid;
            int row = idx >> 2, c = idx & 3;
            if (row < 256) {
                cp16(st + F_OFFA + (uint32_t)(row * ROWB + c * 16),
                     A + (long long)(m0 + row) * 512 + k0 + c * 8);
            } else {
                int r2 = row - 256;
                cp16(st + F_OFFB + (uint32_t)(r2 * ROWB + c * 16),
                     bb_ + (long long)(n0 + r2) * 512 + k0 + c * 8);
            }
        }
        asm volatile("cp.async.commit_group;" ::: "memory");
    };

    load_stage(0, 0);
    load_stage(1, 1);

    int wm = wid >> 1, wn = wid & 1;
    uint32_t aRowOff = (uint32_t)(F_OFFA + (wm * 64 + (lane & 15)) * ROWB + (lane >> 4) * 16);
    uint32_t bRowOff = (uint32_t)(F_OFFB + (wn * 64 + (lane & 15)) * ROWB + (lane >> 4) * 16);

    for (int c = 0; c < NKCH; c++) {
        if (c < NKCH - 1) asm volatile("cp.async.wait_group 1;" ::: "memory");
        else              asm volatile("cp.async.wait_group 0;" ::: "memory");
        __syncthreads();
        if (c + 2 < NKCH) load_stage(c + 2, (c + 2) % 3);

        uint32_t st = sb + (c % 3) * F_STG;
#pragma unroll
        for (int kk = 0; kk < 2; kk++) {
            uint32_t kOff = kk * 32;
            uint32_t aB = st + aRowOff + kOff;
            uint32_t bB = st + bRowOff + kOff;

            uint32_t aF[4][4];
#pragma unroll
            for (int im = 0; im < 4; im++)
                ldsm4(aF[im][0], aF[im][1], aF[im][2], aF[im][3], aB + im * 16 * ROWB);
            uint32_t bF[4][4];
#pragma unroll
            for (int ib = 0; ib < 4; ib++)
                ldsm4(bF[ib][0], bF[ib][1], bF[ib][2], bF[ib][3], bB + ib * 16 * ROWB);
#pragma unroll
            for (int im = 0; im < 4; im++) {
#pragma unroll
                for (int jn = 0; jn < 8; jn++) {
                    int ib = jn >> 1, js = jn & 1;
                    mma16816h(acc[im][jn], aF[im], bF[ib][js], bF[ib][2 + js]);
                }
            }
        }
    }

    const float* bb = bias + (long long)batch * 512;
    float bcol0[8], bcol1[8];
#pragma unroll
    for (int jn = 0; jn < 8; jn++) {
        int cc = n0 + wn * 64 + jn * 8 + 2 * (lane & 3);
        bcol0[jn] = bb[cc];
        bcol1[jn] = bb[cc + 1];
    }
#pragma unroll
    for (int im = 0; im < 4; im++) {
        int r0 = m0 + wm * 64 + im * 16 + (lane >> 2);
#pragma unroll
        for (int jn = 0; jn < 8; jn++) {
            int cc = n0 + wn * 64 + jn * 8 + 2 * (lane & 3);
            *(float2*)(Cfp + (long long)r0 * ldc + cc) =
                make_float2(acc[im][jn][0] + bcol0[jn], acc[im][jn][1] + bcol1[jn]);
            *(float2*)(Cfp + (long long)(r0 + 8) * ldc + cc) =
                make_float2(acc[im][jn][2] + bcol0[jn], acc[im][jn][3] + bcol1[jn]);
        }
    }
}

// ===========================================================================
// SYRK fp16x3 partials: grid (10, 4, 16); K=1024 each. Diag blocks aliased.
// x in fp16 hi/lo (split error 2^-22 — tighter than bf16).
// ===========================================================================
#define SROWB  272
#define SMATB  (32 * SROWB)             // 8704
#define SSTGB  (4 * SMATB)              // 34816
#define S_AH   0
#define S_AL   SMATB
#define S_BH   (2 * SMATB)
#define S_BL   (3 * SMATB)

__constant__ int c_EB[10] = {0,0,0,0,1,1,1,2,2,3};
__constant__ int c_FB[10] = {0,1,2,3,1,2,3,2,3,3};

__global__ __launch_bounds__(128, 2)
void syrk_partial(const h16* __restrict__ Xhi, const h16* __restrict__ Xlo)
{
    extern __shared__ char smem[];
    uint32_t sb = smem_u32(smem);
    int tid = threadIdx.x, wid = tid >> 5, lane = tid & 31;
    int p = blockIdx.x, kc = blockIdx.y, bp = blockIdx.z;
    int e0 = c_EB[p] * 128, f0 = c_FB[p] * 128;
    bool diag = (e0 == f0);
    long long xbase = (long long)bp * NTOK * 512;

    float acc[4][8][4];
#pragma unroll
    for (int i = 0; i < 4; i++)
#pragma unroll
        for (int j = 0; j < 8; j++)
#pragma unroll
            for (int r = 0; r < 4; r++) acc[i][j][r] = 0.f;

    auto load_stage = [&](int chunk, int stage) {
        uint32_t st = sb + stage * SSTGB;
        int t0 = kc * 1024 + chunk * 32;
#pragma unroll
        for (int i = 0; i < 4; i++) {
            int idx = i * 128 + tid;
            int row = idx >> 4, c = idx & 15;
            uint32_t so = (uint32_t)(row * SROWB + c * 16);
            long long ge = xbase + (long long)(t0 + row) * 512 + e0 + c * 8;
            cp16(st + S_AH + so, Xhi + ge);
            cp16(st + S_AL + so, Xlo + ge);
            if (!diag) {
                long long gf = xbase + (long long)(t0 + row) * 512 + f0 + c * 8;
                cp16(st + S_BH + so, Xhi + gf);
                cp16(st + S_BL + so, Xlo + gf);
            }
        }
        asm volatile("cp.async.commit_group;" ::: "memory");
    };

    load_stage(0, 0);

    int wm = wid >> 1, wn = wid & 1;
    int sub = lane >> 3;
    int nloc = (lane & 7) + ((sub >> 1) << 3);
    uint32_t cpad = (uint32_t)((sub & 1) * 16);
    uint32_t aColB = (uint32_t)((wm * 64) * 2) + cpad;
    uint32_t bColB = (uint32_t)((wn * 64) * 2) + cpad;
    uint32_t offBH = diag ? (uint32_t)S_AH : (uint32_t)S_BH;
    uint32_t offBL = diag ? (uint32_t)S_AL : (uint32_t)S_BL;

    const int NCH = 32;
    for (int c = 0; c < NCH; c++) {
        if (c + 1 < NCH) {
            load_stage(c + 1, (c + 1) & 1);
            asm volatile("cp.async.wait_group 1;" ::: "memory");
        } else {
            asm volatile("cp.async.wait_group 0;" ::: "memory");
        }
        __syncthreads();

        uint32_t st = sb + (c & 1) * SSTGB;
#pragma unroll
        for (int kk = 0; kk < 2; kk++) {
            uint32_t rowB = (uint32_t)((kk * 16 + nloc) * SROWB);
            uint32_t aB = st + rowB + aColB;
            uint32_t bB = st + rowB + bColB;

            uint32_t aH[4][4], aL[4][4];
#pragma unroll
            for (int im = 0; im < 4; im++) {
                ldsm4t(aH[im][0], aH[im][1], aH[im][2], aH[im][3], aB + S_AH + im * 32);
                ldsm4t(aL[im][0], aL[im][1], aL[im][2], aL[im][3], aB + S_AL + im * 32);
            }
            uint32_t bH[4][4], bL[4][4];
#pragma unroll
            for (int ib = 0; ib < 4; ib++) {
                ldsm4t(bH[ib][0], bH[ib][1], bH[ib][2], bH[ib][3], bB + offBH + ib * 32);
                ldsm4t(bL[ib][0], bL[ib][1], bL[ib][2], bL[ib][3], bB + offBL + ib * 32);
            }
#pragma unroll
            for (int im = 0; im < 4; im++) {
#pragma unroll
                for (int jn = 0; jn < 8; jn++) {
                    int ib = jn >> 1, js = jn & 1;
                    mma16816h(acc[im][jn], aH[im], bH[ib][js], bH[ib][2 + js]);
                    mma16816h(acc[im][jn], aH[im], bL[ib][js], bL[ib][2 + js]);
                    mma16816h(acc[im][jn], aL[im], bH[ib][js], bH[ib][2 + js]);
                }
            }
        }
        __syncthreads();
    }

    float* dst = g_Sp + (((long long)kc * BP + bp) * 10 + p) * 16384;
#pragma unroll
    for (int im = 0; im < 4; im++) {
        int el = wm * 64 + im * 16 + (lane >> 2);
#pragma unroll
        for (int jn = 0; jn < 8; jn++) {
            int fl = wn * 64 + jn * 8 + 2 * (lane & 3);
            *(float2*)(dst + el * 128 + fl)       = make_float2(acc[im][jn][0], acc[im][jn][1]);
            *(float2*)(dst + (el + 8) * 128 + fl) = make_float2(acc[im][jn][2], acc[im][jn][3]);
        }
    }
}

// ===========================================================================
// SYRK finish: sum 4 partials, write single fp16 S (both orientations).
// ===========================================================================
__global__ __launch_bounds__(256)
void syrk_finish()
{
    extern __shared__ float tile[];    // 128 x 129
    int p = blockIdx.x, bp = blockIdx.y;
    int e0 = c_EB[p] * 128, f0 = c_FB[p] * 128;
    int tid = threadIdx.x;

    const float* p0 = g_Sp + (((long long)0 * BP + bp) * 10 + p) * 16384;
    const float* p1 = g_Sp + (((long long)1 * BP + bp) * 10 + p) * 16384;
    const float* p2 = g_Sp + (((long long)2 * BP + bp) * 10 + p) * 16384;
    const float* p3 = g_Sp + (((long long)3 * BP + bp) * 10 + p) * 16384;
    for (int idx = tid; idx < 16384; idx += 256) {
        float s = (p0[idx] + p1[idx]) + (p2[idx] + p3[idx]);
        tile[(idx >> 7) * 129 + (idx & 127)] = s;
    }
    __syncthreads();

    h16* SB = g_Sf16 + (long long)bp * 512 * 512;
    for (int idx = tid; idx < 16384; idx += 256) {
        int r = idx >> 7, c = idx & 127;
        SB[(long long)(e0 + r) * 512 + f0 + c] = __float2half_rn(tile[r * 129 + c]);
    }
    if (e0 != f0) {
        for (int idx = tid; idx < 16384; idx += 256) {
            int r = idx >> 7, c = idx & 127;
            SB[(long long)(f0 + r) * 512 + e0 + c] = __float2half_rn(tile[c * 129 + r]);
        }
    }
}

// ===========================================================================
// fused x split (fp16 hi/lo) + column sums
// ===========================================================================
__global__ __launch_bounds__(256) void split_colsum(const float* __restrict__ x) {
    int bp = blockIdx.x, ch = blockIdx.y, t = threadIdx.x;
    long long base = ((long long)bp * NTOK + ch * 256) * 512 + t * 2;
    float s0 = 0.f, s1 = 0.f;
    for (int n = 0; n < 256; n++) {
        long long idx = base + (long long)n * 512;
        float2 v = *(const float2*)(x + idx);
        s0 += v.x; s1 += v.y;
        ((__half2*)g_xf16)[idx >> 1]   = h2hi(v.x, v.y);
        ((__half2*)g_xf16lo)[idx >> 1] = h2lo(v.x, v.y);
    }
    atomicAdd(&g_s[bp * 512 + t * 2], s0);
    atomicAdd(&g_s[bp * 512 + t * 2 + 1], s1);
}
__global__ void zero_s_kernel() {
    int i = blockIdx.x * blockDim.x + threadIdx.x;
    if (i < BP * 512) g_s[i] = 0.f;
}

// ===========================================================================
// weight splits (single fp16)
// ===========================================================================
__global__ __launch_bounds__(256) void wq_single_kernel(const float* __restrict__ wqkv) {
    int i = blockIdx.x * 256 + threadIdx.x;
    if (i >= 1024 * 512) return;
    g_wqf16[i] = __float2half_rn(wqkv[i]);
}
__global__ __launch_bounds__(256) void wvt_split_kernel(const float* __restrict__ wqkv) {
    int i = blockIdx.x * 256 + threadIdx.x;
    if (i >= 512 * 512) return;
    int e = i >> 9, c = i & 511;
    g_wvtf16[i] = __float2half_rn(wqkv[(long long)(1024 + c) * 512 + e]);
}

// ===========================================================================
// attention finish per (bp,h)
// ===========================================================================
__global__ __launch_bounds__(256) void attn_from_s(const float* __restrict__ wqkv,
                                                   const float* __restrict__ b_qkv,
                                                   const float* __restrict__ temp)
{
    int bp = blockIdx.x, h = blockIdx.y;
    int tid = threadIdx.x, tr = tid >> 4, tc = tid & 15;

    extern __shared__ float dyn[];
    float* wqs = dyn;                  // 64 x 68
    float* wks = dyn + 4352;
    float* tqs = dyn + 2 * 4352;
    float* tks = dyn + 3 * 4352;
    __shared__ float schunk[64];
    __shared__ float uqv[64], ukv[64], nqv[64], nkv[64], bqs[64], bks[64];

    if (tid < 64)       bqs[tid] = b_qkv[h * 64 + tid];
    else if (tid < 128) bks[tid - 64] = b_qkv[512 + h * 64 + (tid - 64)];

    float acc[4][4];
#pragma unroll
    for (int i = 0; i < 4; i++)
#pragma unroll
        for (int j = 0; j < 4; j++) acc[i][j] = 0.f;
    float uacc = 0.f, nacc = 0.f;

    const float* wq_h = wqkv + (long long)(h * 64) * 512;
    const float* wk_h = wqkv + (long long)(512 + h * 64) * 512;
    const float* T_b  = g_T + (long long)bp * 512 * 1024;
    const float* svec = g_s + bp * 512;

    for (int xc = 0; xc < 8; xc++) {
        __syncthreads();
#pragma unroll
        for (int i = 0; i < 4; i++) {
            int idx4 = i * 256 + tid;
            int row = idx4 >> 4, c4 = (idx4 & 15) * 4;
            *(float4*)&wqs[row * 68 + c4] = *(const float4*)(wq_h + (long long)row * 512 + xc * 64 + c4);
            *(float4*)&wks[row * 68 + c4] = *(const float4*)(wk_h + (long long)row * 512 + xc * 64 + c4);
            const float* trow = T_b + (long long)(xc * 64 + row) * 1024 + h * 64;
            *(float4*)&tqs[row * 68 + c4] = *(const float4*)(trow + c4);
            *(float4*)&tks[row * 68 + c4] = *(const float4*)(trow + 512 + c4);
        }
        if (tid < 64) schunk[tid] = svec[xc * 64 + tid];
        __syncthreads();
#pragma unroll 8
        for (int x = 0; x < 64; x++) {
            float rm[4], rn[4];
#pragma unroll
            for (int i = 0; i < 4; i++) rm[i] = wqs[(tr * 4 + i) * 68 + x];
            float4 r4 = *(const float4*)&tks[x * 68 + tc * 4];
            rn[0] = r4.x; rn[1] = r4.y; rn[2] = r4.z; rn[3] = r4.w;
#pragma unroll
            for (int i = 0; i < 4; i++)
#pragma unroll
                for (int j = 0; j < 4; j++) acc[i][j] += rm[i] * rn[j];
        }
        if (tid < 64) {
            int d = tid;
            for (int x = 0; x < 64; x++) {
                float w = wqs[d * 68 + x];
                uacc += w * schunk[x];
                nacc += w * tqs[x * 68 + d];
            }
        } else if (tid < 128) {
            int d = tid - 64;
            for (int x = 0; x < 64; x++) {
                float w = wks[d * 68 + x];
                uacc += w * schunk[x];
                nacc += w * tks[x * 68 + d];
            }
        }
    }

    if (tid < 64) {
        float b = bqs[tid];
        float n2 = nacc + 2.f * b * uacc + (float)NTOK * b * b;
        nqv[tid] = fmaxf(sqrtf(fmaxf(n2, 0.f)), EPS);
        uqv[tid] = uacc;
    } else if (tid < 128) {
        int d = tid - 64;
        float b = bks[d];
        float n2 = nacc + 2.f * b * uacc + (float)NTOK * b * b;
        nkv[d] = fmaxf(sqrtf(fmaxf(n2, 0.f)), EPS);
        ukv[d] = uacc;
    }
    __syncthreads();

    float tf = temp[h];
    float* Gs = wqs;
#pragma unroll
    for (int i = 0; i < 4; i++) {
        int d = tr * 4 + i;
#pragma unroll
        for (int j = 0; j < 4; j++) {
            int e = tc * 4 + j;
            float G = acc[i][j] + bqs[d] * ukv[e] + bks[e] * uqv[d]
                      + (float)NTOK * bqs[d] * bks[e];
            Gs[d * 64 + e] = G * tf / (nqv[d] * nkv[e]);
        }
    }
    __syncthreads();

    int warp = tid >> 5, lane = tid & 31;
    float* attn_base = g_attn + ((long long)(bp * HEADS + h) << 12);
    for (int rr = 0; rr < 8; rr++) {
        int r = warp * 8 + rr;
        float x0 = Gs[r * 64 + lane];
        float x1 = Gs[r * 64 + 32 + lane];
        float m = fmaxf(x0, x1);
#pragma unroll
        for (int o = 16; o > 0; o >>= 1) m = fmaxf(m, __shfl_xor_sync(0xffffffffu, m, o));
        float e0 = expf(x0 - m), e1 = expf(x1 - m);
        float ssum = e0 + e1;
#pragma unroll
        for (int o = 16; o > 0; o >>= 1) ssum += __shfl_xor_sync(0xffffffffu, ssum, o);
        float inv = 1.f / ssum;
        attn_base[r * 64 + lane]      = e0 * inv;
        attn_base[r * 64 + 32 + lane] = e1 * inv;
    }
}

// ===========================================================================
// W2[bp][f, h*64+e] = sum_d w_out[f, h*64+d]*attn[bp,h,d,e] -> single fp16
// ===========================================================================
__global__ __launch_bounds__(256) void make_w2_kernel(const float* __restrict__ w_out) {
    long long i = (long long)blockIdx.x * 256 + threadIdx.x;
    int c = (int)(i & 511);
    int f = (int)((i >> 9) & 511);
    int bp = (int)(i >> 18);
    int h = c >> 6, e = c & 63;
    const float* wrow = w_out + f * 512 + h * 64;
    const float* acol = g_attn + ((long long)(bp * HEADS + h) << 12) + e;
    float s = 0.f;
#pragma unroll 16
    for (int d = 0; d < 64; d++) s += wrow[d] * acol[d * 64];
    g_w2f16[i] = __float2half_rn(s);
}

// ===========================================================================
// b3: warp-per-row coalesced reduction
// ===========================================================================
__global__ __launch_bounds__(256) void b3_kernel(const float* __restrict__ b_qkv,
                                                 const float* __restrict__ b_out) {
    int row = blockIdx.x * 8 + (threadIdx.x >> 5);
    int lane = threadIdx.x & 31;
    const h16* w2 = g_w2f16 + (long long)row * 512;
    const float* bv = b_qkv + 1024;
    float s = 0.f;
#pragma unroll
    for (int i = 0; i < 16; i++) {
        int c = lane + 32 * i;
        s += __half2float(w2[c]) * bv[c];
    }
#pragma unroll
    for (int o = 16; o > 0; o >>= 1) s += __shfl_xor_sync(0xffffffffu, s, o);
    if (lane == 0) g_b3[row] = s + b_out[row & 511];
}

// ===========================================================================
// launch
// ===========================================================================
extern "C" void kernel_launch(void* const* d_in, const int* in_sizes, int n_in,
                              void* d_out, int out_size)
{
    const float* x     = (const float*)d_in[0];
    const float* wq    = (const float*)d_in[1];
    const float* b_qkv = (const float*)d_in[2];
    const float* temp  = (const float*)d_in[3];
    const float* w_out = (const float*)d_in[4];
    const float* b_out = (const float*)d_in[5];
    float* out = (float*)d_out;

    h16 *xf_p, *xflo_p, *wqf_p, *Sf_p, *w2f_p, *wvtf_p, *w3f_p;
    float *T_p, *b3_p;
    cudaGetSymbolAddress((void**)&xf_p,   g_xf16);
    cudaGetSymbolAddress((void**)&xflo_p, g_xf16lo);
    cudaGetSymbolAddress((void**)&wqf_p,  g_wqf16);
    cudaGetSymbolAddress((void**)&Sf_p,   g_Sf16);
    cudaGetSymbolAddress((void**)&T_p,    g_T);
    cudaGetSymbolAddress((void**)&w2f_p,  g_w2f16);
    cudaGetSymbolAddress((void**)&wvtf_p, g_wvtf16);
    cudaGetSymbolAddress((void**)&w3f_p,  g_w3f16);
    cudaGetSymbolAddress((void**)&b3_p,   g_b3);

    const int GEMS_SMEM = 3 * STGW;      // 61440
    const int GEMF_SMEM = 3 * F_STG;     // 92160
    const int SYRK_SMEM = 2 * SSTGB;     // 69632
    const int ATTN_SMEM = 4 * 4352 * 4;  // 69632
    const int FIN_SMEM  = 128 * 129 * 4; // 66048
    cudaFuncSetAttribute(gemm_ss,      cudaFuncAttributeMaxDynamicSharedMemorySize, GEMS_SMEM);
    cudaFuncSetAttribute(gemm_final,   cudaFuncAttributeMaxDynamicSharedMemorySize, GEMF_SMEM);
    cudaFuncSetAttribute(syrk_partial, cudaFuncAttributeMaxDynamicSharedMemorySize, SYRK_SMEM);
    cudaFuncSetAttribute(attn_from_s,  cudaFuncAttributeMaxDynamicSharedMemorySize, ATTN_SMEM);
    cudaFuncSetAttribute(syrk_finish,  cudaFuncAttributeMaxDynamicSharedMemorySize, FIN_SMEM);

    // 1. splits + column sums (single read of x; fp16 hi/lo only)
    zero_s_kernel<<<(BP * 512 + 255) / 256, 256>>>();
    {
        dim3 grid(BP, NTOK / 256);
        split_colsum<<<grid, 256>>>(x);
    }
    wq_single_kernel<<<(1024 * 512 + 255) / 256, 256>>>(wq);
    wvt_split_kernel<<<(512 * 512 + 255) / 256, 256>>>(wq);

    // 2. S = X^T X: fp16 hi/lo x3 partials (diag-aliased), reduce+mirror -> fp16
    {
        dim3 grid(10, 4, BP);
        syrk_partial<<<grid, 128, SYRK_SMEM>>>(xf_p, xflo_p);
    }
    {
        dim3 grid(10, BP);
        syrk_finish<<<grid, 256, FIN_SMEM>>>();
    }

    // 3. T = Sf16·[Wq|Wk]f16^T  (single x single, 1 product, 3-stage)
    {
        dim3 grid(8, BP * 512 / 128);
        gemm_ss<<<grid, 128, GEMS_SMEM>>>(Sf_p, wqf_p, T_p, nullptr, 1024);
    }

    // 4. attention logits + softmax
    {
        dim3 grid(BP, HEADS);
        attn_from_s<<<grid, 256, ATTN_SMEM>>>(wq, b_qkv, temp);
    }

    // 5. W2 (fp16 single); W3 = W2·Wv (single x single, fp16 out); b3
    make_w2_kernel<<<(BP * EDIM * QKV) / 256, 256>>>(w_out);
    {
        dim3 grid(4, BP * 512 / 128);
        gemm_ss<<<grid, 128, GEMS_SMEM>>>(w2f_p, wvtf_p, nullptr, w3f_p, 512);
    }
    b3_kernel<<<(BP * 512) / 8, 256>>>(b_qkv, b_out);

    // 6. out = x_f16 · W3_f16[bp]^T + b3[bp]  (256x128 tiles, 3-stage, 1 product)
    {
        dim3 grid(EDIM / 128, MTOT / 256);
        gemm_final<<<grid, 256, GEMF_SMEM>>>(xf_p, w3f_p, b3_p, out, 512,
                                             (long long)512 * 512);
    }
}

// round 16
// speedup vs baseline: 2.8506x; 1.0537x over previous
#include <cuda_runtime.h>
#include <cuda_fp16.h>
#include <cstdint>
#include <math.h>

// ---------------- problem constants ----------------
#define NTOK  4096
#define EDIM  512
#define QKV   512
#define HEADS 8
#define DH    64
#define BP    16
#define MTOT  65536
#define EPS   1e-12f

typedef __half h16;

// ---------------- scratch (device globals) ----------------
__device__ h16    g_xf16[(size_t)MTOT * 512];     // fp16 hi of x
__device__ h16    g_xf16lo[(size_t)MTOT * 512];   // fp16 lo of x (SYRK)
__device__ h16    g_wqf16[1024 * EDIM];           // Wq|Wk single fp16
__device__ h16    g_Sf16[BP * 512 * 512];         // S single fp16
__device__ h16    g_Sp[(size_t)4 * BP * 10 * 128 * 128];   // SYRK k-partials (fp16)
__device__ h16    g_T[(size_t)BP * 512 * 1024];            // [Tq | Tk] per bp (fp16)
__device__ float  g_s[BP * 512];
__device__ float  g_attn[BP * HEADS * DH * DH];
__device__ h16    g_w2f16[BP * EDIM * QKV];       // W2 single fp16
__device__ h16    g_wvtf16[EDIM * QKV];           // Wv^T single fp16
__device__ h16    g_w3f16[BP * EDIM * EDIM];      // W3 single fp16
__device__ float  g_b3[BP * EDIM];

// ---------------- PTX helpers ----------------
__device__ __forceinline__ uint32_t smem_u32(const void* p) {
    uint32_t a;
    asm("{ .reg .u64 t; cvta.to.shared.u64 t, %1; cvt.u32.u64 %0, t; }" : "=r"(a) : "l"(p));
    return a;
}
__device__ __forceinline__ void cp16(uint32_t saddr, const void* gptr) {
    asm volatile("cp.async.cg.shared.global [%0], [%1], 16;" :: "r"(saddr), "l"(gptr));
}
__device__ __forceinline__ void ldsm4(uint32_t& r0, uint32_t& r1, uint32_t& r2, uint32_t& r3,
                                      uint32_t addr) {
    asm volatile("ldmatrix.sync.aligned.m8n8.x4.shared.b16 {%0,%1,%2,%3}, [%4];"
                 : "=r"(r0), "=r"(r1), "=r"(r2), "=r"(r3) : "r"(addr));
}
__device__ __forceinline__ void ldsm4t(uint32_t& r0, uint32_t& r1, uint32_t& r2, uint32_t& r3,
                                       uint32_t addr) {
    asm volatile("ldmatrix.sync.aligned.m8n8.x4.trans.shared.b16 {%0,%1,%2,%3}, [%4];"
                 : "=r"(r0), "=r"(r1), "=r"(r2), "=r"(r3) : "r"(addr));
}
__device__ __forceinline__ void mma16816h(float* d, const uint32_t* a, uint32_t b0, uint32_t b1) {
    asm volatile(
        "mma.sync.aligned.m16n8k16.row.col.f32.f16.f16.f32 "
        "{%0,%1,%2,%3}, {%4,%5,%6,%7}, {%8,%9}, {%0,%1,%2,%3};"
        : "+f"(d[0]), "+f"(d[1]), "+f"(d[2]), "+f"(d[3])
        : "r"(a[0]), "r"(a[1]), "r"(a[2]), "r"(a[3]), "r"(b0), "r"(b1));
}
__device__ __forceinline__ __half2 h2hi(float a, float b) {
    return __floats2half2_rn(a, b);
}
__device__ __forceinline__ __half2 h2lo(float a, float b) {
    __half2 r;
    r.x = __float2half_rn(a - __half2float(__float2half_rn(a)));
    r.y = __float2half_rn(b - __half2float(__float2half_rn(b)));
    return r;
}

#define ROWB   80
#define MATB   (128 * ROWB)
#define NKCH   16

// ===========================================================================
// UNIFIED big GEMM (T / W3 / final): C = A·B^T (+ optional bias).
// single fp16 x single fp16, 256x128 CTA tile, 256 threads, 8 warps (4m x 2n),
// warp tile 64x64, 3-stage, 1 CTA/SM.  (R14/R15-proven skeleton.)
// Output: fp32 (Cfp) or fp16 (Ch). B/bias batched via m0>>12 when bStride!=0.
// ===========================================================================
#define F_STG  (384 * ROWB)             // 30720/stage
#define F_OFFA 0
#define F_OFFB (256 * ROWB)             // 20480

__global__ __launch_bounds__(256, 1)
void gemm_big(const h16* __restrict__ A, const h16* __restrict__ B,
              const float* __restrict__ bias,
              float* __restrict__ Cfp, h16* __restrict__ Ch,
              int ldc, long long bStride)
{
    extern __shared__ char smem[];
    uint32_t sb = smem_u32(smem);
    int tid = threadIdx.x, wid = tid >> 5, lane = tid & 31;
    int n0 = blockIdx.x * 128, m0 = blockIdx.y * 256;
    int batch = (bStride != 0) ? (m0 >> 12) : 0;

    const h16* bb_ = B + (long long)batch * bStride;

    float acc[4][8][4];
#pragma unroll
    for (int i = 0; i < 4; i++)
#pragma unroll
        for (int j = 0; j < 8; j++)
#pragma unroll
            for (int r = 0; r < 4; r++) acc[i][j][r] = 0.f;

    auto load_stage = [&](int chunk, int stage) {
        uint32_t st = sb + stage * F_STG;
        int k0 = chunk * 32;
#pragma unroll
        for (int i = 0; i < 6; i++) {
            int idx = i * 256 + tid;
            int row = idx >> 2, c = idx & 3;
            if (row < 256) {
                cp16(st + F_OFFA + (uint32_t)(row * ROWB + c * 16),
                     A + (long long)(m0 + row) * 512 + k0 + c * 8);
            } else {
                int r2 = row - 256;
                cp16(st + F_OFFB + (uint32_t)(r2 * ROWB + c * 16),
                     bb_ + (long long)(n0 + r2) * 512 + k0 + c * 8);
            }
        }
        asm volatile("cp.async.commit_group;" ::: "memory");
    };

    load_stage(0, 0);
    load_stage(1, 1);

    int wm = wid >> 1, wn = wid & 1;
    uint32_t aRowOff = (uint32_t)(F_OFFA + (wm * 64 + (lane & 15)) * ROWB + (lane >> 4) * 16);
    uint32_t bRowOff = (uint32_t)(F_OFFB + (wn * 64 + (lane & 15)) * ROWB + (lane >> 4) * 16);

    for (int c = 0; c < NKCH; c++) {
        if (c < NKCH - 1) asm volatile("cp.async.wait_group 1;" ::: "memory");
        else              asm volatile("cp.async.wait_group 0;" ::: "memory");
        __syncthreads();
        if (c + 2 < NKCH) load_stage(c + 2, (c + 2) % 3);

        uint32_t st = sb + (c % 3) * F_STG;
#pragma unroll
        for (int kk = 0; kk < 2; kk++) {
            uint32_t kOff = kk * 32;
            uint32_t aB = st + aRowOff + kOff;
            uint32_t bB = st + bRowOff + kOff;

            uint32_t aF[4][4];
#pragma unroll
            for (int im = 0; im < 4; im++)
                ldsm4(aF[im][0], aF[im][1], aF[im][2], aF[im][3], aB + im * 16 * ROWB);
            uint32_t bF[4][4];
#pragma unroll
            for (int ib = 0; ib < 4; ib++)
                ldsm4(bF[ib][0], bF[ib][1], bF[ib][2], bF[ib][3], bB + ib * 16 * ROWB);
#pragma unroll
            for (int im = 0; im < 4; im++) {
#pragma unroll
                for (int jn = 0; jn < 8; jn++) {
                    int ib = jn >> 1, js = jn & 1;
                    mma16816h(acc[im][jn], aF[im], bF[ib][js], bF[ib][2 + js]);
                }
            }
        }
    }

    float bcol0[8], bcol1[8];
#pragma unroll
    for (int jn = 0; jn < 8; jn++) { bcol0[jn] = 0.f; bcol1[jn] = 0.f; }
    if (bias) {
        const float* bb = bias + (long long)batch * 512;
#pragma unroll
        for (int jn = 0; jn < 8; jn++) {
            int cc = n0 + wn * 64 + jn * 8 + 2 * (lane & 3);
            bcol0[jn] = bb[cc];
            bcol1[jn] = bb[cc + 1];
        }
    }
#pragma unroll
    for (int im = 0; im < 4; im++) {
        int r0 = m0 + wm * 64 + im * 16 + (lane >> 2);
#pragma unroll
        for (int jn = 0; jn < 8; jn++) {
            int cc = n0 + wn * 64 + jn * 8 + 2 * (lane & 3);
            float v00 = acc[im][jn][0] + bcol0[jn];
            float v01 = acc[im][jn][1] + bcol1[jn];
            float v10 = acc[im][jn][2] + bcol0[jn];
            float v11 = acc[im][jn][3] + bcol1[jn];
            if (Ch) {
                *(__half2*)(Ch + (long long)r0 * ldc + cc)       = h2hi(v00, v01);
                *(__half2*)(Ch + (long long)(r0 + 8) * ldc + cc) = h2hi(v10, v11);
            } else {
                *(float2*)(Cfp + (long long)r0 * ldc + cc)       = make_float2(v00, v01);
                *(float2*)(Cfp + (long long)(r0 + 8) * ldc + cc) = make_float2(v10, v11);
            }
        }
    }
}

// ===========================================================================
// SYRK fp16x3 partials: grid (10, 4, 16); K=1024 each. Diag blocks aliased.
// Writes fp16 partials (S-level quantization proven harmless in R13/R15).
// ===========================================================================
#define SROWB  272
#define SMATB  (32 * SROWB)             // 8704
#define SSTGB  (4 * SMATB)              // 34816
#define S_AH   0
#define S_AL   SMATB
#define S_BH   (2 * SMATB)
#define S_BL   (3 * SMATB)

__constant__ int c_EB[10] = {0,0,0,0,1,1,1,2,2,3};
__constant__ int c_FB[10] = {0,1,2,3,1,2,3,2,3,3};

__global__ __launch_bounds__(128, 2)
void syrk_partial(const h16* __restrict__ Xhi, const h16* __restrict__ Xlo)
{
    extern __shared__ char smem[];
    uint32_t sb = smem_u32(smem);
    int tid = threadIdx.x, wid = tid >> 5, lane = tid & 31;
    int p = blockIdx.x, kc = blockIdx.y, bp = blockIdx.z;
    int e0 = c_EB[p] * 128, f0 = c_FB[p] * 128;
    bool diag = (e0 == f0);
    long long xbase = (long long)bp * NTOK * 512;

    float acc[4][8][4];
#pragma unroll
    for (int i = 0; i < 4; i++)
#pragma unroll
        for (int j = 0; j < 8; j++)
#pragma unroll
            for (int r = 0; r < 4; r++) acc[i][j][r] = 0.f;

    auto load_stage = [&](int chunk, int stage) {
        uint32_t st = sb + stage * SSTGB;
        int t0 = kc * 1024 + chunk * 32;
#pragma unroll
        for (int i = 0; i < 4; i++) {
            int idx = i * 128 + tid;
            int row = idx >> 4, c = idx & 15;
            uint32_t so = (uint32_t)(row * SROWB + c * 16);
            long long ge = xbase + (long long)(t0 + row) * 512 + e0 + c * 8;
            cp16(st + S_AH + so, Xhi + ge);
            cp16(st + S_AL + so, Xlo + ge);
            if (!diag) {
                long long gf = xbase + (long long)(t0 + row) * 512 + f0 + c * 8;
                cp16(st + S_BH + so, Xhi + gf);
                cp16(st + S_BL + so, Xlo + gf);
            }
        }
        asm volatile("cp.async.commit_group;" ::: "memory");
    };

    load_stage(0, 0);

    int wm = wid >> 1, wn = wid & 1;
    int sub = lane >> 3;
    int nloc = (lane & 7) + ((sub >> 1) << 3);
    uint32_t cpad = (uint32_t)((sub & 1) * 16);
    uint32_t aColB = (uint32_t)((wm * 64) * 2) + cpad;
    uint32_t bColB = (uint32_t)((wn * 64) * 2) + cpad;
    uint32_t offBH = diag ? (uint32_t)S_AH : (uint32_t)S_BH;
    uint32_t offBL = diag ? (uint32_t)S_AL : (uint32_t)S_BL;

    const int NCH = 32;
    for (int c = 0; c < NCH; c++) {
        if (c + 1 < NCH) {
            load_stage(c + 1, (c + 1) & 1);
            asm volatile("cp.async.wait_group 1;" ::: "memory");
        } else {
            asm volatile("cp.async.wait_group 0;" ::: "memory");
        }
        __syncthreads();

        uint32_t st = sb + (c & 1) * SSTGB;
#pragma unroll
        for (int kk = 0; kk < 2; kk++) {
            uint32_t rowB = (uint32_t)((kk * 16 + nloc) * SROWB);
            uint32_t aB = st + rowB + aColB;
            uint32_t bB = st + rowB + bColB;

            uint32_t aH[4][4], aL[4][4];
#pragma unroll
            for (int im = 0; im < 4; im++) {
                ldsm4t(aH[im][0], aH[im][1], aH[im][2], aH[im][3], aB + S_AH + im * 32);
                ldsm4t(aL[im][0], aL[im][1], aL[im][2], aL[im][3], aB + S_AL + im * 32);
            }
            uint32_t bH[4][4], bL[4][4];
#pragma unroll
            for (int ib = 0; ib < 4; ib++) {
                ldsm4t(bH[ib][0], bH[ib][1], bH[ib][2], bH[ib][3], bB + offBH + ib * 32);
                ldsm4t(bL[ib][0], bL[ib][1], bL[ib][2], bL[ib][3], bB + offBL + ib * 32);
            }
#pragma unroll
            for (int im = 0; im < 4; im++) {
#pragma unroll
                for (int jn = 0; jn < 8; jn++) {
                    int ib = jn >> 1, js = jn & 1;
                    mma16816h(acc[im][jn], aH[im], bH[ib][js], bH[ib][2 + js]);
                    mma16816h(acc[im][jn], aH[im], bL[ib][js], bL[ib][2 + js]);
                    mma16816h(acc[im][jn], aL[im], bH[ib][js], bH[ib][2 + js]);
                }
            }
        }
        __syncthreads();
    }

    h16* dst = g_Sp + (((long long)kc * BP + bp) * 10 + p) * 16384;
#pragma unroll
    for (int im = 0; im < 4; im++) {
        int el = wm * 64 + im * 16 + (lane >> 2);
#pragma unroll
        for (int jn = 0; jn < 8; jn++) {
            int fl = wn * 64 + jn * 8 + 2 * (lane & 3);
            *(__half2*)(dst + el * 128 + fl)       = h2hi(acc[im][jn][0], acc[im][jn][1]);
            *(__half2*)(dst + (el + 8) * 128 + fl) = h2hi(acc[im][jn][2], acc[im][jn][3]);
        }
    }
}

// ===========================================================================
// SYRK finish: sum 4 fp16 partials, write single fp16 S (both orientations).
// ===========================================================================
__global__ __launch_bounds__(256)
void syrk_finish()
{
    extern __shared__ float tile[];    // 128 x 129
    int p = blockIdx.x, bp = blockIdx.y;
    int e0 = c_EB[p] * 128, f0 = c_FB[p] * 128;
    int tid = threadIdx.x;

    const h16* p0 = g_Sp + (((long long)0 * BP + bp) * 10 + p) * 16384;
    const h16* p1 = g_Sp + (((long long)1 * BP + bp) * 10 + p) * 16384;
    const h16* p2 = g_Sp + (((long long)2 * BP + bp) * 10 + p) * 16384;
    const h16* p3 = g_Sp + (((long long)3 * BP + bp) * 10 + p) * 16384;
    for (int idx = tid; idx < 16384; idx += 256) {
        float s = (__half2float(p0[idx]) + __half2float(p1[idx]))
                + (__half2float(p2[idx]) + __half2float(p3[idx]));
        tile[(idx >> 7) * 129 + (idx & 127)] = s;
    }
    __syncthreads();

    h16* SB = g_Sf16 + (long long)bp * 512 * 512;
    for (int idx = tid; idx < 16384; idx += 256) {
        int r = idx >> 7, c = idx & 127;
        SB[(long long)(e0 + r) * 512 + f0 + c] = __float2half_rn(tile[r * 129 + c]);
    }
    if (e0 != f0) {
        for (int idx = tid; idx < 16384; idx += 256) {
            int r = idx >> 7, c = idx & 127;
            SB[(long long)(f0 + r) * 512 + e0 + c] = __float2half_rn(tile[c * 129 + r]);
        }
    }
}

// ===========================================================================
// fused x split (fp16 hi/lo, float4 loads) + column sums
// grid (BP, 32 chunks of 128 rows), 256 threads (2 row-groups x 128 col4).
// ===========================================================================
__global__ __launch_bounds__(256) void split_colsum(const float* __restrict__ x) {
    int bp = blockIdx.x, ch = blockIdx.y;
    int cg = threadIdx.x & 127;          // col group (4 floats)
    int rh = threadIdx.x >> 7;           // row half (0/1)
    int c0 = cg * 4;
    long long rbase = (long long)bp * NTOK + ch * 128 + rh * 64;
    float s0 = 0.f, s1 = 0.f, s2 = 0.f, s3 = 0.f;
    for (int r = 0; r < 64; r++) {
        long long idx = (rbase + r) * 512 + c0;
        float4 v = *(const float4*)(x + idx);
        s0 += v.x; s1 += v.y; s2 += v.z; s3 += v.w;
        *(__half2*)(g_xf16 + idx)       = h2hi(v.x, v.y);
        *(__half2*)(g_xf16 + idx + 2)   = h2hi(v.z, v.w);
        *(__half2*)(g_xf16lo + idx)     = h2lo(v.x, v.y);
        *(__half2*)(g_xf16lo + idx + 2) = h2lo(v.z, v.w);
    }
    float* sdst = &g_s[bp * 512 + c0];
    atomicAdd(sdst + 0, s0);
    atomicAdd(sdst + 1, s1);
    atomicAdd(sdst + 2, s2);
    atomicAdd(sdst + 3, s3);
}
__global__ void zero_s_kernel() {
    int i = blockIdx.x * blockDim.x + threadIdx.x;
    if (i < BP * 512) g_s[i] = 0.f;
}

// ===========================================================================
// weight splits (single fp16)
// ===========================================================================
__global__ __launch_bounds__(256) void wq_single_kernel(const float* __restrict__ wqkv) {
    int i = blockIdx.x * 256 + threadIdx.x;
    if (i >= 1024 * 512) return;
    g_wqf16[i] = __float2half_rn(wqkv[i]);
}
__global__ __launch_bounds__(256) void wvt_split_kernel(const float* __restrict__ wqkv) {
    int i = blockIdx.x * 256 + threadIdx.x;
    if (i >= 512 * 512) return;
    int e = i >> 9, c = i & 511;
    g_wvtf16[i] = __float2half_rn(wqkv[(long long)(1024 + c) * 512 + e]);
}

// ===========================================================================
// attention finish per (bp,h)  (T now fp16)
// ===========================================================================
__global__ __launch_bounds__(256) void attn_from_s(const float* __restrict__ wqkv,
                                                   const float* __restrict__ b_qkv,
                                                   const float* __restrict__ temp)
{
    int bp = blockIdx.x, h = blockIdx.y;
    int tid = threadIdx.x, tr = tid >> 4, tc = tid & 15;

    extern __shared__ float dyn[];
    float* wqs = dyn;                  // 64 x 68
    float* wks = dyn + 4352;
    float* tqs = dyn + 2 * 4352;
    float* tks = dyn + 3 * 4352;
    __shared__ float schunk[64];
    __shared__ float uqv[64], ukv[64], nqv[64], nkv[64], bqs[64], bks[64];

    if (tid < 64)       bqs[tid] = b_qkv[h * 64 + tid];
    else if (tid < 128) bks[tid - 64] = b_qkv[512 + h * 64 + (tid - 64)];

    float acc[4][4];
#pragma unroll
    for (int i = 0; i < 4; i++)
#pragma unroll
        for (int j = 0; j < 4; j++) acc[i][j] = 0.f;
    float uacc = 0.f, nacc = 0.f;

    const float* wq_h = wqkv + (long long)(h * 64) * 512;
    const float* wk_h = wqkv + (long long)(512 + h * 64) * 512;
    const h16*   T_b  = g_T + (long long)bp * 512 * 1024;
    const float* svec = g_s + bp * 512;

    for (int xc = 0; xc < 8; xc++) {
        __syncthreads();
#pragma unroll
        for (int i = 0; i < 4; i++) {
            int idx4 = i * 256 + tid;
            int row = idx4 >> 4, c4 = (idx4 & 15) * 4;
            *(float4*)&wqs[row * 68 + c4] = *(const float4*)(wq_h + (long long)row * 512 + xc * 64 + c4);
            *(float4*)&wks[row * 68 + c4] = *(const float4*)(wk_h + (long long)row * 512 + xc * 64 + c4);
            const h16* trow = T_b + (long long)(xc * 64 + row) * 1024 + h * 64;
            __half2 q0 = *(const __half2*)(trow + c4);
            __half2 q1 = *(const __half2*)(trow + c4 + 2);
            float2 f0 = __half22float2(q0), f1 = __half22float2(q1);
            tqs[row * 68 + c4 + 0] = f0.x; tqs[row * 68 + c4 + 1] = f0.y;
            tqs[row * 68 + c4 + 2] = f1.x; tqs[row * 68 + c4 + 3] = f1.y;
            __half2 k0 = *(const __half2*)(trow + 512 + c4);
            __half2 k1 = *(const __half2*)(trow + 512 + c4 + 2);
            float2 g0 = __half22float2(k0), g1 = __half22float2(k1);
            tks[row * 68 + c4 + 0] = g0.x; tks[row * 68 + c4 + 1] = g0.y;
            tks[row * 68 + c4 + 2] = g1.x; tks[row * 68 + c4 + 3] = g1.y;
        }
        if (tid < 64) schunk[tid] = svec[xc * 64 + tid];
        __syncthreads();
#pragma unroll 8
        for (int x = 0; x < 64; x++) {
            float rm[4], rn[4];
#pragma unroll
            for (int i = 0; i < 4; i++) rm[i] = wqs[(tr * 4 + i) * 68 + x];
            float4 r4 = *(const float4*)&tks[x * 68 + tc * 4];
            rn[0] = r4.x; rn[1] = r4.y; rn[2] = r4.z; rn[3] = r4.w;
#pragma unroll
            for (int i = 0; i < 4; i++)
#pragma unroll
                for (int j = 0; j < 4; j++) acc[i][j] += rm[i] * rn[j];
        }
        if (tid < 64) {
            int d = tid;
            for (int x = 0; x < 64; x++) {
                float w = wqs[d * 68 + x];
                uacc += w * schunk[x];
                nacc += w * tqs[x * 68 + d];
            }
        } else if (tid < 128) {
            int d = tid - 64;
            for (int x = 0; x < 64; x++) {
                float w = wks[d * 68 + x];
                uacc += w * schunk[x];
                nacc += w * tks[x * 68 + d];
            }
        }
    }

    if (tid < 64) {
        float b = bqs[tid];
        float n2 = nacc + 2.f * b * uacc + (float)NTOK * b * b;
        nqv[tid] = fmaxf(sqrtf(fmaxf(n2, 0.f)), EPS);
        uqv[tid] = uacc;
    } else if (tid < 128) {
        int d = tid - 64;
        float b = bks[d];
        float n2 = nacc + 2.f * b * uacc + (float)NTOK * b * b;
        nkv[d] = fmaxf(sqrtf(fmaxf(n2, 0.f)), EPS);
        ukv[d] = uacc;
    }
    __syncthreads();

    float tf = temp[h];
    float* Gs = wqs;
#pragma unroll
    for (int i = 0; i < 4; i++) {
        int d = tr * 4 + i;
#pragma unroll
        for (int j = 0; j < 4; j++) {
            int e = tc * 4 + j;
            float G = acc[i][j] + bqs[d] * ukv[e] + bks[e] * uqv[d]
                      + (float)NTOK * bqs[d] * bks[e];
            Gs[d * 64 + e] = G * tf / (nqv[d] * nkv[e]);
        }
    }
    __syncthreads();

    int warp = tid >> 5, lane = tid & 31;
    float* attn_base = g_attn + ((long long)(bp * HEADS + h) << 12);
    for (int rr = 0; rr < 8; rr++) {
        int r = warp * 8 + rr;
        float x0 = Gs[r * 64 + lane];
        float x1 = Gs[r * 64 + 32 + lane];
        float m = fmaxf(x0, x1);
#pragma unroll
        for (int o = 16; o > 0; o >>= 1) m = fmaxf(m, __shfl_xor_sync(0xffffffffu, m, o));
        float e0 = expf(x0 - m), e1 = expf(x1 - m);
        float ssum = e0 + e1;
#pragma unroll
        for (int o = 16; o > 0; o >>= 1) ssum += __shfl_xor_sync(0xffffffffu, ssum, o);
        float inv = 1.f / ssum;
        attn_base[r * 64 + lane]      = e0 * inv;
        attn_base[r * 64 + 32 + lane] = e1 * inv;
    }
}

// ===========================================================================
// W2[bp][f, h*64+e] = sum_d w_out[f, h*64+d]*attn[bp,h,d,e] -> single fp16
// ===========================================================================
__global__ __launch_bounds__(256) void make_w2_kernel(const float* __restrict__ w_out) {
    long long i = (long long)blockIdx.x * 256 + threadIdx.x;
    int c = (int)(i & 511);
    int f = (int)((i >> 9) & 511);
    int bp = (int)(i >> 18);
    int h = c >> 6, e = c & 63;
    const float* wrow = w_out + f * 512 + h * 64;
    const float* acol = g_attn + ((long long)(bp * HEADS + h) << 12) + e;
    float s = 0.f;
#pragma unroll 16
    for (int d = 0; d < 64; d++) s += wrow[d] * acol[d * 64];
    g_w2f16[i] = __float2half_rn(s);
}

// ===========================================================================
// b3: warp-per-row coalesced reduction
// ===========================================================================
__global__ __launch_bounds__(256) void b3_kernel(const float* __restrict__ b_qkv,
                                                 const float* __restrict__ b_out) {
    int row = blockIdx.x * 8 + (threadIdx.x >> 5);
    int lane = threadIdx.x & 31;
    const h16* w2 = g_w2f16 + (long long)row * 512;
    const float* bv = b_qkv + 1024;
    float s = 0.f;
#pragma unroll
    for (int i = 0; i < 16; i++) {
        int c = lane + 32 * i;
        s += __half2float(w2[c]) * bv[c];
    }
#pragma unroll
    for (int o = 16; o > 0; o >>= 1) s += __shfl_xor_sync(0xffffffffu, s, o);
    if (lane == 0) g_b3[row] = s + b_out[row & 511];
}

// ===========================================================================
// launch
// ===========================================================================
extern "C" void kernel_launch(void* const* d_in, const int* in_sizes, int n_in,
                              void* d_out, int out_size)
{
    const float* x     = (const float*)d_in[0];
    const float* wq    = (const float*)d_in[1];
    const float* b_qkv = (const float*)d_in[2];
    const float* temp  = (const float*)d_in[3];
    const float* w_out = (const float*)d_in[4];
    const float* b_out = (const float*)d_in[5];
    float* out = (float*)d_out;

    h16 *xf_p, *xflo_p, *wqf_p, *Sf_p, *T_p, *w2f_p, *wvtf_p, *w3f_p;
    float *b3_p;
    cudaGetSymbolAddress((void**)&xf_p,   g_xf16);
    cudaGetSymbolAddress((void**)&xflo_p, g_xf16lo);
    cudaGetSymbolAddress((void**)&wqf_p,  g_wqf16);
    cudaGetSymbolAddress((void**)&Sf_p,   g_Sf16);
    cudaGetSymbolAddress((void**)&T_p,    g_T);
    cudaGetSymbolAddress((void**)&w2f_p,  g_w2f16);
    cudaGetSymbolAddress((void**)&wvtf_p, g_wvtf16);
    cudaGetSymbolAddress((void**)&w3f_p,  g_w3f16);
    cudaGetSymbolAddress((void**)&b3_p,   g_b3);

    const int GEMF_SMEM = 3 * F_STG;     // 92160
    const int SYRK_SMEM = 2 * SSTGB;     // 69632
    const int ATTN_SMEM = 4 * 4352 * 4;  // 69632
    const int FIN_SMEM  = 128 * 129 * 4; // 66048
    cudaFuncSetAttribute(gemm_big,     cudaFuncAttributeMaxDynamicSharedMemorySize, GEMF_SMEM);
    cudaFuncSetAttribute(syrk_partial, cudaFuncAttributeMaxDynamicSharedMemorySize, SYRK_SMEM);
    cudaFuncSetAttribute(attn_from_s,  cudaFuncAttributeMaxDynamicSharedMemorySize, ATTN_SMEM);
    cudaFuncSetAttribute(syrk_finish,  cudaFuncAttributeMaxDynamicSharedMemorySize, FIN_SMEM);

    // 1. splits + column sums (single read of x; fp16 hi/lo)
    zero_s_kernel<<<(BP * 512 + 255) / 256, 256>>>();
    {
        dim3 grid(BP, NTOK / 128);
        split_colsum<<<grid, 256>>>(x);
    }
    wq_single_kernel<<<(1024 * 512 + 255) / 256, 256>>>(wq);
    wvt_split_kernel<<<(512 * 512 + 255) / 256, 256>>>(wq);

    // 2. S = X^T X: fp16x3 partials (diag-aliased, fp16 out), reduce+mirror
    {
        dim3 grid(10, 4, BP);
        syrk_partial<<<grid, 128, SYRK_SMEM>>>(xf_p, xflo_p);
    }
    {
        dim3 grid(10, BP);
        syrk_finish<<<grid, 256, FIN_SMEM>>>();
    }

    // 3. T = Sf16·[Wq|Wk]f16^T  (256x128 tiles, fp16 out)
    {
        dim3 grid(8, BP * 512 / 256);
        gemm_big<<<grid, 256, GEMF_SMEM>>>(Sf_p, wqf_p, nullptr, nullptr, T_p, 1024, 0LL);
    }

    // 4. attention logits + softmax
    {
        dim3 grid(BP, HEADS);
        attn_from_s<<<grid, 256, ATTN_SMEM>>>(wq, b_qkv, temp);
    }

    // 5. W2 (fp16 single); W3 = W2·Wv (256x128 tiles, fp16 out); b3
    make_w2_kernel<<<(BP * EDIM * QKV) / 256, 256>>>(w_out);
    {
        dim3 grid(4, BP * 512 / 256);
        gemm_big<<<grid, 256, GEMF_SMEM>>>(w2f_p, wvtf_p, nullptr, nullptr, w3f_p, 512, 0LL);
    }
    b3_kernel<<<(BP * 512) / 8, 256>>>(b_qkv, b_out);

    // 6. out = x_f16 · W3_f16[bp]^T + b3[bp]
    {
        dim3 grid(EDIM / 128, MTOT / 256);
        gemm_big<<<grid, 256, GEMF_SMEM>>>(xf_p, w3f_p, b3_p, out, nullptr, 512,
                                           (long long)512 * 512);
    }
}

// round 17
// speedup vs baseline: 2.8508x; 1.0001x over previous
#include <cuda_runtime.h>
#include <cuda_fp16.h>
#include <cstdint>
#include <math.h>

// ---------------- problem constants ----------------
#define NTOK  4096
#define EDIM  512
#define QKV   512
#define HEADS 8
#define DH    64
#define BP    16
#define MTOT  65536
#define EPS   1e-12f

typedef __half h16;

// ---------------- scratch (device globals) ----------------
__device__ h16    g_xf16[(size_t)MTOT * 512];     // fp16 hi of x
__device__ h16    g_xf16lo[(size_t)MTOT * 512];   // fp16 lo of x (SYRK)
__device__ h16    g_wqf16[1024 * EDIM];           // Wq|Wk single fp16
__device__ h16    g_Sf16[BP * 512 * 512];         // S single fp16
__device__ h16    g_Sp[(size_t)4 * BP * 10 * 128 * 128];   // SYRK k-partials (fp16)
__device__ h16    g_T[(size_t)BP * 512 * 1024];            // [Tq | Tk] per bp (fp16)
__device__ float  g_s[BP * 512];
__device__ float  g_attn[BP * HEADS * DH * DH];
__device__ h16    g_w2f16[BP * EDIM * QKV];       // W2 single fp16
__device__ h16    g_wvtf16[EDIM * QKV];           // Wv^T single fp16
__device__ h16    g_w3f16[BP * EDIM * EDIM];      // W3 single fp16
__device__ float  g_b3[BP * EDIM];

// ---------------- PTX helpers ----------------
__device__ __forceinline__ uint32_t smem_u32(const void* p) {
    uint32_t a;
    asm("{ .reg .u64 t; cvta.to.shared.u64 t, %1; cvt.u32.u64 %0, t; }" : "=r"(a) : "l"(p));
    return a;
}
__device__ __forceinline__ void cp16(uint32_t saddr, const void* gptr) {
    asm volatile("cp.async.cg.shared.global [%0], [%1], 16;" :: "r"(saddr), "l"(gptr));
}
__device__ __forceinline__ void ldsm4(uint32_t& r0, uint32_t& r1, uint32_t& r2, uint32_t& r3,
                                      uint32_t addr) {
    asm volatile("ldmatrix.sync.aligned.m8n8.x4.shared.b16 {%0,%1,%2,%3}, [%4];"
                 : "=r"(r0), "=r"(r1), "=r"(r2), "=r"(r3) : "r"(addr));
}
__device__ __forceinline__ void ldsm4t(uint32_t& r0, uint32_t& r1, uint32_t& r2, uint32_t& r3,
                                       uint32_t addr) {
    asm volatile("ldmatrix.sync.aligned.m8n8.x4.trans.shared.b16 {%0,%1,%2,%3}, [%4];"
                 : "=r"(r0), "=r"(r1), "=r"(r2), "=r"(r3) : "r"(addr));
}
__device__ __forceinline__ void mma16816h(float* d, const uint32_t* a, uint32_t b0, uint32_t b1) {
    asm volatile(
        "mma.sync.aligned.m16n8k16.row.col.f32.f16.f16.f32 "
        "{%0,%1,%2,%3}, {%4,%5,%6,%7}, {%8,%9}, {%0,%1,%2,%3};"
        : "+f"(d[0]), "+f"(d[1]), "+f"(d[2]), "+f"(d[3])
        : "r"(a[0]), "r"(a[1]), "r"(a[2]), "r"(a[3]), "r"(b0), "r"(b1));
}
__device__ __forceinline__ __half2 h2hi(float a, float b) {
    return __floats2half2_rn(a, b);
}
__device__ __forceinline__ __half2 h2lo(float a, float b) {
    __half2 r;
    r.x = __float2half_rn(a - __half2float(__float2half_rn(a)));
    r.y = __float2half_rn(b - __half2float(__float2half_rn(b)));
    return r;
}

#define ROWB   80
#define MATB   (128 * ROWB)
#define NKCH   16

// ===========================================================================
// UNIFIED big GEMM (T / W3 / final): C = A·B^T (+ optional bias).
// single fp16 x single fp16, 256x128 CTA tile, 256 threads, 8 warps (4m x 2n),
// warp tile 64x64, 3-stage, 1 CTA/SM.  (R14/R15-proven skeleton.)
// Output: fp32 (Cfp) or fp16 (Ch). B/bias batched via m0>>12 when bStride!=0.
// ===========================================================================
#define F_STG  (384 * ROWB)             // 30720/stage
#define F_OFFA 0
#define F_OFFB (256 * ROWB)             // 20480

__global__ __launch_bounds__(256, 1)
void gemm_big(const h16* __restrict__ A, const h16* __restrict__ B,
              const float* __restrict__ bias,
              float* __restrict__ Cfp, h16* __restrict__ Ch,
              int ldc, long long bStride)
{
    extern __shared__ char smem[];
    uint32_t sb = smem_u32(smem);
    int tid = threadIdx.x, wid = tid >> 5, lane = tid & 31;
    int n0 = blockIdx.x * 128, m0 = blockIdx.y * 256;
    int batch = (bStride != 0) ? (m0 >> 12) : 0;

    const h16* bb_ = B + (long long)batch * bStride;

    float acc[4][8][4];
#pragma unroll
    for (int i = 0; i < 4; i++)
#pragma unroll
        for (int j = 0; j < 8; j++)
#pragma unroll
            for (int r = 0; r < 4; r++) acc[i][j][r] = 0.f;

    auto load_stage = [&](int chunk, int stage) {
        uint32_t st = sb + stage * F_STG;
        int k0 = chunk * 32;
#pragma unroll
        for (int i = 0; i < 6; i++) {
            int idx = i * 256 + tid;
            int row = idx >> 2, c = idx & 3;
            if (row < 256) {
                cp16(st + F_OFFA + (uint32_t)(row * ROWB + c * 16),
                     A + (long long)(m0 + row) * 512 + k0 + c * 8);
            } else {
                int r2 = row - 256;
                cp16(st + F_OFFB + (uint32_t)(r2 * ROWB + c * 16),
                     bb_ + (long long)(n0 + r2) * 512 + k0 + c * 8);
            }
        }
        asm volatile("cp.async.commit_group;" ::: "memory");
    };

    load_stage(0, 0);
    load_stage(1, 1);

    int wm = wid >> 1, wn = wid & 1;
    uint32_t aRowOff = (uint32_t)(F_OFFA + (wm * 64 + (lane & 15)) * ROWB + (lane >> 4) * 16);
    uint32_t bRowOff = (uint32_t)(F_OFFB + (wn * 64 + (lane & 15)) * ROWB + (lane >> 4) * 16);

    for (int c = 0; c < NKCH; c++) {
        if (c < NKCH - 1) asm volatile("cp.async.wait_group 1;" ::: "memory");
        else              asm volatile("cp.async.wait_group 0;" ::: "memory");
        __syncthreads();
        if (c + 2 < NKCH) load_stage(c + 2, (c + 2) % 3);

        uint32_t st = sb + (c % 3) * F_STG;
#pragma unroll
        for (int kk = 0; kk < 2; kk++) {
            uint32_t kOff = kk * 32;
            uint32_t aB = st + aRowOff + kOff;
            uint32_t bB = st + bRowOff + kOff;

            uint32_t aF[4][4];
#pragma unroll
            for (int im = 0; im < 4; im++)
                ldsm4(aF[im][0], aF[im][1], aF[im][2], aF[im][3], aB + im * 16 * ROWB);
            uint32_t bF[4][4];
#pragma unroll
            for (int ib = 0; ib < 4; ib++)
                ldsm4(bF[ib][0], bF[ib][1], bF[ib][2], bF[ib][3], bB + ib * 16 * ROWB);
#pragma unroll
            for (int im = 0; im < 4; im++) {
#pragma unroll
                for (int jn = 0; jn < 8; jn++) {
                    int ib = jn >> 1, js = jn & 1;
                    mma16816h(acc[im][jn], aF[im], bF[ib][js], bF[ib][2 + js]);
                }
            }
        }
    }

    float bcol0[8], bcol1[8];
#pragma unroll
    for (int jn = 0; jn < 8; jn++) { bcol0[jn] = 0.f; bcol1[jn] = 0.f; }
    if (bias) {
        const float* bb = bias + (long long)batch * 512;
#pragma unroll
        for (int jn = 0; jn < 8; jn++) {
            int cc = n0 + wn * 64 + jn * 8 + 2 * (lane & 3);
            bcol0[jn] = bb[cc];
            bcol1[jn] = bb[cc + 1];
        }
    }
#pragma unroll
    for (int im = 0; im < 4; im++) {
        int r0 = m0 + wm * 64 + im * 16 + (lane >> 2);
#pragma unroll
        for (int jn = 0; jn < 8; jn++) {
            int cc = n0 + wn * 64 + jn * 8 + 2 * (lane & 3);
            float v00 = acc[im][jn][0] + bcol0[jn];
            float v01 = acc[im][jn][1] + bcol1[jn];
            float v10 = acc[im][jn][2] + bcol0[jn];
            float v11 = acc[im][jn][3] + bcol1[jn];
            if (Ch) {
                *(__half2*)(Ch + (long long)r0 * ldc + cc)       = h2hi(v00, v01);
                *(__half2*)(Ch + (long long)(r0 + 8) * ldc + cc) = h2hi(v10, v11);
            } else {
                *(float2*)(Cfp + (long long)r0 * ldc + cc)       = make_float2(v00, v01);
                *(float2*)(Cfp + (long long)(r0 + 8) * ldc + cc) = make_float2(v10, v11);
            }
        }
    }
}

// ===========================================================================
// SYRK fp16x3 partials: grid (10, 4, 16); K=1024 each. Diag blocks aliased.
// Writes fp16 partials (S-level quantization proven harmless in R13/R15).
// ===========================================================================
#define SROWB  272
#define SMATB  (32 * SROWB)             // 8704
#define SSTGB  (4 * SMATB)              // 34816
#define S_AH   0
#define S_AL   SMATB
#define S_BH   (2 * SMATB)
#define S_BL   (3 * SMATB)

__constant__ int c_EB[10] = {0,0,0,0,1,1,1,2,2,3};
__constant__ int c_FB[10] = {0,1,2,3,1,2,3,2,3,3};

__global__ __launch_bounds__(128, 2)
void syrk_partial(const h16* __restrict__ Xhi, const h16* __restrict__ Xlo)
{
    extern __shared__ char smem[];
    uint32_t sb = smem_u32(smem);
    int tid = threadIdx.x, wid = tid >> 5, lane = tid & 31;
    int p = blockIdx.x, kc = blockIdx.y, bp = blockIdx.z;
    int e0 = c_EB[p] * 128, f0 = c_FB[p] * 128;
    bool diag = (e0 == f0);
    long long xbase = (long long)bp * NTOK * 512;

    float acc[4][8][4];
#pragma unroll
    for (int i = 0; i < 4; i++)
#pragma unroll
        for (int j = 0; j < 8; j++)
#pragma unroll
            for (int r = 0; r < 4; r++) acc[i][j][r] = 0.f;

    auto load_stage = [&](int chunk, int stage) {
        uint32_t st = sb + stage * SSTGB;
        int t0 = kc * 1024 + chunk * 32;
#pragma unroll
        for (int i = 0; i < 4; i++) {
            int idx = i * 128 + tid;
            int row = idx >> 4, c = idx & 15;
            uint32_t so = (uint32_t)(row * SROWB + c * 16);
            long long ge = xbase + (long long)(t0 + row) * 512 + e0 + c * 8;
            cp16(st + S_AH + so, Xhi + ge);
            cp16(st + S_AL + so, Xlo + ge);
            if (!diag) {
                long long gf = xbase + (long long)(t0 + row) * 512 + f0 + c * 8;
                cp16(st + S_BH + so, Xhi + gf);
                cp16(st + S_BL + so, Xlo + gf);
            }
        }
        asm volatile("cp.async.commit_group;" ::: "memory");
    };

    load_stage(0, 0);

    int wm = wid >> 1, wn = wid & 1;
    int sub = lane >> 3;
    int nloc = (lane & 7) + ((sub >> 1) << 3);
    uint32_t cpad = (uint32_t)((sub & 1) * 16);
    uint32_t aColB = (uint32_t)((wm * 64) * 2) + cpad;
    uint32_t bColB = (uint32_t)((wn * 64) * 2) + cpad;
    uint32_t offBH = diag ? (uint32_t)S_AH : (uint32_t)S_BH;
    uint32_t offBL = diag ? (uint32_t)S_AL : (uint32_t)S_BL;

    const int NCH = 32;
    for (int c = 0; c < NCH; c++) {
        if (c + 1 < NCH) {
            load_stage(c + 1, (c + 1) & 1);
            asm volatile("cp.async.wait_group 1;" ::: "memory");
        } else {
            asm volatile("cp.async.wait_group 0;" ::: "memory");
        }
        __syncthreads();

        uint32_t st = sb + (c & 1) * SSTGB;
#pragma unroll
        for (int kk = 0; kk < 2; kk++) {
            uint32_t rowB = (uint32_t)((kk * 16 + nloc) * SROWB);
            uint32_t aB = st + rowB + aColB;
            uint32_t bB = st + rowB + bColB;

            uint32_t aH[4][4], aL[4][4];
#pragma unroll
            for (int im = 0; im < 4; im++) {
                ldsm4t(aH[im][0], aH[im][1], aH[im][2], aH[im][3], aB + S_AH + im * 32);
                ldsm4t(aL[im][0], aL[im][1], aL[im][2], aL[im][3], aB + S_AL + im * 32);
            }
            uint32_t bH[4][4], bL[4][4];
#pragma unroll
            for (int ib = 0; ib < 4; ib++) {
                ldsm4t(bH[ib][0], bH[ib][1], bH[ib][2], bH[ib][3], bB + offBH + ib * 32);
                ldsm4t(bL[ib][0], bL[ib][1], bL[ib][2], bL[ib][3], bB + offBL + ib * 32);
            }
#pragma unroll
            for (int im = 0; im < 4; im++) {
#pragma unroll
                for (int jn = 0; jn < 8; jn++) {
                    int ib = jn >> 1, js = jn & 1;
                    mma16816h(acc[im][jn], aH[im], bH[ib][js], bH[ib][2 + js]);
                    mma16816h(acc[im][jn], aH[im], bL[ib][js], bL[ib][2 + js]);
                    mma16816h(acc[im][jn], aL[im], bH[ib][js], bH[ib][2 + js]);
                }
            }
        }
        __syncthreads();
    }

    h16* dst = g_Sp + (((long long)kc * BP + bp) * 10 + p) * 16384;
#pragma unroll
    for (int im = 0; im < 4; im++) {
        int el = wm * 64 + im * 16 + (lane >> 2);
#pragma unroll
        for (int jn = 0; jn < 8; jn++) {
            int fl = wn * 64 + jn * 8 + 2 * (lane & 3);
            *(__half2*)(dst + el * 128 + fl)       = h2hi(acc[im][jn][0], acc[im][jn][1]);
            *(__half2*)(dst + (el + 8) * 128 + fl) = h2hi(acc[im][jn][2], acc[im][jn][3]);
        }
    }
}

// ===========================================================================
// SYRK finish: sum 4 fp16 partials, write single fp16 S (both orientations).
// ===========================================================================
__global__ __launch_bounds__(256)
void syrk_finish()
{
    extern __shared__ float tile[];    // 128 x 129
    int p = blockIdx.x, bp = blockIdx.y;
    int e0 = c_EB[p] * 128, f0 = c_FB[p] * 128;
    int tid = threadIdx.x;

    const h16* p0 = g_Sp + (((long long)0 * BP + bp) * 10 + p) * 16384;
    const h16* p1 = g_Sp + (((long long)1 * BP + bp) * 10 + p) * 16384;
    const h16* p2 = g_Sp + (((long long)2 * BP + bp) * 10 + p) * 16384;
    const h16* p3 = g_Sp + (((long long)3 * BP + bp) * 10 + p) * 16384;
    for (int idx = tid; idx < 16384; idx += 256) {
        float s = (__half2float(p0[idx]) + __half2float(p1[idx]))
                + (__half2float(p2[idx]) + __half2float(p3[idx]));
        tile[(idx >> 7) * 129 + (idx & 127)] = s;
    }
    __syncthreads();

    h16* SB = g_Sf16 + (long long)bp * 512 * 512;
    for (int idx = tid; idx < 16384; idx += 256) {
        int r = idx >> 7, c = idx & 127;
        SB[(long long)(e0 + r) * 512 + f0 + c] = __float2half_rn(tile[r * 129 + c]);
    }
    if (e0 != f0) {
        for (int idx = tid; idx < 16384; idx += 256) {
            int r = idx >> 7, c = idx & 127;
            SB[(long long)(f0 + r) * 512 + e0 + c] = __float2half_rn(tile[c * 129 + r]);
        }
    }
}

// ===========================================================================
// fused x split (fp16 hi/lo, float4 loads) + column sums
// grid (BP, 32 chunks of 128 rows), 256 threads (2 row-groups x 128 col4).
// ===========================================================================
__global__ __launch_bounds__(256) void split_colsum(const float* __restrict__ x) {
    int bp = blockIdx.x, ch = blockIdx.y;
    int cg = threadIdx.x & 127;          // col group (4 floats)
    int rh = threadIdx.x >> 7;           // row half (0/1)
    int c0 = cg * 4;
    long long rbase = (long long)bp * NTOK + ch * 128 + rh * 64;
    float s0 = 0.f, s1 = 0.f, s2 = 0.f, s3 = 0.f;
    for (int r = 0; r < 64; r++) {
        long long idx = (rbase + r) * 512 + c0;
        float4 v = *(const float4*)(x + idx);
        s0 += v.x; s1 += v.y; s2 += v.z; s3 += v.w;
        *(__half2*)(g_xf16 + idx)       = h2hi(v.x, v.y);
        *(__half2*)(g_xf16 + idx + 2)   = h2hi(v.z, v.w);
        *(__half2*)(g_xf16lo + idx)     = h2lo(v.x, v.y);
        *(__half2*)(g_xf16lo + idx + 2) = h2lo(v.z, v.w);
    }
    float* sdst = &g_s[bp * 512 + c0];
    atomicAdd(sdst + 0, s0);
    atomicAdd(sdst + 1, s1);
    atomicAdd(sdst + 2, s2);
    atomicAdd(sdst + 3, s3);
}
__global__ void zero_s_kernel() {
    int i = blockIdx.x * blockDim.x + threadIdx.x;
    if (i < BP * 512) g_s[i] = 0.f;
}

// ===========================================================================
// weight splits (single fp16)
// ===========================================================================
__global__ __launch_bounds__(256) void wq_single_kernel(const float* __restrict__ wqkv) {
    int i = blockIdx.x * 256 + threadIdx.x;
    if (i >= 1024 * 512) return;
    g_wqf16[i] = __float2half_rn(wqkv[i]);
}
__global__ __launch_bounds__(256) void wvt_split_kernel(const float* __restrict__ wqkv) {
    int i = blockIdx.x * 256 + threadIdx.x;
    if (i >= 512 * 512) return;
    int e = i >> 9, c = i & 511;
    g_wvtf16[i] = __float2half_rn(wqkv[(long long)(1024 + c) * 512 + e]);
}

// ===========================================================================
// attention finish per (bp,h)  (T now fp16)
// ===========================================================================
__global__ __launch_bounds__(256) void attn_from_s(const float* __restrict__ wqkv,
                                                   const float* __restrict__ b_qkv,
                                                   const float* __restrict__ temp)
{
    int bp = blockIdx.x, h = blockIdx.y;
    int tid = threadIdx.x, tr = tid >> 4, tc = tid & 15;

    extern __shared__ float dyn[];
    float* wqs = dyn;                  // 64 x 68
    float* wks = dyn + 4352;
    float* tqs = dyn + 2 * 4352;
    float* tks = dyn + 3 * 4352;
    __shared__ float schunk[64];
    __shared__ float uqv[64], ukv[64], nqv[64], nkv[64], bqs[64], bks[64];

    if (tid < 64)       bqs[tid] = b_qkv[h * 64 + tid];
    else if (tid < 128) bks[tid - 64] = b_qkv[512 + h * 64 + (tid - 64)];

    float acc[4][4];
#pragma unroll
    for (int i = 0; i < 4; i++)
#pragma unroll
        for (int j = 0; j < 4; j++) acc[i][j] = 0.f;
    float uacc = 0.f, nacc = 0.f;

    const float* wq_h = wqkv + (long long)(h * 64) * 512;
    const float* wk_h = wqkv + (long long)(512 + h * 64) * 512;
    const h16*   T_b  = g_T + (long long)bp * 512 * 1024;
    const float* svec = g_s + bp * 512;

    for (int xc = 0; xc < 8; xc++) {
        __syncthreads();
#pragma unroll
        for (int i = 0; i < 4; i++) {
            int idx4 = i * 256 + tid;
            int row = idx4 >> 4, c4 = (idx4 & 15) * 4;
            *(float4*)&wqs[row * 68 + c4] = *(const float4*)(wq_h + (long long)row * 512 + xc * 64 + c4);
            *(float4*)&wks[row * 68 + c4] = *(const float4*)(wk_h + (long long)row * 512 + xc * 64 + c4);
            const h16* trow = T_b + (long long)(xc * 64 + row) * 1024 + h * 64;
            __half2 q0 = *(const __half2*)(trow + c4);
            __half2 q1 = *(const __half2*)(trow + c4 + 2);
            float2 f0 = __half22float2(q0), f1 = __half22float2(q1);
            tqs[row * 68 + c4 + 0] = f0.x; tqs[row * 68 + c4 + 1] = f0.y;
            tqs[row * 68 + c4 + 2] = f1.x; tqs[row * 68 + c4 + 3] = f1.y;
            __half2 k0 = *(const __half2*)(trow + 512 + c4);
            __half2 k1 = *(const __half2*)(trow + 512 + c4 + 2);
            float2 g0 = __half22float2(k0), g1 = __half22float2(k1);
            tks[row * 68 + c4 + 0] = g0.x; tks[row * 68 + c4 + 1] = g0.y;
            tks[row * 68 + c4 + 2] = g1.x; tks[row * 68 + c4 + 3] = g1.y;
        }
        if (tid < 64) schunk[tid] = svec[xc * 64 + tid];
        __syncthreads();
#pragma unroll 8
        for (int x = 0; x < 64; x++) {
            float rm[4], rn[4];
#pragma unroll
            for (int i = 0; i < 4; i++) rm[i] = wqs[(tr * 4 + i) * 68 + x];
            float4 r4 = *(const float4*)&tks[x * 68 + tc * 4];
            rn[0] = r4.x; rn[1] = r4.y; rn[2] = r4.z; rn[3] = r4.w;
#pragma unroll
            for (int i = 0; i < 4; i++)
#pragma unroll
                for (int j = 0; j < 4; j++) acc[i][j] += rm[i] * rn[j];
        }
        if (tid < 64) {
            int d = tid;
            for (int x = 0; x < 64; x++) {
                float w = wqs[d * 68 + x];
                uacc += w * schunk[x];
                nacc += w * tqs[x * 68 + d];
            }
        } else if (tid < 128) {
            int d = tid - 64;
            for (int x = 0; x < 64; x++) {
                float w = wks[d * 68 + x];
                uacc += w * schunk[x];
                nacc += w * tks[x * 68 + d];
            }
        }
    }

    if (tid < 64) {
        float b = bqs[tid];
        float n2 = nacc + 2.f * b * uacc + (float)NTOK * b * b;
        nqv[tid] = fmaxf(sqrtf(fmaxf(n2, 0.f)), EPS);
        uqv[tid] = uacc;
    } else if (tid < 128) {
        int d = tid - 64;
        float b = bks[d];
        float n2 = nacc + 2.f * b * uacc + (float)NTOK * b * b;
        nkv[d] = fmaxf(sqrtf(fmaxf(n2, 0.f)), EPS);
        ukv[d] = uacc;
    }
    __syncthreads();

    float tf = temp[h];
    float* Gs = wqs;
#pragma unroll
    for (int i = 0; i < 4; i++) {
        int d = tr * 4 + i;
#pragma unroll
        for (int j = 0; j < 4; j++) {
            int e = tc * 4 + j;
            float G = acc[i][j] + bqs[d] * ukv[e] + bks[e] * uqv[d]
                      + (float)NTOK * bqs[d] * bks[e];
            Gs[d * 64 + e] = G * tf / (nqv[d] * nkv[e]);
        }
    }
    __syncthreads();

    int warp = tid >> 5, lane = tid & 31;
    float* attn_base = g_attn + ((long long)(bp * HEADS + h) << 12);
    for (int rr = 0; rr < 8; rr++) {
        int r = warp * 8 + rr;
        float x0 = Gs[r * 64 + lane];
        float x1 = Gs[r * 64 + 32 + lane];
        float m = fmaxf(x0, x1);
#pragma unroll
        for (int o = 16; o > 0; o >>= 1) m = fmaxf(m, __shfl_xor_sync(0xffffffffu, m, o));
        float e0 = expf(x0 - m), e1 = expf(x1 - m);
        float ssum = e0 + e1;
#pragma unroll
        for (int o = 16; o > 0; o >>= 1) ssum += __shfl_xor_sync(0xffffffffu, ssum, o);
        float inv = 1.f / ssum;
        attn_base[r * 64 + lane]      = e0 * inv;
        attn_base[r * 64 + 32 + lane] = e1 * inv;
    }
}

// ===========================================================================
// W2[bp][f, h*64+e] = sum_d w_out[f, h*64+d]*attn[bp,h,d,e] -> single fp16
// ===========================================================================
__global__ __launch_bounds__(256) void make_w2_kernel(const float* __restrict__ w_out) {
    long long i = (long long)blockIdx.x * 256 + threadIdx.x;
    int c = (int)(i & 511);
    int f = (int)((i >> 9) & 511);
    int bp = (int)(i >> 18);
    int h = c >> 6, e = c & 63;
    const float* wrow = w_out + f * 512 + h * 64;
    const float* acol = g_attn + ((long long)(bp * HEADS + h) << 12) + e;
    float s = 0.f;
#pragma unroll 16
    for (int d = 0; d < 64; d++) s += wrow[d] * acol[d * 64];
    g_w2f16[i] = __float2half_rn(s);
}

// ===========================================================================
// b3: warp-per-row coalesced reduction
// ===========================================================================
__global__ __launch_bounds__(256) void b3_kernel(const float* __restrict__ b_qkv,
                                                 const float* __restrict__ b_out) {
    int row = blockIdx.x * 8 + (threadIdx.x >> 5);
    int lane = threadIdx.x & 31;
    const h16* w2 = g_w2f16 + (long long)row * 512;
    const float* bv = b_qkv + 1024;
    float s = 0.f;
#pragma unroll
    for (int i = 0; i < 16; i++) {
        int c = lane + 32 * i;
        s += __half2float(w2[c]) * bv[c];
    }
#pragma unroll
    for (int o = 16; o > 0; o >>= 1) s += __shfl_xor_sync(0xffffffffu, s, o);
    if (lane == 0) g_b3[row] = s + b_out[row & 511];
}

// ===========================================================================
// launch
// ===========================================================================
extern "C" void kernel_launch(void* const* d_in, const int* in_sizes, int n_in,
                              void* d_out, int out_size)
{
    const float* x     = (const float*)d_in[0];
    const float* wq    = (const float*)d_in[1];
    const float* b_qkv = (const float*)d_in[2];
    const float* temp  = (const float*)d_in[3];
    const float* w_out = (const float*)d_in[4];
    const float* b_out = (const float*)d_in[5];
    float* out = (float*)d_out;

    h16 *xf_p, *xflo_p, *wqf_p, *Sf_p, *T_p, *w2f_p, *wvtf_p, *w3f_p;
    float *b3_p;
    cudaGetSymbolAddress((void**)&xf_p,   g_xf16);
    cudaGetSymbolAddress((void**)&xflo_p, g_xf16lo);
    cudaGetSymbolAddress((void**)&wqf_p,  g_wqf16);
    cudaGetSymbolAddress((void**)&Sf_p,   g_Sf16);
    cudaGetSymbolAddress((void**)&T_p,    g_T);
    cudaGetSymbolAddress((void**)&w2f_p,  g_w2f16);
    cudaGetSymbolAddress((void**)&wvtf_p, g_wvtf16);
    cudaGetSymbolAddress((void**)&w3f_p,  g_w3f16);
    cudaGetSymbolAddress((void**)&b3_p,   g_b3);

    const int GEMF_SMEM = 3 * F_STG;     // 92160
    const int SYRK_SMEM = 2 * SSTGB;     // 69632
    const int ATTN_SMEM = 4 * 4352 * 4;  // 69632
    const int FIN_SMEM  = 128 * 129 * 4; // 66048
    cudaFuncSetAttribute(gemm_big,     cudaFuncAttributeMaxDynamicSharedMemorySize, GEMF_SMEM);
    cudaFuncSetAttribute(syrk_partial, cudaFuncAttributeMaxDynamicSharedMemorySize, SYRK_SMEM);
    cudaFuncSetAttribute(attn_from_s,  cudaFuncAttributeMaxDynamicSharedMemorySize, ATTN_SMEM);
    cudaFuncSetAttribute(syrk_finish,  cudaFuncAttributeMaxDynamicSharedMemorySize, FIN_SMEM);

    // 1. splits + column sums (single read of x; fp16 hi/lo)
    zero_s_kernel<<<(BP * 512 + 255) / 256, 256>>>();
    {
        dim3 grid(BP, NTOK / 128);
        split_colsum<<<grid, 256>>>(x);
    }
    wq_single_kernel<<<(1024 * 512 + 255) / 256, 256>>>(wq);
    wvt_split_kernel<<<(512 * 512 + 255) / 256, 256>>>(wq);

    // 2. S = X^T X: fp16x3 partials (diag-aliased, fp16 out), reduce+mirror
    {
        dim3 grid(10, 4, BP);
        syrk_partial<<<grid, 128, SYRK_SMEM>>>(xf_p, xflo_p);
    }
    {
        dim3 grid(10, BP);
        syrk_finish<<<grid, 256, FIN_SMEM>>>();
    }

    // 3. T = Sf16·[Wq|Wk]f16^T  (256x128 tiles, fp16 out)
    {
        dim3 grid(8, BP * 512 / 256);
        gemm_big<<<grid, 256, GEMF_SMEM>>>(Sf_p, wqf_p, nullptr, nullptr, T_p, 1024, 0LL);
    }

    // 4. attention logits + softmax
    {
        dim3 grid(BP, HEADS);
        attn_from_s<<<grid, 256, ATTN_SMEM>>>(wq, b_qkv, temp);
    }

    // 5. W2 (fp16 single); W3 = W2·Wv (256x128 tiles, fp16 out); b3
    make_w2_kernel<<<(BP * EDIM * QKV) / 256, 256>>>(w_out);
    {
        dim3 grid(4, BP * 512 / 256);
        gemm_big<<<grid, 256, GEMF_SMEM>>>(w2f_p, wvtf_p, nullptr, nullptr, w3f_p, 512, 0LL);
    }
    b3_kernel<<<(BP * 512) / 8, 256>>>(b_qkv, b_out);

    // 6. out = x_f16 · W3_f16[bp]^T + b3[bp]
    {
        dim3 grid(EDIM / 128, MTOT / 256);
        gemm_big<<<grid, 256, GEMF_SMEM>>>(xf_p, w3f_p, b3_p, out, nullptr, 512,
                                           (long long)512 * 512);
    }
}